// round 2
// baseline (speedup 1.0000x reference)
#include <cuda_runtime.h>
#include <math.h>

// ---------------- problem constants ----------------
constexpr int LAY = 8;
constexpr int NH  = 16;
constexpr int EMB = 1024;
constexpr int VOC = 32000;
constexpr int SEQ = 1024;
constexpr int BSZ = 2;
constexpr int HSD = 64;        // head size
constexpr int DFF = 4096;
constexpr int MROWS = BSZ * SEQ;   // 2048

// ---------------- scratch (device globals; no cudaMalloc allowed) ----------------
__device__ float g_x [MROWS * EMB];   // residual stream
__device__ float g_h [MROWS * EMB];   // layernorm output
__device__ float g_q [MROWS * EMB];
__device__ float g_k [MROWS * EMB];
__device__ float g_v [MROWS * EMB];
__device__ float g_o [MROWS * EMB];
__device__ float g_ff[MROWS * DFF];   // MLP hidden

// ---------------- embedding ----------------
__global__ void embed_kernel(float* __restrict__ x, const int* __restrict__ idx,
                             const float* __restrict__ tok, const float* __restrict__ pos)
{
    int i = blockIdx.x * blockDim.x + threadIdx.x;    // over MROWS*EMB
    int e  = i & (EMB - 1);
    int bt = i >> 10;                // /EMB
    int t  = bt & (SEQ - 1);
    x[i] = tok[(size_t)idx[bt] * EMB + e] + pos[(size_t)t * EMB + e];
}

// ---------------- layernorm (one block per row, 256 threads, E=1024) ----------------
__global__ __launch_bounds__(256) void ln_kernel(float* __restrict__ out,
                                                 const float* __restrict__ in,
                                                 const float* __restrict__ g,
                                                 const float* __restrict__ b)
{
    const int row = blockIdx.x;
    const float* xr = in + (size_t)row * EMB;
    float v[4];
    float s = 0.f;
    #pragma unroll
    for (int i = 0; i < 4; i++) { v[i] = xr[threadIdx.x + i * 256]; s += v[i]; }

    __shared__ float red[8];
    __shared__ float mean_s, rstd_s;

    #pragma unroll
    for (int o = 16; o; o >>= 1) s += __shfl_xor_sync(0xffffffffu, s, o);
    if ((threadIdx.x & 31) == 0) red[threadIdx.x >> 5] = s;
    __syncthreads();
    if (threadIdx.x == 0) {
        float t = 0.f;
        #pragma unroll
        for (int i = 0; i < 8; i++) t += red[i];
        mean_s = t * (1.f / EMB);
    }
    __syncthreads();
    const float m = mean_s;

    float ss = 0.f;
    #pragma unroll
    for (int i = 0; i < 4; i++) { float d = v[i] - m; ss += d * d; }
    #pragma unroll
    for (int o = 16; o; o >>= 1) ss += __shfl_xor_sync(0xffffffffu, ss, o);
    if ((threadIdx.x & 31) == 0) red[threadIdx.x >> 5] = ss;
    __syncthreads();
    if (threadIdx.x == 0) {
        float t = 0.f;
        #pragma unroll
        for (int i = 0; i < 8; i++) t += red[i];
        rstd_s = rsqrtf(t * (1.f / EMB) + 1e-5f);
    }
    __syncthreads();
    const float r = rstd_s;

    #pragma unroll
    for (int i = 0; i < 4; i++) {
        int col = threadIdx.x + i * 256;
        out[(size_t)row * EMB + col] = (v[i] - m) * r * g[col] + b[col];
    }
}

// ---------------- SGEMM: C[M,N] = A[M,K] @ B(+T) [+bias][+res][relu] ----------------
// BM=BN=128, BK=8, 256 threads, 8x8 microtile. All dims are multiples (no bounds checks).
template<bool BTRANS, bool BIAS, bool RELU, bool RES>
__global__ __launch_bounds__(256) void gemm_kernel(
    const float* __restrict__ A, const float* __restrict__ Bm,
    const float* __restrict__ bias, const float* __restrict__ res,
    float* __restrict__ C, int M, int N, int K)
{
    __shared__ float As[8][128];
    __shared__ float Bs[8][128];
    const int tid = threadIdx.x;
    const int bm0 = blockIdx.y * 128;
    const int bn0 = blockIdx.x * 128;
    const int ty = tid >> 4;     // 0..15
    const int tx = tid & 15;     // 0..15

    const int arow = tid >> 1;          // 0..127
    const int ak4  = (tid & 1) * 4;     // 0 or 4
    const float* Ap = A + (size_t)(bm0 + arow) * K + ak4;

    const float* Bp;
    if (BTRANS) {
        Bp = Bm + (size_t)(bn0 + arow) * K + ak4;     // Bm is [N,K]
    } else {
        Bp = Bm + (size_t)(tid >> 5) * N + bn0 + (tid & 31) * 4;  // [K,N]
    }

    float acc[8][8];
    #pragma unroll
    for (int i = 0; i < 8; i++)
        #pragma unroll
        for (int j = 0; j < 8; j++) acc[i][j] = 0.f;

    for (int k0 = 0; k0 < K; k0 += 8) {
        float4 av = *reinterpret_cast<const float4*>(Ap + k0);
        As[ak4 + 0][arow] = av.x;
        As[ak4 + 1][arow] = av.y;
        As[ak4 + 2][arow] = av.z;
        As[ak4 + 3][arow] = av.w;
        if (BTRANS) {
            float4 bv = *reinterpret_cast<const float4*>(Bp + k0);
            Bs[ak4 + 0][arow] = bv.x;
            Bs[ak4 + 1][arow] = bv.y;
            Bs[ak4 + 2][arow] = bv.z;
            Bs[ak4 + 3][arow] = bv.w;
        } else {
            float4 bv = *reinterpret_cast<const float4*>(Bp + (size_t)k0 * N);
            *reinterpret_cast<float4*>(&Bs[tid >> 5][(tid & 31) * 4]) = bv;
        }
        __syncthreads();
        #pragma unroll
        for (int kk = 0; kk < 8; kk++) {
            float a[8], b[8];
            *reinterpret_cast<float4*>(&a[0]) = *reinterpret_cast<const float4*>(&As[kk][ty * 8]);
            *reinterpret_cast<float4*>(&a[4]) = *reinterpret_cast<const float4*>(&As[kk][ty * 8 + 4]);
            *reinterpret_cast<float4*>(&b[0]) = *reinterpret_cast<const float4*>(&Bs[kk][tx * 8]);
            *reinterpret_cast<float4*>(&b[4]) = *reinterpret_cast<const float4*>(&Bs[kk][tx * 8 + 4]);
            #pragma unroll
            for (int i = 0; i < 8; i++)
                #pragma unroll
                for (int j = 0; j < 8; j++)
                    acc[i][j] += a[i] * b[j];
        }
        __syncthreads();
    }

    #pragma unroll
    for (int i = 0; i < 8; i++) {
        const int row = bm0 + ty * 8 + i;
        #pragma unroll
        for (int jv = 0; jv < 2; jv++) {
            const int col = bn0 + tx * 8 + jv * 4;
            float4 r;
            r.x = acc[i][jv * 4 + 0]; r.y = acc[i][jv * 4 + 1];
            r.z = acc[i][jv * 4 + 2]; r.w = acc[i][jv * 4 + 3];
            if (BIAS) {
                float4 bv = *reinterpret_cast<const float4*>(bias + col);
                r.x += bv.x; r.y += bv.y; r.z += bv.z; r.w += bv.w;
            }
            if (RES) {
                float4 rv = *reinterpret_cast<const float4*>(res + (size_t)row * N + col);
                r.x += rv.x; r.y += rv.y; r.z += rv.z; r.w += rv.w;
            }
            if (RELU) {
                r.x = fmaxf(r.x, 0.f); r.y = fmaxf(r.y, 0.f);
                r.z = fmaxf(r.z, 0.f); r.w = fmaxf(r.w, 0.f);
            }
            *reinterpret_cast<float4*>(C + (size_t)row * N + col) = r;
        }
    }
}

// ---------------- flash attention (fp32, causal), 64-query tiles ----------------
// Q,K,V,O stored as [B,T,E] with E = h*64+d. grid = (SEQ/64, BSZ*NH), 256 threads.
constexpr int QP = 68;  // Qs pitch (float4-aligned, conflict-benign)
constexpr int KP = 65;  // Ks (transposed [d][key]) pitch (scalar stores)
constexpr int VP = 68;
constexpr int PP = 68;
constexpr int ATTN_SMEM = (64 * QP + 64 * KP + 64 * VP + 64 * PP) * 4;   // 68,864 B

__global__ __launch_bounds__(256) void attn_kernel(const float* __restrict__ Q,
                                                   const float* __restrict__ Kc,
                                                   const float* __restrict__ Vc,
                                                   float* __restrict__ O)
{
    extern __shared__ float sm[];
    float* Qs = sm;                  // [64][QP]  (q-row major)
    float* Ks = Qs + 64 * QP;        // [64][KP]  TRANSPOSED: Ks[d*KP + key]
    float* Vs = Ks + 64 * KP;        // [64][VP]  (key-row major)
    float* Ps = Vs + 64 * VP;        // [64][PP]  probs

    const int qt  = blockIdx.x;
    const int bh  = blockIdx.y;
    const int b   = bh >> 4;
    const int h   = bh & 15;
    const int tid = threadIdx.x;
    const int ty  = tid >> 4;   // 0..15 -> query rows 4*ty..+3
    const int tx  = tid & 15;   // 0..15 -> cols 4*tx..+3

    const size_t baseQ = ((size_t)(b * SEQ + qt * 64)) * EMB + h * 64;

    #pragma unroll
    for (int r = 0; r < 4; r++) {
        int id = tid + r * 256;
        int row = id >> 4, c4 = id & 15;
        float4 qv = *reinterpret_cast<const float4*>(Q + baseQ + (size_t)row * EMB + c4 * 4);
        *reinterpret_cast<float4*>(&Qs[row * QP + c4 * 4]) = qv;
    }

    float m[4], l[4], oacc[4][4];
    #pragma unroll
    for (int i = 0; i < 4; i++) {
        m[i] = -1e30f; l[i] = 0.f;
        #pragma unroll
        for (int j = 0; j < 4; j++) oacc[i][j] = 0.f;
    }
    const float scale = 0.125f;   // HS^-0.5 = 1/8

    for (int jt = 0; jt <= qt; jt++) {
        __syncthreads();   // previous PV + Q load done before overwriting tiles
        const size_t baseK = ((size_t)(b * SEQ + jt * 64)) * EMB + h * 64;
        #pragma unroll
        for (int r = 0; r < 4; r++) {
            int id = tid + r * 256;
            int row = id >> 4, c4 = id & 15;
            float4 kv = *reinterpret_cast<const float4*>(Kc + baseK + (size_t)row * EMB + c4 * 4);
            Ks[(c4 * 4 + 0) * KP + row] = kv.x;
            Ks[(c4 * 4 + 1) * KP + row] = kv.y;
            Ks[(c4 * 4 + 2) * KP + row] = kv.z;
            Ks[(c4 * 4 + 3) * KP + row] = kv.w;
            float4 vv = *reinterpret_cast<const float4*>(Vc + baseK + (size_t)row * EMB + c4 * 4);
            *reinterpret_cast<float4*>(&Vs[row * VP + c4 * 4]) = vv;
        }
        __syncthreads();

        float s[4][4];
        #pragma unroll
        for (int i = 0; i < 4; i++)
            #pragma unroll
            for (int j = 0; j < 4; j++) s[i][j] = 0.f;

        #pragma unroll 8
        for (int d = 0; d < 64; d++) {
            float qa[4], kb[4];
            #pragma unroll
            for (int i = 0; i < 4; i++) qa[i] = Qs[(ty * 4 + i) * QP + d];
            #pragma unroll
            for (int j = 0; j < 4; j++) kb[j] = Ks[d * KP + tx * 4 + j];
            #pragma unroll
            for (int i = 0; i < 4; i++)
                #pragma unroll
                for (int j = 0; j < 4; j++) s[i][j] += qa[i] * kb[j];
        }

        const bool diag = (jt == qt);
        #pragma unroll
        for (int i = 0; i < 4; i++)
            #pragma unroll
            for (int j = 0; j < 4; j++) {
                s[i][j] *= scale;
                if (diag && (tx * 4 + j) > (ty * 4 + i)) s[i][j] = -1e30f;
            }

        #pragma unroll
        for (int i = 0; i < 4; i++) {
            float mx = fmaxf(fmaxf(s[i][0], s[i][1]), fmaxf(s[i][2], s[i][3]));
            #pragma unroll
            for (int o = 8; o; o >>= 1) mx = fmaxf(mx, __shfl_xor_sync(0xffffffffu, mx, o, 16));
            float mnew = fmaxf(m[i], mx);
            float alpha = __expf(m[i] - mnew);
            m[i] = mnew;
            float rs = 0.f;
            #pragma unroll
            for (int j = 0; j < 4; j++) {
                float p = __expf(s[i][j] - mnew);
                s[i][j] = p; rs += p;
            }
            #pragma unroll
            for (int o = 8; o; o >>= 1) rs += __shfl_xor_sync(0xffffffffu, rs, o, 16);
            l[i] = l[i] * alpha + rs;
            #pragma unroll
            for (int j = 0; j < 4; j++) oacc[i][j] *= alpha;
        }

        #pragma unroll
        for (int i = 0; i < 4; i++)
            #pragma unroll
            for (int j = 0; j < 4; j++)
                Ps[(ty * 4 + i) * PP + tx * 4 + j] = s[i][j];
        __syncthreads();

        #pragma unroll 8
        for (int kk = 0; kk < 64; kk++) {
            float pa[4], vb[4];
            #pragma unroll
            for (int i = 0; i < 4; i++) pa[i] = Ps[(ty * 4 + i) * PP + kk];
            #pragma unroll
            for (int j = 0; j < 4; j++) vb[j] = Vs[kk * VP + tx * 4 + j];
            #pragma unroll
            for (int i = 0; i < 4; i++)
                #pragma unroll
                for (int j = 0; j < 4; j++) oacc[i][j] += pa[i] * vb[j];
        }
    }

    #pragma unroll
    for (int i = 0; i < 4; i++) {
        float inv = 1.f / l[i];
        #pragma unroll
        for (int j = 0; j < 4; j++)
            O[baseQ + (size_t)(ty * 4 + i) * EMB + tx * 4 + j] = oacc[i][j] * inv;
    }
}

// ---------------- host orchestration ----------------
extern "C" void kernel_launch(void* const* d_in, const int* in_sizes, int n_in,
                              void* d_out, int out_size)
{
    const int*   idx  = (const int*)  d_in[0];
    const float* tok  = (const float*)d_in[1];
    const float* pos  = (const float*)d_in[2];
    const float* Wq   = (const float*)d_in[3];
    const float* Wk   = (const float*)d_in[4];
    const float* Wv   = (const float*)d_in[5];
    const float* Wo   = (const float*)d_in[6];
    const float* bo   = (const float*)d_in[7];
    const float* W1   = (const float*)d_in[8];
    const float* b1   = (const float*)d_in[9];
    const float* W2   = (const float*)d_in[10];
    const float* b2   = (const float*)d_in[11];
    const float* ln1g = (const float*)d_in[12];
    const float* ln1b = (const float*)d_in[13];
    const float* ln2g = (const float*)d_in[14];
    const float* ln2b = (const float*)d_in[15];
    const float* lnfg = (const float*)d_in[16];
    const float* lnfb = (const float*)d_in[17];
    const float* lmb  = (const float*)d_in[18];
    float* out = (float*)d_out;

    float *x, *h, *q, *k, *v, *o, *ff;
    cudaGetSymbolAddress((void**)&x,  g_x);
    cudaGetSymbolAddress((void**)&h,  g_h);
    cudaGetSymbolAddress((void**)&q,  g_q);
    cudaGetSymbolAddress((void**)&k,  g_k);
    cudaGetSymbolAddress((void**)&v,  g_v);
    cudaGetSymbolAddress((void**)&o,  g_o);
    cudaGetSymbolAddress((void**)&ff, g_ff);

    cudaFuncSetAttribute(attn_kernel, cudaFuncAttributeMaxDynamicSharedMemorySize, ATTN_SMEM);

    embed_kernel<<<(MROWS * EMB) / 256, 256>>>(x, idx, tok, pos);

    const dim3 g1024(EMB / 128, MROWS / 128);   // N=1024
    const dim3 g4096(DFF / 128, MROWS / 128);   // N=4096
    const dim3 gvoc (VOC / 128, MROWS / 128);   // N=32000

    for (int l = 0; l < LAY; l++) {
        const size_t wo = (size_t)l * EMB * EMB;
        ln_kernel<<<MROWS, 256>>>(h, x, ln1g + (size_t)l * EMB, ln1b + (size_t)l * EMB);
        gemm_kernel<false, false, false, false><<<g1024, 256>>>(h, Wq + wo, nullptr, nullptr, q, MROWS, EMB, EMB);
        gemm_kernel<false, false, false, false><<<g1024, 256>>>(h, Wk + wo, nullptr, nullptr, k, MROWS, EMB, EMB);
        gemm_kernel<false, false, false, false><<<g1024, 256>>>(h, Wv + wo, nullptr, nullptr, v, MROWS, EMB, EMB);
        attn_kernel<<<dim3(SEQ / 64, BSZ * NH), 256, ATTN_SMEM>>>(q, k, v, o);
        gemm_kernel<false, true, false, true><<<g1024, 256>>>(o, Wo + wo, bo + (size_t)l * EMB, x, x, MROWS, EMB, EMB);
        ln_kernel<<<MROWS, 256>>>(h, x, ln2g + (size_t)l * EMB, ln2b + (size_t)l * EMB);
        gemm_kernel<false, true, true, false><<<g4096, 256>>>(h, W1 + (size_t)l * EMB * DFF, b1 + (size_t)l * DFF, nullptr, ff, MROWS, DFF, EMB);
        gemm_kernel<false, true, false, true><<<g1024, 256>>>(ff, W2 + (size_t)l * DFF * EMB, b2 + (size_t)l * EMB, x, x, MROWS, EMB, DFF);
    }

    ln_kernel<<<MROWS, 256>>>(h, x, lnfg, lnfb);
    // logits = h @ tok^T + lm_b   (tok is [V,E] -> B transposed)
    gemm_kernel<true, true, false, false><<<gvoc, 256>>>(h, tok, lmb, nullptr, out, MROWS, VOC, EMB);
}

// round 4
// speedup vs baseline: 2.3849x; 2.3849x over previous
#include <cuda_runtime.h>
#include <cuda_bf16.h>
#include <cstdint>
#include <math.h>

// ---------------- problem constants ----------------
constexpr int LAY = 8;
constexpr int NH  = 16;
constexpr int EMB = 1024;
constexpr int VOC = 32000;
constexpr int SEQ = 1024;
constexpr int BSZ = 2;
constexpr int DFF = 4096;
constexpr int MROWS = BSZ * SEQ;   // 2048

// ---------------- scratch (device globals; no cudaMalloc allowed) ----------------
__device__ float g_x [MROWS * EMB];
__device__ float g_h [MROWS * EMB];
__device__ float g_q [MROWS * EMB];
__device__ float g_k [MROWS * EMB];
__device__ float g_v [MROWS * EMB];
__device__ float g_o [MROWS * EMB];
__device__ float g_ff[MROWS * DFF];

// split-bf16 storage
constexpr size_t WPL = 4ull * EMB * EMB + 2ull * EMB * DFF;   // per layer
__device__ __align__(16) __nv_bfloat16 g_Whi[LAY * WPL];
__device__ __align__(16) __nv_bfloat16 g_Wlo[LAY * WPL];
__device__ __align__(16) __nv_bfloat16 g_tokhi[(size_t)VOC * EMB];
__device__ __align__(16) __nv_bfloat16 g_toklo[(size_t)VOC * EMB];
__device__ __align__(16) __nv_bfloat16 g_ahi[MROWS * DFF];
__device__ __align__(16) __nv_bfloat16 g_alo[MROWS * DFF];

// per-layer weight offsets inside WPL block (transposed to [N,K])
constexpr size_t OFF_WQ = 0;
constexpr size_t OFF_WK = 1ull << 20;
constexpr size_t OFF_WV = 2ull << 20;
constexpr size_t OFF_WO = 3ull << 20;
constexpr size_t OFF_W1 = 4ull << 20;   // [DFF, EMB]
constexpr size_t OFF_W2 = 8ull << 20;   // [EMB, DFF]

// ---------------- low-level helpers (sm_80-compatible instructions only) ----------------
__device__ __forceinline__ uint32_t smem_u32(const void* p) {
    uint32_t a;
    asm("{ .reg .u64 t; cvta.to.shared.u64 t, %1; cvt.u32.u64 %0, t; }" : "=r"(a) : "l"(p));
    return a;
}
__device__ __forceinline__ void cp16(uint32_t s, const void* g) {
    asm volatile("cp.async.cg.shared.global [%0], [%1], 16;" :: "r"(s), "l"(g) : "memory");
}
__device__ __forceinline__ void cp_commit() {
    asm volatile("cp.async.commit_group;" ::: "memory");
}
__device__ __forceinline__ void cp_wait1() {
    asm volatile("cp.async.wait_group 1;" ::: "memory");
}
__device__ __forceinline__ void cp_wait0() {
    asm volatile("cp.async.wait_group 0;" ::: "memory");
}
__device__ __forceinline__ void ldm_x4(uint32_t* r, uint32_t a) {
    asm volatile("ldmatrix.sync.aligned.m8n8.x4.shared.b16 {%0,%1,%2,%3}, [%4];"
                 : "=r"(r[0]), "=r"(r[1]), "=r"(r[2]), "=r"(r[3]) : "r"(a));
}
__device__ __forceinline__ void mma16816(float* d, const uint32_t* a, const uint32_t* b) {
    asm volatile(
        "mma.sync.aligned.m16n8k16.row.col.f32.bf16.bf16.f32 "
        "{%0,%1,%2,%3}, {%4,%5,%6,%7}, {%8,%9}, {%0,%1,%2,%3};"
        : "+f"(d[0]), "+f"(d[1]), "+f"(d[2]), "+f"(d[3])
        : "r"(a[0]), "r"(a[1]), "r"(a[2]), "r"(a[3]), "r"(b[0]), "r"(b[1]));
}

// ---------------- conversion kernels ----------------
__global__ void split_kernel(const float* __restrict__ in,
                             __nv_bfloat16* __restrict__ hi, __nv_bfloat16* __restrict__ lo,
                             int n)
{
    int i = blockIdx.x * blockDim.x + threadIdx.x;
    if (i >= n) return;
    float x = in[i];
    __nv_bfloat16 h = __float2bfloat16(x);
    hi[i] = h;
    lo[i] = __float2bfloat16(x - __bfloat162float(h));
}

// in: [K, N] fp32 row-major -> out hi/lo: [N, K] bf16 row-major (transpose + split)
__global__ void tsplit_kernel(const float* __restrict__ in,
                              __nv_bfloat16* __restrict__ hi, __nv_bfloat16* __restrict__ lo,
                              int K, int N)
{
    __shared__ float t[32][33];
    const int n0 = blockIdx.x * 32, k0 = blockIdx.y * 32;
    const int tx = threadIdx.x, ty = threadIdx.y;   // 32 x 8
    #pragma unroll
    for (int j = 0; j < 4; j++)
        t[ty + j * 8][tx] = in[(size_t)(k0 + ty + j * 8) * N + n0 + tx];
    __syncthreads();
    #pragma unroll
    for (int j = 0; j < 4; j++) {
        float x = t[tx][ty + j * 8];
        size_t o = (size_t)(n0 + ty + j * 8) * K + k0 + tx;
        __nv_bfloat16 h = __float2bfloat16(x);
        hi[o] = h;
        lo[o] = __float2bfloat16(x - __bfloat162float(h));
    }
}

// ---------------- embedding ----------------
__global__ void embed_kernel(float* __restrict__ x, const int* __restrict__ idx,
                             const float* __restrict__ tok, const float* __restrict__ pos)
{
    int i = blockIdx.x * blockDim.x + threadIdx.x;
    int e  = i & (EMB - 1);
    int bt = i >> 10;
    int t  = bt & (SEQ - 1);
    x[i] = tok[(size_t)idx[bt] * EMB + e] + pos[(size_t)t * EMB + e];
}

// ---------------- layernorm ----------------
__global__ __launch_bounds__(256) void ln_kernel(float* __restrict__ out,
                                                 const float* __restrict__ in,
                                                 const float* __restrict__ g,
                                                 const float* __restrict__ b)
{
    const int row = blockIdx.x;
    const float* xr = in + (size_t)row * EMB;
    float v[4];
    float s = 0.f;
    #pragma unroll
    for (int i = 0; i < 4; i++) { v[i] = xr[threadIdx.x + i * 256]; s += v[i]; }

    __shared__ float red[8];
    __shared__ float mean_s, rstd_s;

    #pragma unroll
    for (int o = 16; o; o >>= 1) s += __shfl_xor_sync(0xffffffffu, s, o);
    if ((threadIdx.x & 31) == 0) red[threadIdx.x >> 5] = s;
    __syncthreads();
    if (threadIdx.x == 0) {
        float t = 0.f;
        #pragma unroll
        for (int i = 0; i < 8; i++) t += red[i];
        mean_s = t * (1.f / EMB);
    }
    __syncthreads();
    const float m = mean_s;

    float ss = 0.f;
    #pragma unroll
    for (int i = 0; i < 4; i++) { float d = v[i] - m; ss += d * d; }
    #pragma unroll
    for (int o = 16; o; o >>= 1) ss += __shfl_xor_sync(0xffffffffu, ss, o);
    if ((threadIdx.x & 31) == 0) red[threadIdx.x >> 5] = ss;
    __syncthreads();
    if (threadIdx.x == 0) {
        float t = 0.f;
        #pragma unroll
        for (int i = 0; i < 8; i++) t += red[i];
        rstd_s = rsqrtf(t * (1.f / EMB) + 1e-5f);
    }
    __syncthreads();
    const float r = rstd_s;

    #pragma unroll
    for (int i = 0; i < 4; i++) {
        int col = threadIdx.x + i * 256;
        out[(size_t)row * EMB + col] = (v[i] - m) * r * g[col] + b[col];
    }
}

// ---------------- bf16x3 GEMM on mma.sync (m16n8k16) ----------------
// C[M,N] = A[M,K] @ Bt[N,K]^T, acc fp32. BM=BN=128, BK=32, 256 thr, 3-stage cp.async.
// smem per stage: Ahi | Alo | Bhi | Blo, each 128 rows x 40 bf16 pitch (80B rows).
constexpr int PITCH = 40;                       // bf16 elems; 80B rows -> conflict-free ldmatrix
constexpr int MAT_BYTES = 128 * PITCH * 2;      // 10240
constexpr int STAGE_BYTES = 4 * MAT_BYTES;      // 40960
constexpr int GSTAGES = 3;
constexpr int GEMM_SMEM = GSTAGES * STAGE_BYTES; // 122880

template<bool BIAS, bool RELU, bool RES>
__global__ __launch_bounds__(256) void mma_gemm(
    const __nv_bfloat16* __restrict__ Ahi, const __nv_bfloat16* __restrict__ Alo,
    const __nv_bfloat16* __restrict__ Bhi, const __nv_bfloat16* __restrict__ Blo,
    const float* __restrict__ bias, const float* __restrict__ res,
    float* __restrict__ C, int M, int N, int K)
{
    extern __shared__ char sm[];
    const int tid  = threadIdx.x;
    const int lane = tid & 31, wid = tid >> 5;
    const int wm = wid >> 1, wn = wid & 1;      // 4 x 2 warp grid
    const int bm0 = blockIdx.x * 128, bn0 = blockIdx.y * 128;
    const uint32_t smb = smem_u32(sm);

    // cp.async indexing: 2 chunks per thread per matrix (128 rows x 4 segs)
    const int r_c0 = tid >> 2,        seg0 = tid & 3;
    const int r_c1 = (tid + 256) >> 2, seg1 = (tid + 256) & 3;

    float acc[2][8][4];
    #pragma unroll
    for (int i = 0; i < 2; i++)
        #pragma unroll
        for (int j = 0; j < 8; j++)
            #pragma unroll
            for (int q = 0; q < 4; q++) acc[i][j][q] = 0.f;

    const int NC = K >> 5;

    // ldmatrix per-thread base offsets (within a stage)
    const int rA = lane & 15, cA = lane >> 4;
    uint32_t offA[2];
    #pragma unroll
    for (int i = 0; i < 2; i++)
        offA[i] = (uint32_t)(((wm * 32 + i * 16 + rA) * PITCH + cA * 8) * 2);
    const int rB = (lane & 7) | ((lane >> 4) << 3), cB = (lane >> 3) & 1;
    uint32_t offB[4];
    #pragma unroll
    for (int j = 0; j < 4; j++)
        offB[j] = (uint32_t)(((wn * 64 + j * 16 + rB) * PITCH + cB * 8) * 2);

    auto issue = [&](int c) {
        const int k0 = c << 5;
        const uint32_t st = smb + (c % GSTAGES) * STAGE_BYTES;
        {
            const uint32_t so = (uint32_t)(r_c0 * PITCH * 2 + seg0 * 16);
            const size_t ga = (size_t)(bm0 + r_c0) * K + k0 + seg0 * 8;
            const size_t gb = (size_t)(bn0 + r_c0) * K + k0 + seg0 * 8;
            cp16(st + so,                 Ahi + ga);
            cp16(st + MAT_BYTES + so,     Alo + ga);
            cp16(st + 2 * MAT_BYTES + so, Bhi + gb);
            cp16(st + 3 * MAT_BYTES + so, Blo + gb);
        }
        {
            const uint32_t so = (uint32_t)(r_c1 * PITCH * 2 + seg1 * 16);
            const size_t ga = (size_t)(bm0 + r_c1) * K + k0 + seg1 * 8;
            const size_t gb = (size_t)(bn0 + r_c1) * K + k0 + seg1 * 8;
            cp16(st + so,                 Ahi + ga);
            cp16(st + MAT_BYTES + so,     Alo + ga);
            cp16(st + 2 * MAT_BYTES + so, Bhi + gb);
            cp16(st + 3 * MAT_BYTES + so, Blo + gb);
        }
        cp_commit();
    };

    issue(0);
    issue(1);

    for (int c = 0; c < NC; c++) {
        if (c + 2 < NC) cp_wait1(); else cp_wait0();
        __syncthreads();
        if (c + 2 < NC) issue(c + 2);

        const uint32_t st = smb + (c % GSTAGES) * STAGE_BYTES;
        #pragma unroll
        for (int ks = 0; ks < 2; ks++) {
            const uint32_t kadd = ks * 32;   // 16 bf16 = 32 bytes
            uint32_t ah[2][4], al[2][4], bh[4][4], bl[4][4];
            #pragma unroll
            for (int i = 0; i < 2; i++) {
                ldm_x4(ah[i], st + offA[i] + kadd);
                ldm_x4(al[i], st + MAT_BYTES + offA[i] + kadd);
            }
            #pragma unroll
            for (int j = 0; j < 4; j++) {
                ldm_x4(bh[j], st + 2 * MAT_BYTES + offB[j] + kadd);
                ldm_x4(bl[j], st + 3 * MAT_BYTES + offB[j] + kadd);
            }
            #pragma unroll
            for (int i = 0; i < 2; i++)
                #pragma unroll
                for (int j = 0; j < 8; j++) {
                    const int j4 = j >> 1, hh = (j & 1) * 2;
                    mma16816(acc[i][j], ah[i], &bh[j4][hh]);
                    mma16816(acc[i][j], ah[i], &bl[j4][hh]);
                    mma16816(acc[i][j], al[i], &bh[j4][hh]);
                }
        }
        __syncthreads();
    }

    // epilogue: fragment layout m16n8 -> (row g / g+8, col 2t, 2t+1)
    const int g2 = lane >> 2, t2 = lane & 3;
    #pragma unroll
    for (int i = 0; i < 2; i++) {
        #pragma unroll
        for (int j = 0; j < 8; j++) {
            const int row0 = bm0 + wm * 32 + i * 16 + g2;
            const int col  = bn0 + wn * 64 + j * 8 + t2 * 2;
            #pragma unroll
            for (int half = 0; half < 2; half++) {
                const int row = row0 + half * 8;
                float2 v;
                v.x = acc[i][j][half * 2 + 0];
                v.y = acc[i][j][half * 2 + 1];
                if (BIAS) {
                    v.x += bias[col];
                    v.y += bias[col + 1];
                }
                if (RES) {
                    const float2 rr = *reinterpret_cast<const float2*>(res + (size_t)row * N + col);
                    v.x += rr.x; v.y += rr.y;
                }
                if (RELU) {
                    v.x = fmaxf(v.x, 0.f); v.y = fmaxf(v.y, 0.f);
                }
                *reinterpret_cast<float2*>(C + (size_t)row * N + col) = v;
            }
        }
    }
}

// ---------------- flash attention (fp32, causal), 64-query tiles ----------------
constexpr int QP = 68;
constexpr int KP = 65;
constexpr int VP = 68;
constexpr int PP = 68;
constexpr int ATTN_SMEM = (64 * QP + 64 * KP + 64 * VP + 64 * PP) * 4;

__global__ __launch_bounds__(256) void attn_kernel(const float* __restrict__ Q,
                                                   const float* __restrict__ Kc,
                                                   const float* __restrict__ Vc,
                                                   float* __restrict__ O)
{
    extern __shared__ float smf[];
    float* Qs = smf;
    float* Ks = Qs + 64 * QP;
    float* Vs = Ks + 64 * KP;
    float* Ps = Vs + 64 * VP;

    const int qt  = blockIdx.x;
    const int bh  = blockIdx.y;
    const int b   = bh >> 4;
    const int h   = bh & 15;
    const int tid = threadIdx.x;
    const int ty  = tid >> 4;
    const int tx  = tid & 15;

    const size_t baseQ = ((size_t)(b * SEQ + qt * 64)) * EMB + h * 64;

    #pragma unroll
    for (int r = 0; r < 4; r++) {
        int id = tid + r * 256;
        int row = id >> 4, c4 = id & 15;
        float4 qv = *reinterpret_cast<const float4*>(Q + baseQ + (size_t)row * EMB + c4 * 4);
        *reinterpret_cast<float4*>(&Qs[row * QP + c4 * 4]) = qv;
    }

    float m[4], l[4], oacc[4][4];
    #pragma unroll
    for (int i = 0; i < 4; i++) {
        m[i] = -1e30f; l[i] = 0.f;
        #pragma unroll
        for (int j = 0; j < 4; j++) oacc[i][j] = 0.f;
    }
    const float scale = 0.125f;

    for (int jt = 0; jt <= qt; jt++) {
        __syncthreads();
        const size_t baseK = ((size_t)(b * SEQ + jt * 64)) * EMB + h * 64;
        #pragma unroll
        for (int r = 0; r < 4; r++) {
            int id = tid + r * 256;
            int row = id >> 4, c4 = id & 15;
            float4 kv = *reinterpret_cast<const float4*>(Kc + baseK + (size_t)row * EMB + c4 * 4);
            Ks[(c4 * 4 + 0) * KP + row] = kv.x;
            Ks[(c4 * 4 + 1) * KP + row] = kv.y;
            Ks[(c4 * 4 + 2) * KP + row] = kv.z;
            Ks[(c4 * 4 + 3) * KP + row] = kv.w;
            float4 vv = *reinterpret_cast<const float4*>(Vc + baseK + (size_t)row * EMB + c4 * 4);
            *reinterpret_cast<float4*>(&Vs[row * VP + c4 * 4]) = vv;
        }
        __syncthreads();

        float s[4][4];
        #pragma unroll
        for (int i = 0; i < 4; i++)
            #pragma unroll
            for (int j = 0; j < 4; j++) s[i][j] = 0.f;

        #pragma unroll 8
        for (int d = 0; d < 64; d++) {
            float qa[4], kb[4];
            #pragma unroll
            for (int i = 0; i < 4; i++) qa[i] = Qs[(ty * 4 + i) * QP + d];
            #pragma unroll
            for (int j = 0; j < 4; j++) kb[j] = Ks[d * KP + tx * 4 + j];
            #pragma unroll
            for (int i = 0; i < 4; i++)
                #pragma unroll
                for (int j = 0; j < 4; j++) s[i][j] += qa[i] * kb[j];
        }

        const bool diag = (jt == qt);
        #pragma unroll
        for (int i = 0; i < 4; i++)
            #pragma unroll
            for (int j = 0; j < 4; j++) {
                s[i][j] *= scale;
                if (diag && (tx * 4 + j) > (ty * 4 + i)) s[i][j] = -1e30f;
            }

        #pragma unroll
        for (int i = 0; i < 4; i++) {
            float mx = fmaxf(fmaxf(s[i][0], s[i][1]), fmaxf(s[i][2], s[i][3]));
            #pragma unroll
            for (int o = 8; o; o >>= 1) mx = fmaxf(mx, __shfl_xor_sync(0xffffffffu, mx, o, 16));
            float mnew = fmaxf(m[i], mx);
            float alpha = __expf(m[i] - mnew);
            m[i] = mnew;
            float rs = 0.f;
            #pragma unroll
            for (int j = 0; j < 4; j++) {
                float p = __expf(s[i][j] - mnew);
                s[i][j] = p; rs += p;
            }
            #pragma unroll
            for (int o = 8; o; o >>= 1) rs += __shfl_xor_sync(0xffffffffu, rs, o, 16);
            l[i] = l[i] * alpha + rs;
            #pragma unroll
            for (int j = 0; j < 4; j++) oacc[i][j] *= alpha;
        }

        #pragma unroll
        for (int i = 0; i < 4; i++)
            #pragma unroll
            for (int j = 0; j < 4; j++)
                Ps[(ty * 4 + i) * PP + tx * 4 + j] = s[i][j];
        __syncthreads();

        #pragma unroll 8
        for (int kk = 0; kk < 64; kk++) {
            float pa[4], vb[4];
            #pragma unroll
            for (int i = 0; i < 4; i++) pa[i] = Ps[(ty * 4 + i) * PP + kk];
            #pragma unroll
            for (int j = 0; j < 4; j++) vb[j] = Vs[kk * VP + tx * 4 + j];
            #pragma unroll
            for (int i = 0; i < 4; i++)
                #pragma unroll
                for (int j = 0; j < 4; j++) oacc[i][j] += pa[i] * vb[j];
        }
    }

    #pragma unroll
    for (int i = 0; i < 4; i++) {
        float inv = 1.f / l[i];
        #pragma unroll
        for (int j = 0; j < 4; j++)
            O[baseQ + (size_t)(ty * 4 + i) * EMB + tx * 4 + j] = oacc[i][j] * inv;
    }
}

// ---------------- host orchestration ----------------
extern "C" void kernel_launch(void* const* d_in, const int* in_sizes, int n_in,
                              void* d_out, int out_size)
{
    const int*   idx  = (const int*)  d_in[0];
    const float* tok  = (const float*)d_in[1];
    const float* pos  = (const float*)d_in[2];
    const float* Wq   = (const float*)d_in[3];
    const float* Wk   = (const float*)d_in[4];
    const float* Wv   = (const float*)d_in[5];
    const float* Wo   = (const float*)d_in[6];
    const float* bo   = (const float*)d_in[7];
    const float* W1   = (const float*)d_in[8];
    const float* b1   = (const float*)d_in[9];
    const float* W2   = (const float*)d_in[10];
    const float* b2   = (const float*)d_in[11];
    const float* ln1g = (const float*)d_in[12];
    const float* ln1b = (const float*)d_in[13];
    const float* ln2g = (const float*)d_in[14];
    const float* ln2b = (const float*)d_in[15];
    const float* lnfg = (const float*)d_in[16];
    const float* lnfb = (const float*)d_in[17];
    const float* lmb  = (const float*)d_in[18];
    float* out = (float*)d_out;

    float *x, *h, *q, *k, *v, *o, *ff;
    __nv_bfloat16 *whi, *wlo, *tokhi, *toklo, *ahi, *alo;
    cudaGetSymbolAddress((void**)&x,  g_x);
    cudaGetSymbolAddress((void**)&h,  g_h);
    cudaGetSymbolAddress((void**)&q,  g_q);
    cudaGetSymbolAddress((void**)&k,  g_k);
    cudaGetSymbolAddress((void**)&v,  g_v);
    cudaGetSymbolAddress((void**)&o,  g_o);
    cudaGetSymbolAddress((void**)&ff, g_ff);
    cudaGetSymbolAddress((void**)&whi, g_Whi);
    cudaGetSymbolAddress((void**)&wlo, g_Wlo);
    cudaGetSymbolAddress((void**)&tokhi, g_tokhi);
    cudaGetSymbolAddress((void**)&toklo, g_toklo);
    cudaGetSymbolAddress((void**)&ahi, g_ahi);
    cudaGetSymbolAddress((void**)&alo, g_alo);

    cudaFuncSetAttribute(attn_kernel, cudaFuncAttributeMaxDynamicSharedMemorySize, ATTN_SMEM);
    cudaFuncSetAttribute(mma_gemm<false,false,false>, cudaFuncAttributeMaxDynamicSharedMemorySize, GEMM_SMEM);
    cudaFuncSetAttribute(mma_gemm<true,false,true>,   cudaFuncAttributeMaxDynamicSharedMemorySize, GEMM_SMEM);
    cudaFuncSetAttribute(mma_gemm<true,true,false>,   cudaFuncAttributeMaxDynamicSharedMemorySize, GEMM_SMEM);
    cudaFuncSetAttribute(mma_gemm<true,false,false>,  cudaFuncAttributeMaxDynamicSharedMemorySize, GEMM_SMEM);

    const dim3 tb(32, 8);

    // ---- weight conversion (transpose + split to bf16 hi/lo) ----
    for (int l = 0; l < LAY; l++) {
        const size_t wb = (size_t)l * WPL;
        const size_t we = (size_t)l * EMB * EMB;
        tsplit_kernel<<<dim3(EMB / 32, EMB / 32), tb>>>(Wq + we, whi + wb + OFF_WQ, wlo + wb + OFF_WQ, EMB, EMB);
        tsplit_kernel<<<dim3(EMB / 32, EMB / 32), tb>>>(Wk + we, whi + wb + OFF_WK, wlo + wb + OFF_WK, EMB, EMB);
        tsplit_kernel<<<dim3(EMB / 32, EMB / 32), tb>>>(Wv + we, whi + wb + OFF_WV, wlo + wb + OFF_WV, EMB, EMB);
        tsplit_kernel<<<dim3(EMB / 32, EMB / 32), tb>>>(Wo + we, whi + wb + OFF_WO, wlo + wb + OFF_WO, EMB, EMB);
        tsplit_kernel<<<dim3(DFF / 32, EMB / 32), tb>>>(W1 + (size_t)l * EMB * DFF, whi + wb + OFF_W1, wlo + wb + OFF_W1, EMB, DFF);
        tsplit_kernel<<<dim3(EMB / 32, DFF / 32), tb>>>(W2 + (size_t)l * DFF * EMB, whi + wb + OFF_W2, wlo + wb + OFF_W2, DFF, EMB);
    }
    split_kernel<<<((int)((size_t)VOC * EMB) + 255) / 256, 256>>>(tok, tokhi, toklo, VOC * EMB);

    embed_kernel<<<(MROWS * EMB) / 256, 256>>>(x, idx, tok, pos);

    const dim3 g1024(MROWS / 128, EMB / 128);
    const dim3 g4096(MROWS / 128, DFF / 128);
    const dim3 gvoc (MROWS / 128, VOC / 128);
    const int nE = MROWS * EMB, nF = MROWS * DFF;

    for (int l = 0; l < LAY; l++) {
        const size_t wb = (size_t)l * WPL;
        ln_kernel<<<MROWS, 256>>>(h, x, ln1g + (size_t)l * EMB, ln1b + (size_t)l * EMB);
        split_kernel<<<nE / 256, 256>>>(h, ahi, alo, nE);
        mma_gemm<false,false,false><<<g1024, 256, GEMM_SMEM>>>(ahi, alo, whi + wb + OFF_WQ, wlo + wb + OFF_WQ, nullptr, nullptr, q, MROWS, EMB, EMB);
        mma_gemm<false,false,false><<<g1024, 256, GEMM_SMEM>>>(ahi, alo, whi + wb + OFF_WK, wlo + wb + OFF_WK, nullptr, nullptr, k, MROWS, EMB, EMB);
        mma_gemm<false,false,false><<<g1024, 256, GEMM_SMEM>>>(ahi, alo, whi + wb + OFF_WV, wlo + wb + OFF_WV, nullptr, nullptr, v, MROWS, EMB, EMB);
        attn_kernel<<<dim3(SEQ / 64, BSZ * NH), 256, ATTN_SMEM>>>(q, k, v, o);
        split_kernel<<<nE / 256, 256>>>(o, ahi, alo, nE);
        mma_gemm<true,false,true><<<g1024, 256, GEMM_SMEM>>>(ahi, alo, whi + wb + OFF_WO, wlo + wb + OFF_WO, bo + (size_t)l * EMB, x, x, MROWS, EMB, EMB);
        ln_kernel<<<MROWS, 256>>>(h, x, ln2g + (size_t)l * EMB, ln2b + (size_t)l * EMB);
        split_kernel<<<nE / 256, 256>>>(h, ahi, alo, nE);
        mma_gemm<true,true,false><<<g4096, 256, GEMM_SMEM>>>(ahi, alo, whi + wb + OFF_W1, wlo + wb + OFF_W1, b1 + (size_t)l * DFF, nullptr, ff, MROWS, DFF, EMB);
        split_kernel<<<nF / 256, 256>>>(ff, ahi, alo, nF);
        mma_gemm<true,false,true><<<g1024, 256, GEMM_SMEM>>>(ahi, alo, whi + wb + OFF_W2, wlo + wb + OFF_W2, b2 + (size_t)l * EMB, x, x, MROWS, EMB, DFF);
    }

    ln_kernel<<<MROWS, 256>>>(h, x, lnfg, lnfb);
    split_kernel<<<nE / 256, 256>>>(h, ahi, alo, nE);
    mma_gemm<true,false,false><<<gvoc, 256, GEMM_SMEM>>>(ahi, alo, tokhi, toklo, lmb, nullptr, out, MROWS, VOC, EMB);
}

// round 6
// speedup vs baseline: 2.8022x; 1.1750x over previous
#include <cuda_runtime.h>
#include <cuda_bf16.h>
#include <cstdint>
#include <math.h>

// ---------------- problem constants ----------------
constexpr int LAY = 8;
constexpr int NH  = 16;
constexpr int EMB = 1024;
constexpr int VOC = 32000;
constexpr int SEQ = 1024;
constexpr int BSZ = 2;
constexpr int DFF = 4096;
constexpr int MROWS = BSZ * SEQ;   // 2048

// ---------------- scratch (device globals; no cudaMalloc allowed) ----------------
__device__ float g_x [MROWS * EMB];

// split-bf16 weights
constexpr size_t WPL = 4ull * EMB * EMB + 2ull * EMB * DFF;
__device__ __align__(16) __nv_bfloat16 g_Whi[LAY * WPL];
__device__ __align__(16) __nv_bfloat16 g_Wlo[LAY * WPL];
__device__ __align__(16) __nv_bfloat16 g_tokhi[(size_t)VOC * EMB];
__device__ __align__(16) __nv_bfloat16 g_toklo[(size_t)VOC * EMB];

// split-bf16 activations
__device__ __align__(16) __nv_bfloat16 g_ahi[MROWS * EMB];
__device__ __align__(16) __nv_bfloat16 g_alo[MROWS * EMB];
__device__ __align__(16) __nv_bfloat16 g_qhi[MROWS * EMB];
__device__ __align__(16) __nv_bfloat16 g_qlo[MROWS * EMB];
__device__ __align__(16) __nv_bfloat16 g_khi[MROWS * EMB];
__device__ __align__(16) __nv_bfloat16 g_klo[MROWS * EMB];
__device__ __align__(16) __nv_bfloat16 g_vhi[MROWS * EMB];
__device__ __align__(16) __nv_bfloat16 g_vlo[MROWS * EMB];
__device__ __align__(16) __nv_bfloat16 g_ohi[MROWS * EMB];
__device__ __align__(16) __nv_bfloat16 g_olo[MROWS * EMB];
__device__ __align__(16) __nv_bfloat16 g_fhi[MROWS * DFF];
__device__ __align__(16) __nv_bfloat16 g_flo[MROWS * DFF];

// per-layer weight offsets inside WPL block (transposed to [N,K])
constexpr size_t OFF_WQ = 0;
constexpr size_t OFF_WK = 1ull << 20;
constexpr size_t OFF_WV = 2ull << 20;
constexpr size_t OFF_WO = 3ull << 20;
constexpr size_t OFF_W1 = 4ull << 20;
constexpr size_t OFF_W2 = 8ull << 20;

// ---------------- low-level helpers ----------------
__device__ __forceinline__ uint32_t smem_u32(const void* p) {
    uint32_t a;
    asm("{ .reg .u64 t; cvta.to.shared.u64 t, %1; cvt.u32.u64 %0, t; }" : "=r"(a) : "l"(p));
    return a;
}
__device__ __forceinline__ void cp16(uint32_t s, const void* g) {
    asm volatile("cp.async.cg.shared.global [%0], [%1], 16;" :: "r"(s), "l"(g) : "memory");
}
__device__ __forceinline__ void cp_commit() {
    asm volatile("cp.async.commit_group;" ::: "memory");
}
__device__ __forceinline__ void cp_wait1() {
    asm volatile("cp.async.wait_group 1;" ::: "memory");
}
__device__ __forceinline__ void cp_wait0() {
    asm volatile("cp.async.wait_group 0;" ::: "memory");
}
__device__ __forceinline__ void ldm_x4(uint32_t* r, uint32_t a) {
    asm volatile("ldmatrix.sync.aligned.m8n8.x4.shared.b16 {%0,%1,%2,%3}, [%4];"
                 : "=r"(r[0]), "=r"(r[1]), "=r"(r[2]), "=r"(r[3]) : "r"(a));
}
__device__ __forceinline__ void ldm_x4t(uint32_t* r, uint32_t a) {
    asm volatile("ldmatrix.sync.aligned.m8n8.x4.trans.shared.b16 {%0,%1,%2,%3}, [%4];"
                 : "=r"(r[0]), "=r"(r[1]), "=r"(r[2]), "=r"(r[3]) : "r"(a));
}
__device__ __forceinline__ void mma16816(float* d, const uint32_t* a, const uint32_t* b) {
    asm volatile(
        "mma.sync.aligned.m16n8k16.row.col.f32.bf16.bf16.f32 "
        "{%0,%1,%2,%3}, {%4,%5,%6,%7}, {%8,%9}, {%0,%1,%2,%3};"
        : "+f"(d[0]), "+f"(d[1]), "+f"(d[2]), "+f"(d[3])
        : "r"(a[0]), "r"(a[1]), "r"(a[2]), "r"(a[3]), "r"(b[0]), "r"(b[1]));
}
__device__ __forceinline__ uint32_t pack_bf16(float x, float y) {
    __nv_bfloat162 t = __floats2bfloat162_rn(x, y);
    return *reinterpret_cast<uint32_t*>(&t);
}

// ---------------- conversion kernels ----------------
// vectorized split (4 elems/thread)
__global__ void split4_kernel(const float* __restrict__ in,
                              __nv_bfloat16* __restrict__ hi, __nv_bfloat16* __restrict__ lo,
                              int n4)
{
    int i = blockIdx.x * blockDim.x + threadIdx.x;
    if (i >= n4) return;
    float4 v = reinterpret_cast<const float4*>(in)[i];
    float hx = __bfloat162float(__float2bfloat16_rn(v.x));
    float hy = __bfloat162float(__float2bfloat16_rn(v.y));
    float hz = __bfloat162float(__float2bfloat16_rn(v.z));
    float hw = __bfloat162float(__float2bfloat16_rn(v.w));
    uint32_t* hp = reinterpret_cast<uint32_t*>(hi) + i * 2;
    uint32_t* lp = reinterpret_cast<uint32_t*>(lo) + i * 2;
    hp[0] = pack_bf16(v.x, v.y);
    hp[1] = pack_bf16(v.z, v.w);
    lp[0] = pack_bf16(v.x - hx, v.y - hy);
    lp[1] = pack_bf16(v.z - hz, v.w - hw);
}

// in: [K, N] fp32 row-major -> out hi/lo: [N, K] bf16 row-major (transpose + split)
__global__ void tsplit_kernel(const float* __restrict__ in,
                              __nv_bfloat16* __restrict__ hi, __nv_bfloat16* __restrict__ lo,
                              int K, int N)
{
    __shared__ float t[32][33];
    const int n0 = blockIdx.x * 32, k0 = blockIdx.y * 32;
    const int tx = threadIdx.x, ty = threadIdx.y;   // 32 x 8
    #pragma unroll
    for (int j = 0; j < 4; j++)
        t[ty + j * 8][tx] = in[(size_t)(k0 + ty + j * 8) * N + n0 + tx];
    __syncthreads();
    #pragma unroll
    for (int j = 0; j < 4; j++) {
        float x = t[tx][ty + j * 8];
        size_t o = (size_t)(n0 + ty + j * 8) * K + k0 + tx;
        __nv_bfloat16 h = __float2bfloat16(x);
        hi[o] = h;
        lo[o] = __float2bfloat16(x - __bfloat162float(h));
    }
}

// ---------------- embedding ----------------
__global__ void embed_kernel(float* __restrict__ x, const int* __restrict__ idx,
                             const float* __restrict__ tok, const float* __restrict__ pos)
{
    int i = blockIdx.x * blockDim.x + threadIdx.x;
    int e  = i & (EMB - 1);
    int bt = i >> 10;
    int t  = bt & (SEQ - 1);
    x[i] = tok[(size_t)idx[bt] * EMB + e] + pos[(size_t)t * EMB + e];
}

// ---------------- layernorm with fused bf16 split output ----------------
__global__ __launch_bounds__(256) void ln_split_kernel(
    __nv_bfloat16* __restrict__ ohi, __nv_bfloat16* __restrict__ olo,
    const float* __restrict__ in,
    const float* __restrict__ g, const float* __restrict__ b)
{
    const int row = blockIdx.x;
    const int c0 = threadIdx.x * 4;
    const float4 v = *reinterpret_cast<const float4*>(in + (size_t)row * EMB + c0);

    float s = v.x + v.y + v.z + v.w;
    __shared__ float red[8];
    __shared__ float mean_s, rstd_s;

    #pragma unroll
    for (int o = 16; o; o >>= 1) s += __shfl_xor_sync(0xffffffffu, s, o);
    if ((threadIdx.x & 31) == 0) red[threadIdx.x >> 5] = s;
    __syncthreads();
    if (threadIdx.x == 0) {
        float t = 0.f;
        #pragma unroll
        for (int i = 0; i < 8; i++) t += red[i];
        mean_s = t * (1.f / EMB);
    }
    __syncthreads();
    const float m = mean_s;

    float dx = v.x - m, dy = v.y - m, dz = v.z - m, dw = v.w - m;
    float ss = dx * dx + dy * dy + dz * dz + dw * dw;
    #pragma unroll
    for (int o = 16; o; o >>= 1) ss += __shfl_xor_sync(0xffffffffu, ss, o);
    if ((threadIdx.x & 31) == 0) red[threadIdx.x >> 5] = ss;
    __syncthreads();
    if (threadIdx.x == 0) {
        float t = 0.f;
        #pragma unroll
        for (int i = 0; i < 8; i++) t += red[i];
        rstd_s = rsqrtf(t * (1.f / EMB) + 1e-5f);
    }
    __syncthreads();
    const float r = rstd_s;

    const float4 g4 = *reinterpret_cast<const float4*>(g + c0);
    const float4 b4 = *reinterpret_cast<const float4*>(b + c0);
    float ox = dx * r * g4.x + b4.x;
    float oy = dy * r * g4.y + b4.y;
    float oz = dz * r * g4.z + b4.z;
    float ow = dw * r * g4.w + b4.w;

    float hx = __bfloat162float(__float2bfloat16_rn(ox));
    float hy = __bfloat162float(__float2bfloat16_rn(oy));
    float hz = __bfloat162float(__float2bfloat16_rn(oz));
    float hw = __bfloat162float(__float2bfloat16_rn(ow));
    uint32_t* hp = reinterpret_cast<uint32_t*>(ohi + (size_t)row * EMB + c0);
    uint32_t* lp = reinterpret_cast<uint32_t*>(olo + (size_t)row * EMB + c0);
    hp[0] = pack_bf16(ox, oy);
    hp[1] = pack_bf16(oz, ow);
    lp[0] = pack_bf16(ox - hx, oy - hy);
    lp[1] = pack_bf16(oz - hz, ow - hw);
}

// ---------------- bf16x3 GEMM on mma.sync (m16n8k16) ----------------
constexpr int PITCH = 40;
constexpr int MAT_BYTES = 128 * PITCH * 2;
constexpr int STAGE_BYTES = 4 * MAT_BYTES;
constexpr int GSTAGES = 3;
constexpr int GEMM_SMEM = GSTAGES * STAGE_BYTES;

template<bool BIAS, bool RELU, bool RES, bool SPLIT>
__global__ __launch_bounds__(256) void mma_gemm(
    const __nv_bfloat16* __restrict__ Ahi, const __nv_bfloat16* __restrict__ Alo,
    const __nv_bfloat16* __restrict__ Bhi, const __nv_bfloat16* __restrict__ Blo,
    const float* __restrict__ bias, const float* __restrict__ res,
    float* __restrict__ C,
    __nv_bfloat16* __restrict__ Chi, __nv_bfloat16* __restrict__ Clo,
    int M, int N, int K)
{
    extern __shared__ char sm[];
    const int tid  = threadIdx.x;
    const int lane = tid & 31, wid = tid >> 5;
    const int wm = wid >> 1, wn = wid & 1;
    const int bm0 = blockIdx.x * 128, bn0 = blockIdx.y * 128;
    const uint32_t smb = smem_u32(sm);

    const int r_c0 = tid >> 2,         seg0 = tid & 3;
    const int r_c1 = (tid + 256) >> 2, seg1 = (tid + 256) & 3;

    float acc[2][8][4];
    #pragma unroll
    for (int i = 0; i < 2; i++)
        #pragma unroll
        for (int j = 0; j < 8; j++)
            #pragma unroll
            for (int q = 0; q < 4; q++) acc[i][j][q] = 0.f;

    const int NC = K >> 5;

    const int rA = lane & 15, cA = lane >> 4;
    uint32_t offA[2];
    #pragma unroll
    for (int i = 0; i < 2; i++)
        offA[i] = (uint32_t)(((wm * 32 + i * 16 + rA) * PITCH + cA * 8) * 2);
    const int rB = (lane & 7) | ((lane >> 4) << 3), cB = (lane >> 3) & 1;
    uint32_t offB[4];
    #pragma unroll
    for (int j = 0; j < 4; j++)
        offB[j] = (uint32_t)(((wn * 64 + j * 16 + rB) * PITCH + cB * 8) * 2);

    auto issue = [&](int c) {
        const int k0 = c << 5;
        const uint32_t st = smb + (c % GSTAGES) * STAGE_BYTES;
        {
            const uint32_t so = (uint32_t)(r_c0 * PITCH * 2 + seg0 * 16);
            const size_t ga = (size_t)(bm0 + r_c0) * K + k0 + seg0 * 8;
            const size_t gb = (size_t)(bn0 + r_c0) * K + k0 + seg0 * 8;
            cp16(st + so,                 Ahi + ga);
            cp16(st + MAT_BYTES + so,     Alo + ga);
            cp16(st + 2 * MAT_BYTES + so, Bhi + gb);
            cp16(st + 3 * MAT_BYTES + so, Blo + gb);
        }
        {
            const uint32_t so = (uint32_t)(r_c1 * PITCH * 2 + seg1 * 16);
            const size_t ga = (size_t)(bm0 + r_c1) * K + k0 + seg1 * 8;
            const size_t gb = (size_t)(bn0 + r_c1) * K + k0 + seg1 * 8;
            cp16(st + so,                 Ahi + ga);
            cp16(st + MAT_BYTES + so,     Alo + ga);
            cp16(st + 2 * MAT_BYTES + so, Bhi + gb);
            cp16(st + 3 * MAT_BYTES + so, Blo + gb);
        }
        cp_commit();
    };

    issue(0);
    issue(1);

    for (int c = 0; c < NC; c++) {
        if (c + 2 < NC) cp_wait1(); else cp_wait0();
        __syncthreads();
        if (c + 2 < NC) issue(c + 2);

        const uint32_t st = smb + (c % GSTAGES) * STAGE_BYTES;
        #pragma unroll
        for (int ks = 0; ks < 2; ks++) {
            const uint32_t kadd = ks * 32;
            uint32_t ah[2][4], al[2][4], bh[4][4], bl[4][4];
            #pragma unroll
            for (int i = 0; i < 2; i++) {
                ldm_x4(ah[i], st + offA[i] + kadd);
                ldm_x4(al[i], st + MAT_BYTES + offA[i] + kadd);
            }
            #pragma unroll
            for (int j = 0; j < 4; j++) {
                ldm_x4(bh[j], st + 2 * MAT_BYTES + offB[j] + kadd);
                ldm_x4(bl[j], st + 3 * MAT_BYTES + offB[j] + kadd);
            }
            #pragma unroll
            for (int i = 0; i < 2; i++)
                #pragma unroll
                for (int j = 0; j < 8; j++) {
                    const int j4 = j >> 1, hh = (j & 1) * 2;
                    mma16816(acc[i][j], ah[i], &bh[j4][hh]);
                    mma16816(acc[i][j], ah[i], &bl[j4][hh]);
                    mma16816(acc[i][j], al[i], &bh[j4][hh]);
                }
        }
        __syncthreads();
    }

    const int g2 = lane >> 2, t2 = lane & 3;
    #pragma unroll
    for (int i = 0; i < 2; i++) {
        #pragma unroll
        for (int j = 0; j < 8; j++) {
            const int row0 = bm0 + wm * 32 + i * 16 + g2;
            const int col  = bn0 + wn * 64 + j * 8 + t2 * 2;
            #pragma unroll
            for (int half = 0; half < 2; half++) {
                const int row = row0 + half * 8;
                float vx = acc[i][j][half * 2 + 0];
                float vy = acc[i][j][half * 2 + 1];
                if (BIAS) { vx += bias[col]; vy += bias[col + 1]; }
                if (RES) {
                    const float2 rr = *reinterpret_cast<const float2*>(res + (size_t)row * N + col);
                    vx += rr.x; vy += rr.y;
                }
                if (RELU) { vx = fmaxf(vx, 0.f); vy = fmaxf(vy, 0.f); }
                if (SPLIT) {
                    float hx = __bfloat162float(__float2bfloat16_rn(vx));
                    float hy = __bfloat162float(__float2bfloat16_rn(vy));
                    *reinterpret_cast<uint32_t*>(Chi + (size_t)row * N + col) = pack_bf16(vx, vy);
                    *reinterpret_cast<uint32_t*>(Clo + (size_t)row * N + col) = pack_bf16(vx - hx, vy - hy);
                } else {
                    float2 v; v.x = vx; v.y = vy;
                    *reinterpret_cast<float2*>(C + (size_t)row * N + col) = v;
                }
            }
        }
    }
}

// ---------------- tensor-core flash attention (bf16x3, causal) ----------------
// 128 q-rows per block (4 warps x 32 rows), 64-key tiles, 2-stage cp.async K/V.
constexpr int AP = 72;                         // smem pitch (bf16)
constexpr int AQ_HI = 0;
constexpr int AQ_LO = 128 * AP;                // 9216
constexpr int AST0  = 2 * 128 * AP;            // 18432
constexpr int AMAT  = 64 * AP;                 // 4608 (one K/V matrix)
constexpr int ASTAGE = 4 * AMAT;               // 18432
constexpr int ATTN_SMEM = (AST0 + 2 * ASTAGE) * 2;   // 110,592 bytes

__global__ __launch_bounds__(128) void attn_tc_kernel(
    const __nv_bfloat16* __restrict__ Qhi, const __nv_bfloat16* __restrict__ Qlo,
    const __nv_bfloat16* __restrict__ Khi, const __nv_bfloat16* __restrict__ Klo,
    const __nv_bfloat16* __restrict__ Vhi, const __nv_bfloat16* __restrict__ Vlo,
    __nv_bfloat16* __restrict__ Ohi, __nv_bfloat16* __restrict__ Olo)
{
    extern __shared__ __nv_bfloat16 smb16[];
    const uint32_t smb = smem_u32(smb16);

    const int qt = blockIdx.x;
    const int bh = blockIdx.y;
    const int b  = bh >> 4;
    const int h  = bh & 15;
    const int tid = threadIdx.x;
    const int lane = tid & 31, wid = tid >> 5;
    const int g2 = lane >> 2, t2 = lane & 3;

    const size_t rowbase = (size_t)(b * SEQ + qt * 128);
    const int hoff = h * 64;

    // ---- load Q tile (hi & lo) into smem ----
    #pragma unroll
    for (int it = 0; it < 8; it++) {
        int idx = tid + it * 128;          // 0..1023
        int row = idx >> 3, c8 = (idx & 7) * 8;
        const size_t gq = (rowbase + row) * EMB + hoff + c8;
        *reinterpret_cast<uint4*>(smb16 + AQ_HI + row * AP + c8) =
            *reinterpret_cast<const uint4*>(Qhi + gq);
        *reinterpret_cast<uint4*>(smb16 + AQ_LO + row * AP + c8) =
            *reinterpret_cast<const uint4*>(Qlo + gq);
    }

    // ---- K/V tile loader (cp.async) ----
    auto issue_kv = [&](int jt) {
        const uint32_t st = smb + (AST0 + (jt & 1) * ASTAGE) * 2;
        const size_t kb = (size_t)(b * SEQ + jt * 64);
        #pragma unroll
        for (int it = 0; it < 4; it++) {
            int idx = tid + it * 128;      // 0..511
            int row = idx >> 3, c8 = (idx & 7) * 8;
            const size_t g = (kb + row) * EMB + hoff + c8;
            const uint32_t so = (uint32_t)((row * AP + c8) * 2);
            cp16(st + so,            Khi + g);
            cp16(st + AMAT * 2 + so, Klo + g);
            cp16(st + AMAT * 4 + so, Vhi + g);
            cp16(st + AMAT * 6 + so, Vlo + g);
        }
        cp_commit();
    };

    // per-thread ldmatrix offsets
    const int rA = lane & 15, cA = lane >> 4;
    uint32_t qoff[2];
    #pragma unroll
    for (int i = 0; i < 2; i++)
        qoff[i] = (uint32_t)(((wid * 32 + i * 16 + rA) * AP + cA * 8) * 2);
    const int rB = (lane & 7) | ((lane >> 4) << 3), cB = (lane >> 3) & 1;
    uint32_t koff[4];
    #pragma unroll
    for (int j = 0; j < 4; j++)
        koff[j] = (uint32_t)(((j * 16 + rB) * AP + cB * 8) * 2);
    // V trans-ldmatrix: lane L<16 -> row L, col d0; L>=16 -> row L-16, col d0+8
    const uint32_t voff_row = (uint32_t)(rA * AP + cA * 8) * 2;

    float oacc[2][8][4];
    float mstat[4], lstat[4];
    #pragma unroll
    for (int i = 0; i < 2; i++)
        #pragma unroll
        for (int j = 0; j < 8; j++)
            #pragma unroll
            for (int q = 0; q < 4; q++) oacc[i][j][q] = 0.f;
    #pragma unroll
    for (int t = 0; t < 4; t++) { mstat[t] = -1e30f; lstat[t] = 0.f; }

    const int NT = 2 * qt + 2;
    issue_kv(0);

    for (int jt = 0; jt < NT; jt++) {
        if (jt + 1 < NT) { issue_kv(jt + 1); cp_wait1(); }
        else cp_wait0();
        __syncthreads();

        const uint32_t st = smb + (AST0 + (jt & 1) * ASTAGE) * 2;

        // ---- S = Q K^T (bf16x3) ----
        float sacc[2][8][4];
        #pragma unroll
        for (int i = 0; i < 2; i++)
            #pragma unroll
            for (int j = 0; j < 8; j++)
                #pragma unroll
                for (int q = 0; q < 4; q++) sacc[i][j][q] = 0.f;

        #pragma unroll
        for (int ks = 0; ks < 4; ks++) {
            const uint32_t kadd = ks * 32;
            uint32_t qh[2][4], ql[2][4], kh[4][4], kl[4][4];
            #pragma unroll
            for (int i = 0; i < 2; i++) {
                ldm_x4(qh[i], smb + AQ_HI * 2 + qoff[i] + kadd);
                ldm_x4(ql[i], smb + AQ_LO * 2 + qoff[i] + kadd);
            }
            #pragma unroll
            for (int j = 0; j < 4; j++) {
                ldm_x4(kh[j], st + koff[j] + kadd);
                ldm_x4(kl[j], st + AMAT * 2 + koff[j] + kadd);
            }
            #pragma unroll
            for (int i = 0; i < 2; i++)
                #pragma unroll
                for (int j = 0; j < 8; j++) {
                    const int j4 = j >> 1, hh = (j & 1) * 2;
                    mma16816(sacc[i][j], qh[i], &kh[j4][hh]);
                    mma16816(sacc[i][j], qh[i], &kl[j4][hh]);
                    mma16816(sacc[i][j], ql[i], &kh[j4][hh]);
                }
        }

        // ---- scale + causal mask ----
        const bool need_mask = (jt * 64 + 63) > (qt * 128);
        #pragma unroll
        for (int i = 0; i < 2; i++) {
            #pragma unroll
            for (int j = 0; j < 8; j++) {
                #pragma unroll
                for (int q = 0; q < 4; q++) {
                    float s = sacc[i][j][q] * 0.125f;
                    if (need_mask) {
                        const int row = qt * 128 + wid * 32 + i * 16 + g2 + (q >> 1) * 8;
                        const int col = jt * 64 + j * 8 + t2 * 2 + (q & 1);
                        if (col > row) s = -1e30f;
                    }
                    sacc[i][j][q] = s;
                }
            }
        }

        // ---- online softmax (4 tracked rows per thread) ----
        float alpha[4];
        #pragma unroll
        for (int i = 0; i < 2; i++) {
            #pragma unroll
            for (int half = 0; half < 2; half++) {
                const int t = i * 2 + half;
                float mx = -1e30f;
                #pragma unroll
                for (int j = 0; j < 8; j++)
                    mx = fmaxf(mx, fmaxf(sacc[i][j][half * 2], sacc[i][j][half * 2 + 1]));
                mx = fmaxf(mx, __shfl_xor_sync(0xffffffffu, mx, 1));
                mx = fmaxf(mx, __shfl_xor_sync(0xffffffffu, mx, 2));
                const float mnew = fmaxf(mstat[t], mx);
                alpha[t] = exp2f((mstat[t] - mnew) * 1.4426950408889634f);
                mstat[t] = mnew;
                float rs = 0.f;
                #pragma unroll
                for (int j = 0; j < 8; j++) {
                    float p0 = exp2f((sacc[i][j][half * 2]     - mnew) * 1.4426950408889634f);
                    float p1 = exp2f((sacc[i][j][half * 2 + 1] - mnew) * 1.4426950408889634f);
                    sacc[i][j][half * 2] = p0;
                    sacc[i][j][half * 2 + 1] = p1;
                    rs += p0 + p1;
                }
                rs += __shfl_xor_sync(0xffffffffu, rs, 1);
                rs += __shfl_xor_sync(0xffffffffu, rs, 2);
                lstat[t] = lstat[t] * alpha[t] + rs;
                #pragma unroll
                for (int j = 0; j < 8; j++) {
                    oacc[i][j][half * 2]     *= alpha[t];
                    oacc[i][j][half * 2 + 1] *= alpha[t];
                }
            }
        }

        // ---- O += P V (bf16x3, P from registers) ----
        #pragma unroll
        for (int kk = 0; kk < 4; kk++) {
            // build P A-fragments
            uint32_t ph[2][4], pl[2][4];
            #pragma unroll
            for (int i = 0; i < 2; i++) {
                const int j0 = 2 * kk, j1 = j0 + 1;
                const float c0 = sacc[i][j0][0], c1 = sacc[i][j0][1];
                const float c2 = sacc[i][j0][2], c3 = sacc[i][j0][3];
                const float d0 = sacc[i][j1][0], d1 = sacc[i][j1][1];
                const float d2 = sacc[i][j1][2], d3 = sacc[i][j1][3];
                ph[i][0] = pack_bf16(c0, c1);
                ph[i][1] = pack_bf16(c2, c3);
                ph[i][2] = pack_bf16(d0, d1);
                ph[i][3] = pack_bf16(d2, d3);
                const float h0 = __bfloat162float(__float2bfloat16_rn(c0));
                const float h1 = __bfloat162float(__float2bfloat16_rn(c1));
                const float h2 = __bfloat162float(__float2bfloat16_rn(c2));
                const float h3 = __bfloat162float(__float2bfloat16_rn(c3));
                const float e0 = __bfloat162float(__float2bfloat16_rn(d0));
                const float e1 = __bfloat162float(__float2bfloat16_rn(d1));
                const float e2 = __bfloat162float(__float2bfloat16_rn(d2));
                const float e3 = __bfloat162float(__float2bfloat16_rn(d3));
                pl[i][0] = pack_bf16(c0 - h0, c1 - h1);
                pl[i][1] = pack_bf16(c2 - h2, c3 - h3);
                pl[i][2] = pack_bf16(d0 - e0, d1 - e1);
                pl[i][3] = pack_bf16(d2 - e2, d3 - e3);
            }
            // V fragments (trans ldmatrix): 4 loads cover d-frags pairs
            uint32_t vh[4][4], vl[4][4];
            const uint32_t vrow = (uint32_t)((kk * 16) * AP * 2);
            #pragma unroll
            for (int dgrp = 0; dgrp < 4; dgrp++) {
                const uint32_t va = st + AMAT * 4 + vrow + voff_row + (uint32_t)(dgrp * 16 * 2);
                ldm_x4t(vh[dgrp], va);
                ldm_x4t(vl[dgrp], va + AMAT * 2);
            }
            #pragma unroll
            for (int i = 0; i < 2; i++)
                #pragma unroll
                for (int jd = 0; jd < 8; jd++) {
                    const int vg = jd >> 1, sel = (jd & 1) * 2;
                    mma16816(oacc[i][jd], ph[i], &vh[vg][sel]);
                    mma16816(oacc[i][jd], ph[i], &vl[vg][sel]);
                    mma16816(oacc[i][jd], pl[i], &vh[vg][sel]);
                }
        }
        __syncthreads();
    }

    // ---- normalize + split-write O ----
    #pragma unroll
    for (int i = 0; i < 2; i++) {
        #pragma unroll
        for (int half = 0; half < 2; half++) {
            const int t = i * 2 + half;
            const float inv = 1.f / lstat[t];
            const size_t row = rowbase + wid * 32 + i * 16 + g2 + half * 8;
            #pragma unroll
            for (int jd = 0; jd < 8; jd++) {
                const int col = hoff + jd * 8 + t2 * 2;
                const float vx = oacc[i][jd][half * 2]     * inv;
                const float vy = oacc[i][jd][half * 2 + 1] * inv;
                const float hx = __bfloat162float(__float2bfloat16_rn(vx));
                const float hy = __bfloat162float(__float2bfloat16_rn(vy));
                *reinterpret_cast<uint32_t*>(Ohi + row * EMB + col) = pack_bf16(vx, vy);
                *reinterpret_cast<uint32_t*>(Olo + row * EMB + col) = pack_bf16(vx - hx, vy - hy);
            }
        }
    }
}

// ---------------- host orchestration ----------------
extern "C" void kernel_launch(void* const* d_in, const int* in_sizes, int n_in,
                              void* d_out, int out_size)
{
    const int*   idx  = (const int*)  d_in[0];
    const float* tok  = (const float*)d_in[1];
    const float* pos  = (const float*)d_in[2];
    const float* Wq   = (const float*)d_in[3];
    const float* Wk   = (const float*)d_in[4];
    const float* Wv   = (const float*)d_in[5];
    const float* Wo   = (const float*)d_in[6];
    const float* bo   = (const float*)d_in[7];
    const float* W1   = (const float*)d_in[8];
    const float* b1   = (const float*)d_in[9];
    const float* W2   = (const float*)d_in[10];
    const float* b2   = (const float*)d_in[11];
    const float* ln1g = (const float*)d_in[12];
    const float* ln1b = (const float*)d_in[13];
    const float* ln2g = (const float*)d_in[14];
    const float* ln2b = (const float*)d_in[15];
    const float* lnfg = (const float*)d_in[16];
    const float* lnfb = (const float*)d_in[17];
    const float* lmb  = (const float*)d_in[18];
    float* out = (float*)d_out;

    float* x;
    __nv_bfloat16 *whi, *wlo, *tokhi, *toklo;
    __nv_bfloat16 *ahi, *alo, *qhi, *qlo, *khi, *klo, *vhi, *vlo, *ohi, *olo, *fhi, *flo;
    cudaGetSymbolAddress((void**)&x,  g_x);
    cudaGetSymbolAddress((void**)&whi, g_Whi);
    cudaGetSymbolAddress((void**)&wlo, g_Wlo);
    cudaGetSymbolAddress((void**)&tokhi, g_tokhi);
    cudaGetSymbolAddress((void**)&toklo, g_toklo);
    cudaGetSymbolAddress((void**)&ahi, g_ahi);
    cudaGetSymbolAddress((void**)&alo, g_alo);
    cudaGetSymbolAddress((void**)&qhi, g_qhi);
    cudaGetSymbolAddress((void**)&qlo, g_qlo);
    cudaGetSymbolAddress((void**)&khi, g_khi);
    cudaGetSymbolAddress((void**)&klo, g_klo);
    cudaGetSymbolAddress((void**)&vhi, g_vhi);
    cudaGetSymbolAddress((void**)&vlo, g_vlo);
    cudaGetSymbolAddress((void**)&ohi, g_ohi);
    cudaGetSymbolAddress((void**)&olo, g_olo);
    cudaGetSymbolAddress((void**)&fhi, g_fhi);
    cudaGetSymbolAddress((void**)&flo, g_flo);

    cudaFuncSetAttribute(attn_tc_kernel, cudaFuncAttributeMaxDynamicSharedMemorySize, ATTN_SMEM);
    cudaFuncSetAttribute(mma_gemm<false,false,false,true>, cudaFuncAttributeMaxDynamicSharedMemorySize, GEMM_SMEM);
    cudaFuncSetAttribute(mma_gemm<true,false,true,false>,  cudaFuncAttributeMaxDynamicSharedMemorySize, GEMM_SMEM);
    cudaFuncSetAttribute(mma_gemm<true,true,false,true>,   cudaFuncAttributeMaxDynamicSharedMemorySize, GEMM_SMEM);
    cudaFuncSetAttribute(mma_gemm<true,false,false,false>, cudaFuncAttributeMaxDynamicSharedMemorySize, GEMM_SMEM);

    const dim3 tb(32, 8);

    // ---- weight conversion ----
    for (int l = 0; l < LAY; l++) {
        const size_t wb = (size_t)l * WPL;
        const size_t we = (size_t)l * EMB * EMB;
        tsplit_kernel<<<dim3(EMB / 32, EMB / 32), tb>>>(Wq + we, whi + wb + OFF_WQ, wlo + wb + OFF_WQ, EMB, EMB);
        tsplit_kernel<<<dim3(EMB / 32, EMB / 32), tb>>>(Wk + we, whi + wb + OFF_WK, wlo + wb + OFF_WK, EMB, EMB);
        tsplit_kernel<<<dim3(EMB / 32, EMB / 32), tb>>>(Wv + we, whi + wb + OFF_WV, wlo + wb + OFF_WV, EMB, EMB);
        tsplit_kernel<<<dim3(EMB / 32, EMB / 32), tb>>>(Wo + we, whi + wb + OFF_WO, wlo + wb + OFF_WO, EMB, EMB);
        tsplit_kernel<<<dim3(DFF / 32, EMB / 32), tb>>>(W1 + (size_t)l * EMB * DFF, whi + wb + OFF_W1, wlo + wb + OFF_W1, EMB, DFF);
        tsplit_kernel<<<dim3(EMB / 32, DFF / 32), tb>>>(W2 + (size_t)l * DFF * EMB, whi + wb + OFF_W2, wlo + wb + OFF_W2, DFF, EMB);
    }
    {
        const int n4 = (int)(((size_t)VOC * EMB) / 4);
        split4_kernel<<<(n4 + 255) / 256, 256>>>(tok, tokhi, toklo, n4);
    }

    embed_kernel<<<(MROWS * EMB) / 256, 256>>>(x, idx, tok, pos);

    const dim3 g1024(MROWS / 128, EMB / 128);
    const dim3 g4096(MROWS / 128, DFF / 128);
    const dim3 gvoc (MROWS / 128, VOC / 128);
    const dim3 gattn(SEQ / 128, BSZ * NH);

    for (int l = 0; l < LAY; l++) {
        const size_t wb = (size_t)l * WPL;
        ln_split_kernel<<<MROWS, 256>>>(ahi, alo, x, ln1g + (size_t)l * EMB, ln1b + (size_t)l * EMB);
        mma_gemm<false,false,false,true><<<g1024, 256, GEMM_SMEM>>>(ahi, alo, whi + wb + OFF_WQ, wlo + wb + OFF_WQ, nullptr, nullptr, nullptr, qhi, qlo, MROWS, EMB, EMB);
        mma_gemm<false,false,false,true><<<g1024, 256, GEMM_SMEM>>>(ahi, alo, whi + wb + OFF_WK, wlo + wb + OFF_WK, nullptr, nullptr, nullptr, khi, klo, MROWS, EMB, EMB);
        mma_gemm<false,false,false,true><<<g1024, 256, GEMM_SMEM>>>(ahi, alo, whi + wb + OFF_WV, wlo + wb + OFF_WV, nullptr, nullptr, nullptr, vhi, vlo, MROWS, EMB, EMB);
        attn_tc_kernel<<<gattn, 128, ATTN_SMEM>>>(qhi, qlo, khi, klo, vhi, vlo, ohi, olo);
        mma_gemm<true,false,true,false><<<g1024, 256, GEMM_SMEM>>>(ohi, olo, whi + wb + OFF_WO, wlo + wb + OFF_WO, bo + (size_t)l * EMB, x, x, nullptr, nullptr, MROWS, EMB, EMB);
        ln_split_kernel<<<MROWS, 256>>>(ahi, alo, x, ln2g + (size_t)l * EMB, ln2b + (size_t)l * EMB);
        mma_gemm<true,true,false,true><<<g4096, 256, GEMM_SMEM>>>(ahi, alo, whi + wb + OFF_W1, wlo + wb + OFF_W1, b1 + (size_t)l * DFF, nullptr, nullptr, fhi, flo, MROWS, DFF, EMB);
        mma_gemm<true,false,true,false><<<g1024, 256, GEMM_SMEM>>>(fhi, flo, whi + wb + OFF_W2, wlo + wb + OFF_W2, b2 + (size_t)l * EMB, x, x, nullptr, nullptr, MROWS, EMB, DFF);
    }

    ln_split_kernel<<<MROWS, 256>>>(ahi, alo, x, lnfg, lnfb);
    mma_gemm<true,false,false,false><<<gvoc, 256, GEMM_SMEM>>>(ahi, alo, tokhi, toklo, lmb, nullptr, out, nullptr, nullptr, MROWS, VOC, EMB);
}

// round 7
// speedup vs baseline: 2.9922x; 1.0678x over previous
#include <cuda_runtime.h>
#include <cuda_bf16.h>
#include <cstdint>
#include <math.h>

// ---------------- problem constants ----------------
constexpr int LAY = 8;
constexpr int NH  = 16;
constexpr int EMB = 1024;
constexpr int VOC = 32000;
constexpr int SEQ = 1024;
constexpr int BSZ = 2;
constexpr int DFF = 4096;
constexpr int MROWS = BSZ * SEQ;   // 2048
constexpr int QKV = 3 * EMB;       // 3072

// ---------------- scratch (device globals; no cudaMalloc allowed) ----------------
__device__ float g_x [MROWS * EMB];

constexpr size_t WPL = 4ull * EMB * EMB + 2ull * EMB * DFF;
__device__ __align__(16) __nv_bfloat16 g_Whi[LAY * WPL];
__device__ __align__(16) __nv_bfloat16 g_Wlo[LAY * WPL];
__device__ __align__(16) __nv_bfloat16 g_tokhi[(size_t)VOC * EMB];
__device__ __align__(16) __nv_bfloat16 g_toklo[(size_t)VOC * EMB];

__device__ __align__(16) __nv_bfloat16 g_ahi[MROWS * EMB];
__device__ __align__(16) __nv_bfloat16 g_alo[MROWS * EMB];
__device__ __align__(16) __nv_bfloat16 g_qkvh[MROWS * QKV];
__device__ __align__(16) __nv_bfloat16 g_qkvl[MROWS * QKV];
__device__ __align__(16) __nv_bfloat16 g_ohi[MROWS * EMB];
__device__ __align__(16) __nv_bfloat16 g_olo[MROWS * EMB];
__device__ __align__(16) __nv_bfloat16 g_fhi[MROWS * DFF];
__device__ __align__(16) __nv_bfloat16 g_flo[MROWS * DFF];

// per-layer weight offsets inside WPL block (transposed to [N,K]); WQ/WK/WV contiguous => fused [3072,1024]
constexpr size_t OFF_WQ = 0;
constexpr size_t OFF_WO = 3ull << 20;
constexpr size_t OFF_W1 = 4ull << 20;
constexpr size_t OFF_W2 = 8ull << 20;

// ---------------- low-level helpers ----------------
__device__ __forceinline__ uint32_t smem_u32(const void* p) {
    uint32_t a;
    asm("{ .reg .u64 t; cvta.to.shared.u64 t, %1; cvt.u32.u64 %0, t; }" : "=r"(a) : "l"(p));
    return a;
}
__device__ __forceinline__ void cp16(uint32_t s, const void* g) {
    asm volatile("cp.async.cg.shared.global [%0], [%1], 16;" :: "r"(s), "l"(g) : "memory");
}
__device__ __forceinline__ void cp_commit() {
    asm volatile("cp.async.commit_group;" ::: "memory");
}
__device__ __forceinline__ void cp_wait1() {
    asm volatile("cp.async.wait_group 1;" ::: "memory");
}
__device__ __forceinline__ void cp_wait0() {
    asm volatile("cp.async.wait_group 0;" ::: "memory");
}
__device__ __forceinline__ void ldm_x4(uint32_t* r, uint32_t a) {
    asm volatile("ldmatrix.sync.aligned.m8n8.x4.shared.b16 {%0,%1,%2,%3}, [%4];"
                 : "=r"(r[0]), "=r"(r[1]), "=r"(r[2]), "=r"(r[3]) : "r"(a));
}
__device__ __forceinline__ void ldm_x4t(uint32_t* r, uint32_t a) {
    asm volatile("ldmatrix.sync.aligned.m8n8.x4.trans.shared.b16 {%0,%1,%2,%3}, [%4];"
                 : "=r"(r[0]), "=r"(r[1]), "=r"(r[2]), "=r"(r[3]) : "r"(a));
}
__device__ __forceinline__ void mma16816(float* d, const uint32_t* a, const uint32_t* b) {
    asm volatile(
        "mma.sync.aligned.m16n8k16.row.col.f32.bf16.bf16.f32 "
        "{%0,%1,%2,%3}, {%4,%5,%6,%7}, {%8,%9}, {%0,%1,%2,%3};"
        : "+f"(d[0]), "+f"(d[1]), "+f"(d[2]), "+f"(d[3])
        : "r"(a[0]), "r"(a[1]), "r"(a[2]), "r"(a[3]), "r"(b[0]), "r"(b[1]));
}
__device__ __forceinline__ uint32_t pack_bf16(float x, float y) {
    __nv_bfloat162 t = __floats2bfloat162_rn(x, y);
    return *reinterpret_cast<uint32_t*>(&t);
}

// ---------------- conversion kernels ----------------
__global__ void split4_kernel(const float* __restrict__ in,
                              __nv_bfloat16* __restrict__ hi, __nv_bfloat16* __restrict__ lo,
                              int n4)
{
    int i = blockIdx.x * blockDim.x + threadIdx.x;
    if (i >= n4) return;
    float4 v = reinterpret_cast<const float4*>(in)[i];
    float hx = __bfloat162float(__float2bfloat16_rn(v.x));
    float hy = __bfloat162float(__float2bfloat16_rn(v.y));
    float hz = __bfloat162float(__float2bfloat16_rn(v.z));
    float hw = __bfloat162float(__float2bfloat16_rn(v.w));
    uint32_t* hp = reinterpret_cast<uint32_t*>(hi) + i * 2;
    uint32_t* lp = reinterpret_cast<uint32_t*>(lo) + i * 2;
    hp[0] = pack_bf16(v.x, v.y);
    hp[1] = pack_bf16(v.z, v.w);
    lp[0] = pack_bf16(v.x - hx, v.y - hy);
    lp[1] = pack_bf16(v.z - hz, v.w - hw);
}

__global__ void tsplit_kernel(const float* __restrict__ in,
                              __nv_bfloat16* __restrict__ hi, __nv_bfloat16* __restrict__ lo,
                              int K, int N)
{
    __shared__ float t[32][33];
    const int n0 = blockIdx.x * 32, k0 = blockIdx.y * 32;
    const int tx = threadIdx.x, ty = threadIdx.y;   // 32 x 8
    #pragma unroll
    for (int j = 0; j < 4; j++)
        t[ty + j * 8][tx] = in[(size_t)(k0 + ty + j * 8) * N + n0 + tx];
    __syncthreads();
    #pragma unroll
    for (int j = 0; j < 4; j++) {
        float x = t[tx][ty + j * 8];
        size_t o = (size_t)(n0 + ty + j * 8) * K + k0 + tx;
        __nv_bfloat16 h = __float2bfloat16(x);
        hi[o] = h;
        lo[o] = __float2bfloat16(x - __bfloat162float(h));
    }
}

// ---------------- embedding ----------------
__global__ void embed_kernel(float* __restrict__ x, const int* __restrict__ idx,
                             const float* __restrict__ tok, const float* __restrict__ pos)
{
    int i = blockIdx.x * blockDim.x + threadIdx.x;
    int e  = i & (EMB - 1);
    int bt = i >> 10;
    int t  = bt & (SEQ - 1);
    x[i] = tok[(size_t)idx[bt] * EMB + e] + pos[(size_t)t * EMB + e];
}

// ---------------- layernorm with fused bf16 split output ----------------
__global__ __launch_bounds__(256) void ln_split_kernel(
    __nv_bfloat16* __restrict__ ohi, __nv_bfloat16* __restrict__ olo,
    const float* __restrict__ in,
    const float* __restrict__ g, const float* __restrict__ b)
{
    const int row = blockIdx.x;
    const int c0 = threadIdx.x * 4;
    const float4 v = *reinterpret_cast<const float4*>(in + (size_t)row * EMB + c0);

    float s = v.x + v.y + v.z + v.w;
    __shared__ float red[8];
    __shared__ float mean_s, rstd_s;

    #pragma unroll
    for (int o = 16; o; o >>= 1) s += __shfl_xor_sync(0xffffffffu, s, o);
    if ((threadIdx.x & 31) == 0) red[threadIdx.x >> 5] = s;
    __syncthreads();
    if (threadIdx.x == 0) {
        float t = 0.f;
        #pragma unroll
        for (int i = 0; i < 8; i++) t += red[i];
        mean_s = t * (1.f / EMB);
    }
    __syncthreads();
    const float m = mean_s;

    float dx = v.x - m, dy = v.y - m, dz = v.z - m, dw = v.w - m;
    float ss = dx * dx + dy * dy + dz * dz + dw * dw;
    #pragma unroll
    for (int o = 16; o; o >>= 1) ss += __shfl_xor_sync(0xffffffffu, ss, o);
    if ((threadIdx.x & 31) == 0) red[threadIdx.x >> 5] = ss;
    __syncthreads();
    if (threadIdx.x == 0) {
        float t = 0.f;
        #pragma unroll
        for (int i = 0; i < 8; i++) t += red[i];
        rstd_s = rsqrtf(t * (1.f / EMB) + 1e-5f);
    }
    __syncthreads();
    const float r = rstd_s;

    const float4 g4 = *reinterpret_cast<const float4*>(g + c0);
    const float4 b4 = *reinterpret_cast<const float4*>(b + c0);
    float ox = dx * r * g4.x + b4.x;
    float oy = dy * r * g4.y + b4.y;
    float oz = dz * r * g4.z + b4.z;
    float ow = dw * r * g4.w + b4.w;

    float hx = __bfloat162float(__float2bfloat16_rn(ox));
    float hy = __bfloat162float(__float2bfloat16_rn(oy));
    float hz = __bfloat162float(__float2bfloat16_rn(oz));
    float hw = __bfloat162float(__float2bfloat16_rn(ow));
    uint32_t* hp = reinterpret_cast<uint32_t*>(ohi + (size_t)row * EMB + c0);
    uint32_t* lp = reinterpret_cast<uint32_t*>(olo + (size_t)row * EMB + c0);
    hp[0] = pack_bf16(ox, oy);
    hp[1] = pack_bf16(oz, ow);
    lp[0] = pack_bf16(ox - hx, oy - hy);
    lp[1] = pack_bf16(oz - hz, ow - hw);
}

// ---------------- bf16x3 GEMM on mma.sync, persistent tiles, BK=64, 3-stage ----------------
constexpr int PITCH = 72;                        // bf16 elems; 144B rows, conflict-free ldmatrix
constexpr int MAT_BYTES = 128 * PITCH * 2;       // 18432
constexpr int STAGE_BYTES = 4 * MAT_BYTES;       // 73728
constexpr int GSTAGES = 3;
constexpr int GEMM_SMEM = GSTAGES * STAGE_BYTES; // 221184

template<bool BIAS, bool RELU, bool RES, bool SPLIT>
__global__ __launch_bounds__(256) void mma_gemm(
    const __nv_bfloat16* __restrict__ Ahi, const __nv_bfloat16* __restrict__ Alo,
    const __nv_bfloat16* __restrict__ Bhi, const __nv_bfloat16* __restrict__ Blo,
    const float* __restrict__ bias, const float* __restrict__ res,
    float* __restrict__ C,
    __nv_bfloat16* __restrict__ Chi, __nv_bfloat16* __restrict__ Clo,
    int N, int K, int ntn, int ntiles)
{
    extern __shared__ char sm[];
    const int tid  = threadIdx.x;
    const int lane = tid & 31, wid = tid >> 5;
    const int wm = wid >> 1, wn = wid & 1;
    const uint32_t smb = smem_u32(sm);
    const int NC = K >> 6;

    // ldmatrix per-thread offsets (within a stage)
    const int rA = lane & 15, cA = lane >> 4;
    uint32_t offA[2];
    #pragma unroll
    for (int i = 0; i < 2; i++)
        offA[i] = (uint32_t)(((wm * 32 + i * 16 + rA) * PITCH + cA * 8) * 2);
    const int rB = (lane & 7) | ((lane >> 4) << 3), cB = (lane >> 3) & 1;
    uint32_t offB[4];
    #pragma unroll
    for (int j = 0; j < 4; j++)
        offB[j] = (uint32_t)(((wn * 64 + j * 16 + rB) * PITCH + cB * 8) * 2);

    const int g2 = lane >> 2, t2 = lane & 3;

    for (int t = blockIdx.x; t < ntiles; t += gridDim.x) {
        const int bm0 = (t / ntn) * 128;
        const int bn0 = (t % ntn) * 128;

        float acc[2][8][4];
        #pragma unroll
        for (int i = 0; i < 2; i++)
            #pragma unroll
            for (int j = 0; j < 8; j++)
                #pragma unroll
                for (int q = 0; q < 4; q++) acc[i][j][q] = 0.f;

        // loader: 4 segments per matrix per thread (128 rows x 8 segs of 16B)
        auto issue = [&](int c) {
            const int k0 = c << 6;
            const uint32_t st = smb + (c % GSTAGES) * STAGE_BYTES;
            #pragma unroll
            for (int it = 0; it < 4; it++) {
                const int idx = tid + it * 256;
                const int row = idx >> 3, seg = idx & 7;
                const uint32_t so = (uint32_t)(row * PITCH * 2 + seg * 16);
                const size_t ga = (size_t)(bm0 + row) * K + k0 + seg * 8;
                const size_t gb = (size_t)(bn0 + row) * K + k0 + seg * 8;
                cp16(st + so,                 Ahi + ga);
                cp16(st + MAT_BYTES + so,     Alo + ga);
                cp16(st + 2 * MAT_BYTES + so, Bhi + gb);
                cp16(st + 3 * MAT_BYTES + so, Blo + gb);
            }
            cp_commit();
        };

        issue(0);
        if (NC > 1) issue(1);

        for (int c = 0; c < NC; c++) {
            if (c + 2 < NC) cp_wait1(); else cp_wait0();
            __syncthreads();
            if (c + 2 < NC) issue(c + 2);

            const uint32_t st = smb + (c % GSTAGES) * STAGE_BYTES;
            #pragma unroll
            for (int ks = 0; ks < 4; ks++) {
                const uint32_t kadd = ks * 32;
                uint32_t ah[2][4], al[2][4], bh[4][4], bl[4][4];
                #pragma unroll
                for (int i = 0; i < 2; i++) {
                    ldm_x4(ah[i], st + offA[i] + kadd);
                    ldm_x4(al[i], st + MAT_BYTES + offA[i] + kadd);
                }
                #pragma unroll
                for (int j = 0; j < 4; j++) {
                    ldm_x4(bh[j], st + 2 * MAT_BYTES + offB[j] + kadd);
                    ldm_x4(bl[j], st + 3 * MAT_BYTES + offB[j] + kadd);
                }
                #pragma unroll
                for (int i = 0; i < 2; i++)
                    #pragma unroll
                    for (int j = 0; j < 8; j++) {
                        const int j4 = j >> 1, hh = (j & 1) * 2;
                        mma16816(acc[i][j], ah[i], &bh[j4][hh]);
                        mma16816(acc[i][j], ah[i], &bl[j4][hh]);
                        mma16816(acc[i][j], al[i], &bh[j4][hh]);
                    }
            }
        }

        // epilogue (registers -> global)
        #pragma unroll
        for (int i = 0; i < 2; i++) {
            #pragma unroll
            for (int j = 0; j < 8; j++) {
                const int row0 = bm0 + wm * 32 + i * 16 + g2;
                const int col  = bn0 + wn * 64 + j * 8 + t2 * 2;
                #pragma unroll
                for (int half = 0; half < 2; half++) {
                    const int row = row0 + half * 8;
                    float vx = acc[i][j][half * 2 + 0];
                    float vy = acc[i][j][half * 2 + 1];
                    if (BIAS) { vx += bias[col]; vy += bias[col + 1]; }
                    if (RES) {
                        const float2 rr = *reinterpret_cast<const float2*>(res + (size_t)row * N + col);
                        vx += rr.x; vy += rr.y;
                    }
                    if (RELU) { vx = fmaxf(vx, 0.f); vy = fmaxf(vy, 0.f); }
                    if (SPLIT) {
                        float hx = __bfloat162float(__float2bfloat16_rn(vx));
                        float hy = __bfloat162float(__float2bfloat16_rn(vy));
                        *reinterpret_cast<uint32_t*>(Chi + (size_t)row * N + col) = pack_bf16(vx, vy);
                        *reinterpret_cast<uint32_t*>(Clo + (size_t)row * N + col) = pack_bf16(vx - hx, vy - hy);
                    } else {
                        float2 v; v.x = vx; v.y = vy;
                        *reinterpret_cast<float2*>(C + (size_t)row * N + col) = v;
                    }
                }
            }
        }
        __syncthreads();   // protect smem before next tile's prologue
    }
}

// ---------------- tensor-core flash attention (bf16x3, causal), packed QKV ----------------
constexpr int AP = 72;
constexpr int AQ_HI = 0;
constexpr int AQ_LO = 128 * AP;
constexpr int AST0  = 2 * 128 * AP;
constexpr int AMAT  = 64 * AP;
constexpr int ASTAGE = 4 * AMAT;
constexpr int ATTN_SMEM = (AST0 + 2 * ASTAGE) * 2;   // 110,592 bytes

__global__ __launch_bounds__(128) void attn_tc_kernel(
    const __nv_bfloat16* __restrict__ QKVh, const __nv_bfloat16* __restrict__ QKVl,
    __nv_bfloat16* __restrict__ Ohi, __nv_bfloat16* __restrict__ Olo)
{
    extern __shared__ __nv_bfloat16 smb16[];
    const uint32_t smb = smem_u32(smb16);

    const int qt = blockIdx.x;
    const int bh = blockIdx.y;
    const int b  = bh >> 4;
    const int h  = bh & 15;
    const int tid = threadIdx.x;
    const int lane = tid & 31, wid = tid >> 5;
    const int g2 = lane >> 2, t2 = lane & 3;

    const size_t rowbase = (size_t)(b * SEQ + qt * 128);
    const int hoff = h * 64;

    // ---- load Q tile (hi & lo) into smem ----
    #pragma unroll
    for (int it = 0; it < 8; it++) {
        int idx = tid + it * 128;
        int row = idx >> 3, c8 = (idx & 7) * 8;
        const size_t gq = (rowbase + row) * QKV + hoff + c8;
        *reinterpret_cast<uint4*>(smb16 + AQ_HI + row * AP + c8) =
            *reinterpret_cast<const uint4*>(QKVh + gq);
        *reinterpret_cast<uint4*>(smb16 + AQ_LO + row * AP + c8) =
            *reinterpret_cast<const uint4*>(QKVl + gq);
    }

    auto issue_kv = [&](int jt) {
        const uint32_t st = smb + (AST0 + (jt & 1) * ASTAGE) * 2;
        const size_t kb = (size_t)(b * SEQ + jt * 64);
        #pragma unroll
        for (int it = 0; it < 4; it++) {
            int idx = tid + it * 128;
            int row = idx >> 3, c8 = (idx & 7) * 8;
            const size_t g = (kb + row) * QKV + hoff + c8;
            const uint32_t so = (uint32_t)((row * AP + c8) * 2);
            cp16(st + so,            QKVh + g + EMB);        // K hi
            cp16(st + AMAT * 2 + so, QKVl + g + EMB);        // K lo
            cp16(st + AMAT * 4 + so, QKVh + g + 2 * EMB);    // V hi
            cp16(st + AMAT * 6 + so, QKVl + g + 2 * EMB);    // V lo
        }
        cp_commit();
    };

    const int rA = lane & 15, cA = lane >> 4;
    uint32_t qoff[2];
    #pragma unroll
    for (int i = 0; i < 2; i++)
        qoff[i] = (uint32_t)(((wid * 32 + i * 16 + rA) * AP + cA * 8) * 2);
    const int rB = (lane & 7) | ((lane >> 4) << 3), cB = (lane >> 3) & 1;
    uint32_t koff[4];
    #pragma unroll
    for (int j = 0; j < 4; j++)
        koff[j] = (uint32_t)(((j * 16 + rB) * AP + cB * 8) * 2);
    const uint32_t voff_row = (uint32_t)(rA * AP + cA * 8) * 2;

    float oacc[2][8][4];
    float mstat[4], lstat[4];
    #pragma unroll
    for (int i = 0; i < 2; i++)
        #pragma unroll
        for (int j = 0; j < 8; j++)
            #pragma unroll
            for (int q = 0; q < 4; q++) oacc[i][j][q] = 0.f;
    #pragma unroll
    for (int t = 0; t < 4; t++) { mstat[t] = -1e30f; lstat[t] = 0.f; }

    const int NT = 2 * qt + 2;
    issue_kv(0);

    for (int jt = 0; jt < NT; jt++) {
        if (jt + 1 < NT) { issue_kv(jt + 1); cp_wait1(); }
        else cp_wait0();
        __syncthreads();

        const uint32_t st = smb + (AST0 + (jt & 1) * ASTAGE) * 2;

        float sacc[2][8][4];
        #pragma unroll
        for (int i = 0; i < 2; i++)
            #pragma unroll
            for (int j = 0; j < 8; j++)
                #pragma unroll
                for (int q = 0; q < 4; q++) sacc[i][j][q] = 0.f;

        #pragma unroll
        for (int ks = 0; ks < 4; ks++) {
            const uint32_t kadd = ks * 32;
            uint32_t qh[2][4], ql[2][4], kh[4][4], kl[4][4];
            #pragma unroll
            for (int i = 0; i < 2; i++) {
                ldm_x4(qh[i], smb + AQ_HI * 2 + qoff[i] + kadd);
                ldm_x4(ql[i], smb + AQ_LO * 2 + qoff[i] + kadd);
            }
            #pragma unroll
            for (int j = 0; j < 4; j++) {
                ldm_x4(kh[j], st + koff[j] + kadd);
                ldm_x4(kl[j], st + AMAT * 2 + koff[j] + kadd);
            }
            #pragma unroll
            for (int i = 0; i < 2; i++)
                #pragma unroll
                for (int j = 0; j < 8; j++) {
                    const int j4 = j >> 1, hh = (j & 1) * 2;
                    mma16816(sacc[i][j], qh[i], &kh[j4][hh]);
                    mma16816(sacc[i][j], qh[i], &kl[j4][hh]);
                    mma16816(sacc[i][j], ql[i], &kh[j4][hh]);
                }
        }

        const bool need_mask = (jt * 64 + 63) > (qt * 128);
        #pragma unroll
        for (int i = 0; i < 2; i++) {
            #pragma unroll
            for (int j = 0; j < 8; j++) {
                #pragma unroll
                for (int q = 0; q < 4; q++) {
                    float s = sacc[i][j][q] * 0.125f;
                    if (need_mask) {
                        const int row = qt * 128 + wid * 32 + i * 16 + g2 + (q >> 1) * 8;
                        const int col = jt * 64 + j * 8 + t2 * 2 + (q & 1);
                        if (col > row) s = -1e30f;
                    }
                    sacc[i][j][q] = s;
                }
            }
        }

        float alpha[4];
        #pragma unroll
        for (int i = 0; i < 2; i++) {
            #pragma unroll
            for (int half = 0; half < 2; half++) {
                const int t = i * 2 + half;
                float mx = -1e30f;
                #pragma unroll
                for (int j = 0; j < 8; j++)
                    mx = fmaxf(mx, fmaxf(sacc[i][j][half * 2], sacc[i][j][half * 2 + 1]));
                mx = fmaxf(mx, __shfl_xor_sync(0xffffffffu, mx, 1));
                mx = fmaxf(mx, __shfl_xor_sync(0xffffffffu, mx, 2));
                const float mnew = fmaxf(mstat[t], mx);
                alpha[t] = exp2f((mstat[t] - mnew) * 1.4426950408889634f);
                mstat[t] = mnew;
                float rs = 0.f;
                #pragma unroll
                for (int j = 0; j < 8; j++) {
                    float p0 = exp2f((sacc[i][j][half * 2]     - mnew) * 1.4426950408889634f);
                    float p1 = exp2f((sacc[i][j][half * 2 + 1] - mnew) * 1.4426950408889634f);
                    sacc[i][j][half * 2] = p0;
                    sacc[i][j][half * 2 + 1] = p1;
                    rs += p0 + p1;
                }
                rs += __shfl_xor_sync(0xffffffffu, rs, 1);
                rs += __shfl_xor_sync(0xffffffffu, rs, 2);
                lstat[t] = lstat[t] * alpha[t] + rs;
                #pragma unroll
                for (int j = 0; j < 8; j++) {
                    oacc[i][j][half * 2]     *= alpha[t];
                    oacc[i][j][half * 2 + 1] *= alpha[t];
                }
            }
        }

        #pragma unroll
        for (int kk = 0; kk < 4; kk++) {
            uint32_t ph[2][4], pl[2][4];
            #pragma unroll
            for (int i = 0; i < 2; i++) {
                const int j0 = 2 * kk, j1 = j0 + 1;
                const float c0 = sacc[i][j0][0], c1 = sacc[i][j0][1];
                const float c2 = sacc[i][j0][2], c3 = sacc[i][j0][3];
                const float d0 = sacc[i][j1][0], d1 = sacc[i][j1][1];
                const float d2 = sacc[i][j1][2], d3 = sacc[i][j1][3];
                ph[i][0] = pack_bf16(c0, c1);
                ph[i][1] = pack_bf16(c2, c3);
                ph[i][2] = pack_bf16(d0, d1);
                ph[i][3] = pack_bf16(d2, d3);
                const float h0 = __bfloat162float(__float2bfloat16_rn(c0));
                const float h1 = __bfloat162float(__float2bfloat16_rn(c1));
                const float h2 = __bfloat162float(__float2bfloat16_rn(c2));
                const float h3 = __bfloat162float(__float2bfloat16_rn(c3));
                const float e0 = __bfloat162float(__float2bfloat16_rn(d0));
                const float e1 = __bfloat162float(__float2bfloat16_rn(d1));
                const float e2 = __bfloat162float(__float2bfloat16_rn(d2));
                const float e3 = __bfloat162float(__float2bfloat16_rn(d3));
                pl[i][0] = pack_bf16(c0 - h0, c1 - h1);
                pl[i][1] = pack_bf16(c2 - h2, c3 - h3);
                pl[i][2] = pack_bf16(d0 - e0, d1 - e1);
                pl[i][3] = pack_bf16(d2 - e2, d3 - e3);
            }
            uint32_t vh[4][4], vl[4][4];
            const uint32_t vrow = (uint32_t)((kk * 16) * AP * 2);
            #pragma unroll
            for (int dgrp = 0; dgrp < 4; dgrp++) {
                const uint32_t va = st + AMAT * 4 + vrow + voff_row + (uint32_t)(dgrp * 16 * 2);
                ldm_x4t(vh[dgrp], va);
                ldm_x4t(vl[dgrp], va + AMAT * 2);
            }
            #pragma unroll
            for (int i = 0; i < 2; i++)
                #pragma unroll
                for (int jd = 0; jd < 8; jd++) {
                    const int vg = jd >> 1, sel = (jd & 1) * 2;
                    mma16816(oacc[i][jd], ph[i], &vh[vg][sel]);
                    mma16816(oacc[i][jd], ph[i], &vl[vg][sel]);
                    mma16816(oacc[i][jd], pl[i], &vh[vg][sel]);
                }
        }
        __syncthreads();
    }

    #pragma unroll
    for (int i = 0; i < 2; i++) {
        #pragma unroll
        for (int half = 0; half < 2; half++) {
            const int t = i * 2 + half;
            const float inv = 1.f / lstat[t];
            const size_t row = rowbase + wid * 32 + i * 16 + g2 + half * 8;
            #pragma unroll
            for (int jd = 0; jd < 8; jd++) {
                const int col = hoff + jd * 8 + t2 * 2;
                const float vx = oacc[i][jd][half * 2]     * inv;
                const float vy = oacc[i][jd][half * 2 + 1] * inv;
                const float hx = __bfloat162float(__float2bfloat16_rn(vx));
                const float hy = __bfloat162float(__float2bfloat16_rn(vy));
                *reinterpret_cast<uint32_t*>(Ohi + row * EMB + col) = pack_bf16(vx, vy);
                *reinterpret_cast<uint32_t*>(Olo + row * EMB + col) = pack_bf16(vx - hx, vy - hy);
            }
        }
    }
}

// ---------------- host orchestration ----------------
static inline int gclamp(int ntiles) { return ntiles < 148 ? ntiles : 148; }

extern "C" void kernel_launch(void* const* d_in, const int* in_sizes, int n_in,
                              void* d_out, int out_size)
{
    const int*   idx  = (const int*)  d_in[0];
    const float* tok  = (const float*)d_in[1];
    const float* pos  = (const float*)d_in[2];
    const float* Wq   = (const float*)d_in[3];
    const float* Wk   = (const float*)d_in[4];
    const float* Wv   = (const float*)d_in[5];
    const float* Wo   = (const float*)d_in[6];
    const float* bo   = (const float*)d_in[7];
    const float* W1   = (const float*)d_in[8];
    const float* b1   = (const float*)d_in[9];
    const float* W2   = (const float*)d_in[10];
    const float* b2   = (const float*)d_in[11];
    const float* ln1g = (const float*)d_in[12];
    const float* ln1b = (const float*)d_in[13];
    const float* ln2g = (const float*)d_in[14];
    const float* ln2b = (const float*)d_in[15];
    const float* lnfg = (const float*)d_in[16];
    const float* lnfb = (const float*)d_in[17];
    const float* lmb  = (const float*)d_in[18];
    float* out = (float*)d_out;

    float* x;
    __nv_bfloat16 *whi, *wlo, *tokhi, *toklo;
    __nv_bfloat16 *ahi, *alo, *qkvh, *qkvl, *ohi, *olo, *fhi, *flo;
    cudaGetSymbolAddress((void**)&x,  g_x);
    cudaGetSymbolAddress((void**)&whi, g_Whi);
    cudaGetSymbolAddress((void**)&wlo, g_Wlo);
    cudaGetSymbolAddress((void**)&tokhi, g_tokhi);
    cudaGetSymbolAddress((void**)&toklo, g_toklo);
    cudaGetSymbolAddress((void**)&ahi, g_ahi);
    cudaGetSymbolAddress((void**)&alo, g_alo);
    cudaGetSymbolAddress((void**)&qkvh, g_qkvh);
    cudaGetSymbolAddress((void**)&qkvl, g_qkvl);
    cudaGetSymbolAddress((void**)&ohi, g_ohi);
    cudaGetSymbolAddress((void**)&olo, g_olo);
    cudaGetSymbolAddress((void**)&fhi, g_fhi);
    cudaGetSymbolAddress((void**)&flo, g_flo);

    cudaFuncSetAttribute(attn_tc_kernel, cudaFuncAttributeMaxDynamicSharedMemorySize, ATTN_SMEM);
    cudaFuncSetAttribute(mma_gemm<false,false,false,true>, cudaFuncAttributeMaxDynamicSharedMemorySize, GEMM_SMEM);
    cudaFuncSetAttribute(mma_gemm<true,false,true,false>,  cudaFuncAttributeMaxDynamicSharedMemorySize, GEMM_SMEM);
    cudaFuncSetAttribute(mma_gemm<true,true,false,true>,   cudaFuncAttributeMaxDynamicSharedMemorySize, GEMM_SMEM);
    cudaFuncSetAttribute(mma_gemm<true,false,false,false>, cudaFuncAttributeMaxDynamicSharedMemorySize, GEMM_SMEM);

    const dim3 tb(32, 8);

    // ---- weight conversion (transpose + split to bf16 hi/lo) ----
    for (int l = 0; l < LAY; l++) {
        const size_t wb = (size_t)l * WPL;
        const size_t we = (size_t)l * EMB * EMB;
        tsplit_kernel<<<dim3(EMB / 32, EMB / 32), tb>>>(Wq + we, whi + wb + OFF_WQ,            wlo + wb + OFF_WQ,            EMB, EMB);
        tsplit_kernel<<<dim3(EMB / 32, EMB / 32), tb>>>(Wk + we, whi + wb + OFF_WQ + (1ull<<20), wlo + wb + OFF_WQ + (1ull<<20), EMB, EMB);
        tsplit_kernel<<<dim3(EMB / 32, EMB / 32), tb>>>(Wv + we, whi + wb + OFF_WQ + (2ull<<20), wlo + wb + OFF_WQ + (2ull<<20), EMB, EMB);
        tsplit_kernel<<<dim3(EMB / 32, EMB / 32), tb>>>(Wo + we, whi + wb + OFF_WO, wlo + wb + OFF_WO, EMB, EMB);
        tsplit_kernel<<<dim3(DFF / 32, EMB / 32), tb>>>(W1 + (size_t)l * EMB * DFF, whi + wb + OFF_W1, wlo + wb + OFF_W1, EMB, DFF);
        tsplit_kernel<<<dim3(EMB / 32, DFF / 32), tb>>>(W2 + (size_t)l * DFF * EMB, whi + wb + OFF_W2, wlo + wb + OFF_W2, DFF, EMB);
    }
    {
        const int n4 = (int)(((size_t)VOC * EMB) / 4);
        split4_kernel<<<(n4 + 255) / 256, 256>>>(tok, tokhi, toklo, n4);
    }

    embed_kernel<<<(MROWS * EMB) / 256, 256>>>(x, idx, tok, pos);

    const int ntQKV = (MROWS / 128) * (QKV / 128);     // 384
    const int ntE   = (MROWS / 128) * (EMB / 128);     // 128
    const int ntF   = (MROWS / 128) * (DFF / 128);     // 512
    const int ntV   = (MROWS / 128) * (VOC / 128);     // 4000
    const dim3 gattn(SEQ / 128, BSZ * NH);

    for (int l = 0; l < LAY; l++) {
        const size_t wb = (size_t)l * WPL;
        ln_split_kernel<<<MROWS, 256>>>(ahi, alo, x, ln1g + (size_t)l * EMB, ln1b + (size_t)l * EMB);
        mma_gemm<false,false,false,true><<<gclamp(ntQKV), 256, GEMM_SMEM>>>(
            ahi, alo, whi + wb + OFF_WQ, wlo + wb + OFF_WQ, nullptr, nullptr, nullptr,
            qkvh, qkvl, QKV, EMB, QKV / 128, ntQKV);
        attn_tc_kernel<<<gattn, 128, ATTN_SMEM>>>(qkvh, qkvl, ohi, olo);
        mma_gemm<true,false,true,false><<<gclamp(ntE), 256, GEMM_SMEM>>>(
            ohi, olo, whi + wb + OFF_WO, wlo + wb + OFF_WO, bo + (size_t)l * EMB, x, x,
            nullptr, nullptr, EMB, EMB, EMB / 128, ntE);
        ln_split_kernel<<<MROWS, 256>>>(ahi, alo, x, ln2g + (size_t)l * EMB, ln2b + (size_t)l * EMB);
        mma_gemm<true,true,false,true><<<gclamp(ntF), 256, GEMM_SMEM>>>(
            ahi, alo, whi + wb + OFF_W1, wlo + wb + OFF_W1, b1 + (size_t)l * DFF, nullptr, nullptr,
            fhi, flo, DFF, EMB, DFF / 128, ntF);
        mma_gemm<true,false,true,false><<<gclamp(ntE), 256, GEMM_SMEM>>>(
            fhi, flo, whi + wb + OFF_W2, wlo + wb + OFF_W2, b2 + (size_t)l * EMB, x, x,
            nullptr, nullptr, EMB, DFF, EMB / 128, ntE);
    }

    ln_split_kernel<<<MROWS, 256>>>(ahi, alo, x, lnfg, lnfb);
    mma_gemm<true,false,false,false><<<gclamp(ntV), 256, GEMM_SMEM>>>(
        ahi, alo, tokhi, toklo, lmb, nullptr, out,
        nullptr, nullptr, VOC, EMB, VOC / 128, ntV);
}

// round 8
// speedup vs baseline: 3.0442x; 1.0174x over previous
#include <cuda_runtime.h>
#include <cuda_bf16.h>
#include <cstdint>
#include <math.h>

// ---------------- problem constants ----------------
constexpr int LAY = 8;
constexpr int NH  = 16;
constexpr int EMB = 1024;
constexpr int VOC = 32000;
constexpr int SEQ = 1024;
constexpr int BSZ = 2;
constexpr int DFF = 4096;
constexpr int MROWS = BSZ * SEQ;   // 2048
constexpr int QKV = 3 * EMB;       // 3072

// ---------------- scratch (device globals; no cudaMalloc allowed) ----------------
__device__ float g_x [MROWS * EMB];

constexpr size_t WPL = 4ull * EMB * EMB + 2ull * EMB * DFF;
__device__ __align__(16) __nv_bfloat16 g_Whi[LAY * WPL];
__device__ __align__(16) __nv_bfloat16 g_Wlo[LAY * WPL];
__device__ __align__(16) __nv_bfloat16 g_tokhi[(size_t)VOC * EMB];
__device__ __align__(16) __nv_bfloat16 g_toklo[(size_t)VOC * EMB];

__device__ __align__(16) __nv_bfloat16 g_ahi[MROWS * EMB];
__device__ __align__(16) __nv_bfloat16 g_alo[MROWS * EMB];
__device__ __align__(16) __nv_bfloat16 g_qkvh[MROWS * QKV];
__device__ __align__(16) __nv_bfloat16 g_qkvl[MROWS * QKV];
__device__ __align__(16) __nv_bfloat16 g_ohi[MROWS * EMB];
__device__ __align__(16) __nv_bfloat16 g_olo[MROWS * EMB];
__device__ __align__(16) __nv_bfloat16 g_fhi[MROWS * DFF];
__device__ __align__(16) __nv_bfloat16 g_flo[MROWS * DFF];

// per-layer weight offsets inside WPL block (transposed to [N,K]); WQ/WK/WV contiguous => fused [3072,1024]
constexpr size_t OFF_WQ = 0;
constexpr size_t OFF_WO = 3ull << 20;
constexpr size_t OFF_W1 = 4ull << 20;
constexpr size_t OFF_W2 = 8ull << 20;

// ---------------- low-level helpers ----------------
__device__ __forceinline__ uint32_t smem_u32(const void* p) {
    uint32_t a;
    asm("{ .reg .u64 t; cvta.to.shared.u64 t, %1; cvt.u32.u64 %0, t; }" : "=r"(a) : "l"(p));
    return a;
}
__device__ __forceinline__ void cp16(uint32_t s, const void* g) {
    asm volatile("cp.async.cg.shared.global [%0], [%1], 16;" :: "r"(s), "l"(g) : "memory");
}
__device__ __forceinline__ void cp_commit() {
    asm volatile("cp.async.commit_group;" ::: "memory");
}
__device__ __forceinline__ void cp_wait1() {
    asm volatile("cp.async.wait_group 1;" ::: "memory");
}
__device__ __forceinline__ void cp_wait0() {
    asm volatile("cp.async.wait_group 0;" ::: "memory");
}
__device__ __forceinline__ void ldm_x4(uint32_t* r, uint32_t a) {
    asm volatile("ldmatrix.sync.aligned.m8n8.x4.shared.b16 {%0,%1,%2,%3}, [%4];"
                 : "=r"(r[0]), "=r"(r[1]), "=r"(r[2]), "=r"(r[3]) : "r"(a));
}
__device__ __forceinline__ void ldm_x4t(uint32_t* r, uint32_t a) {
    asm volatile("ldmatrix.sync.aligned.m8n8.x4.trans.shared.b16 {%0,%1,%2,%3}, [%4];"
                 : "=r"(r[0]), "=r"(r[1]), "=r"(r[2]), "=r"(r[3]) : "r"(a));
}
__device__ __forceinline__ void mma16816(float* d, const uint32_t* a, const uint32_t* b) {
    asm volatile(
        "mma.sync.aligned.m16n8k16.row.col.f32.bf16.bf16.f32 "
        "{%0,%1,%2,%3}, {%4,%5,%6,%7}, {%8,%9}, {%0,%1,%2,%3};"
        : "+f"(d[0]), "+f"(d[1]), "+f"(d[2]), "+f"(d[3])
        : "r"(a[0]), "r"(a[1]), "r"(a[2]), "r"(a[3]), "r"(b[0]), "r"(b[1]));
}
__device__ __forceinline__ uint32_t pack_bf16(float x, float y) {
    __nv_bfloat162 t = __floats2bfloat162_rn(x, y);
    return *reinterpret_cast<uint32_t*>(&t);
}

// ---------------- merged weight conversion (single launch) ----------------
// Transposing segments: per layer 6144 blocks:
//   [0,512)x4: Wq/Wk/Wv/Wo (K=1024,N=1024), [2048,4096): W1 (K=1024,N=4096),
//   [4096,6144): W2 (K=4096,N=1024).  Tile = 64 n-rows x 32 k-cols, 256 threads.
// Tok segment: copy-split, 2048 elems/block.
constexpr int CONV_WBLKS = LAY * 6144;                         // 49152
constexpr int CONV_TOKBLKS = (VOC * EMB) / 2048;               // 16000
constexpr int CONV_BLKS = CONV_WBLKS + CONV_TOKBLKS;

__global__ __launch_bounds__(256) void conv_all_kernel(
    const float* __restrict__ Wq, const float* __restrict__ Wk,
    const float* __restrict__ Wv, const float* __restrict__ Wo,
    const float* __restrict__ W1, const float* __restrict__ W2,
    const float* __restrict__ tok,
    __nv_bfloat16* __restrict__ whi, __nv_bfloat16* __restrict__ wlo,
    __nv_bfloat16* __restrict__ tokhi, __nv_bfloat16* __restrict__ toklo)
{
    const int blk = blockIdx.x;
    const int tid = threadIdx.x;
    if (blk < CONV_WBLKS) {
        const int l = blk / 6144;
        int r = blk % 6144;
        const float* src;
        size_t dst;
        int K, N;
        if (r < 2048) {
            const int m = r >> 9;       // 0..3
            r &= 511;
            src = (m == 0 ? Wq : m == 1 ? Wk : m == 2 ? Wv : Wo) + (size_t)l * EMB * EMB;
            dst = (size_t)l * WPL + (m < 3 ? ((size_t)m << 20) : OFF_WO);
            K = EMB; N = EMB;
        } else if (r < 4096) {
            r -= 2048;
            src = W1 + (size_t)l * EMB * DFF;
            dst = (size_t)l * WPL + OFF_W1;
            K = EMB; N = DFF;
        } else {
            r -= 4096;
            src = W2 + (size_t)l * DFF * EMB;
            dst = (size_t)l * WPL + OFF_W2;
            K = DFF; N = EMB;
        }
        const int ntk = K >> 5;
        const int n0 = (r / ntk) * 64;
        const int k0 = (r % ntk) * 32;
        const int lane = tid & 31, w = tid >> 5;
        const int n  = n0 + w * 8 + (lane >> 2);
        const int kg = k0 + (lane & 3) * 8;

        float v[8];
        #pragma unroll
        for (int i = 0; i < 8; i++)
            v[i] = src[(size_t)(kg + i) * N + n];
        uint32_t hp[4], lp[4];
        #pragma unroll
        for (int i = 0; i < 4; i++) {
            const float a = v[2 * i], b = v[2 * i + 1];
            const float ha = __bfloat162float(__float2bfloat16_rn(a));
            const float hb = __bfloat162float(__float2bfloat16_rn(b));
            hp[i] = pack_bf16(a, b);
            lp[i] = pack_bf16(a - ha, b - hb);
        }
        const size_t o = dst + (size_t)n * K + kg;
        *reinterpret_cast<uint4*>(whi + o) = *reinterpret_cast<uint4*>(hp);
        *reinterpret_cast<uint4*>(wlo + o) = *reinterpret_cast<uint4*>(lp);
    } else {
        // tok: straight copy-split (tok is [V,E] row-major = already [N,K])
        const size_t base = (size_t)(blk - CONV_WBLKS) * 2048 + (size_t)tid * 8;
        const float4 a = *reinterpret_cast<const float4*>(tok + base);
        const float4 b = *reinterpret_cast<const float4*>(tok + base + 4);
        uint32_t hp[4], lp[4];
        const float h0 = __bfloat162float(__float2bfloat16_rn(a.x));
        const float h1 = __bfloat162float(__float2bfloat16_rn(a.y));
        const float h2 = __bfloat162float(__float2bfloat16_rn(a.z));
        const float h3 = __bfloat162float(__float2bfloat16_rn(a.w));
        const float h4 = __bfloat162float(__float2bfloat16_rn(b.x));
        const float h5 = __bfloat162float(__float2bfloat16_rn(b.y));
        const float h6 = __bfloat162float(__float2bfloat16_rn(b.z));
        const float h7 = __bfloat162float(__float2bfloat16_rn(b.w));
        hp[0] = pack_bf16(a.x, a.y);  hp[1] = pack_bf16(a.z, a.w);
        hp[2] = pack_bf16(b.x, b.y);  hp[3] = pack_bf16(b.z, b.w);
        lp[0] = pack_bf16(a.x - h0, a.y - h1);
        lp[1] = pack_bf16(a.z - h2, a.w - h3);
        lp[2] = pack_bf16(b.x - h4, b.y - h5);
        lp[3] = pack_bf16(b.z - h6, b.w - h7);
        *reinterpret_cast<uint4*>(tokhi + base) = *reinterpret_cast<uint4*>(hp);
        *reinterpret_cast<uint4*>(toklo + base) = *reinterpret_cast<uint4*>(lp);
    }
}

// ---------------- embedding ----------------
__global__ void embed_kernel(float* __restrict__ x, const int* __restrict__ idx,
                             const float* __restrict__ tok, const float* __restrict__ pos)
{
    int i = blockIdx.x * blockDim.x + threadIdx.x;
    int e  = i & (EMB - 1);
    int bt = i >> 10;
    int t  = bt & (SEQ - 1);
    x[i] = tok[(size_t)idx[bt] * EMB + e] + pos[(size_t)t * EMB + e];
}

// ---------------- layernorm (warp-per-row) with fused bf16 split output ----------------
__global__ __launch_bounds__(256) void ln_split_kernel(
    __nv_bfloat16* __restrict__ ohi, __nv_bfloat16* __restrict__ olo,
    const float* __restrict__ in,
    const float* __restrict__ g, const float* __restrict__ b)
{
    const int row  = blockIdx.x * 8 + (threadIdx.x >> 5);
    const int lane = threadIdx.x & 31;
    const float* xr = in + (size_t)row * EMB;

    float4 v[8];
    float s = 0.f;
    #pragma unroll
    for (int i = 0; i < 8; i++) {
        v[i] = *reinterpret_cast<const float4*>(xr + i * 128 + lane * 4);
        s += v[i].x + v[i].y + v[i].z + v[i].w;
    }
    #pragma unroll
    for (int o = 16; o; o >>= 1) s += __shfl_xor_sync(0xffffffffu, s, o);
    const float m = s * (1.f / EMB);

    float ss = 0.f;
    #pragma unroll
    for (int i = 0; i < 8; i++) {
        const float dx = v[i].x - m, dy = v[i].y - m, dz = v[i].z - m, dw = v[i].w - m;
        ss += dx * dx + dy * dy + dz * dz + dw * dw;
    }
    #pragma unroll
    for (int o = 16; o; o >>= 1) ss += __shfl_xor_sync(0xffffffffu, ss, o);
    const float r = rsqrtf(ss * (1.f / EMB) + 1e-5f);

    #pragma unroll
    for (int i = 0; i < 8; i++) {
        const int c0 = i * 128 + lane * 4;
        const float4 g4 = *reinterpret_cast<const float4*>(g + c0);
        const float4 b4 = *reinterpret_cast<const float4*>(b + c0);
        const float ox = (v[i].x - m) * r * g4.x + b4.x;
        const float oy = (v[i].y - m) * r * g4.y + b4.y;
        const float oz = (v[i].z - m) * r * g4.z + b4.z;
        const float ow = (v[i].w - m) * r * g4.w + b4.w;
        const float hx = __bfloat162float(__float2bfloat16_rn(ox));
        const float hy = __bfloat162float(__float2bfloat16_rn(oy));
        const float hz = __bfloat162float(__float2bfloat16_rn(oz));
        const float hw = __bfloat162float(__float2bfloat16_rn(ow));
        uint32_t hp[2], lp[2];
        hp[0] = pack_bf16(ox, oy);  hp[1] = pack_bf16(oz, ow);
        lp[0] = pack_bf16(ox - hx, oy - hy);
        lp[1] = pack_bf16(oz - hz, ow - hw);
        *reinterpret_cast<uint2*>(ohi + (size_t)row * EMB + c0) = *reinterpret_cast<uint2*>(hp);
        *reinterpret_cast<uint2*>(olo + (size_t)row * EMB + c0) = *reinterpret_cast<uint2*>(lp);
    }
}

// ---------------- bf16x3 GEMM on mma.sync, persistent tiles, BK=64, 3-stage ----------------
constexpr int PITCH = 72;                        // bf16 elems; 144B rows, conflict-free ldmatrix
constexpr int MAT_BYTES = 128 * PITCH * 2;       // 18432
constexpr int STAGE_BYTES = 4 * MAT_BYTES;       // 73728
constexpr int GSTAGES = 3;
constexpr int GEMM_SMEM = GSTAGES * STAGE_BYTES; // 221184

template<bool BIAS, bool RELU, bool RES, bool SPLIT>
__global__ __launch_bounds__(256) void mma_gemm(
    const __nv_bfloat16* __restrict__ Ahi, const __nv_bfloat16* __restrict__ Alo,
    const __nv_bfloat16* __restrict__ Bhi, const __nv_bfloat16* __restrict__ Blo,
    const float* __restrict__ bias, const float* __restrict__ res,
    float* __restrict__ C,
    __nv_bfloat16* __restrict__ Chi, __nv_bfloat16* __restrict__ Clo,
    int N, int K, int ntn, int ntiles)
{
    extern __shared__ char sm[];
    const int tid  = threadIdx.x;
    const int lane = tid & 31, wid = tid >> 5;
    const int wm = wid >> 1, wn = wid & 1;
    const uint32_t smb = smem_u32(sm);
    const int NC = K >> 6;

    const int rA = lane & 15, cA = lane >> 4;
    uint32_t offA[2];
    #pragma unroll
    for (int i = 0; i < 2; i++)
        offA[i] = (uint32_t)(((wm * 32 + i * 16 + rA) * PITCH + cA * 8) * 2);
    const int rB = (lane & 7) | ((lane >> 4) << 3), cB = (lane >> 3) & 1;
    uint32_t offB[4];
    #pragma unroll
    for (int j = 0; j < 4; j++)
        offB[j] = (uint32_t)(((wn * 64 + j * 16 + rB) * PITCH + cB * 8) * 2);

    const int g2 = lane >> 2, t2 = lane & 3;

    for (int t = blockIdx.x; t < ntiles; t += gridDim.x) {
        const int bm0 = (t / ntn) * 128;
        const int bn0 = (t % ntn) * 128;

        float acc[2][8][4];
        #pragma unroll
        for (int i = 0; i < 2; i++)
            #pragma unroll
            for (int j = 0; j < 8; j++)
                #pragma unroll
                for (int q = 0; q < 4; q++) acc[i][j][q] = 0.f;

        auto issue = [&](int c) {
            const int k0 = c << 6;
            const uint32_t st = smb + (c % GSTAGES) * STAGE_BYTES;
            #pragma unroll
            for (int it = 0; it < 4; it++) {
                const int idx = tid + it * 256;
                const int row = idx >> 3, seg = idx & 7;
                const uint32_t so = (uint32_t)(row * PITCH * 2 + seg * 16);
                const size_t ga = (size_t)(bm0 + row) * K + k0 + seg * 8;
                const size_t gb = (size_t)(bn0 + row) * K + k0 + seg * 8;
                cp16(st + so,                 Ahi + ga);
                cp16(st + MAT_BYTES + so,     Alo + ga);
                cp16(st + 2 * MAT_BYTES + so, Bhi + gb);
                cp16(st + 3 * MAT_BYTES + so, Blo + gb);
            }
            cp_commit();
        };

        issue(0);
        if (NC > 1) issue(1);

        for (int c = 0; c < NC; c++) {
            if (c + 2 < NC) cp_wait1(); else cp_wait0();
            __syncthreads();
            if (c + 2 < NC) issue(c + 2);

            const uint32_t st = smb + (c % GSTAGES) * STAGE_BYTES;
            #pragma unroll
            for (int ks = 0; ks < 4; ks++) {
                const uint32_t kadd = ks * 32;
                uint32_t ah[2][4], al[2][4], bh[4][4], bl[4][4];
                #pragma unroll
                for (int i = 0; i < 2; i++) {
                    ldm_x4(ah[i], st + offA[i] + kadd);
                    ldm_x4(al[i], st + MAT_BYTES + offA[i] + kadd);
                }
                #pragma unroll
                for (int j = 0; j < 4; j++) {
                    ldm_x4(bh[j], st + 2 * MAT_BYTES + offB[j] + kadd);
                    ldm_x4(bl[j], st + 3 * MAT_BYTES + offB[j] + kadd);
                }
                #pragma unroll
                for (int i = 0; i < 2; i++)
                    #pragma unroll
                    for (int j = 0; j < 8; j++) {
                        const int j4 = j >> 1, hh = (j & 1) * 2;
                        mma16816(acc[i][j], ah[i], &bh[j4][hh]);
                        mma16816(acc[i][j], ah[i], &bl[j4][hh]);
                        mma16816(acc[i][j], al[i], &bh[j4][hh]);
                    }
            }
        }

        #pragma unroll
        for (int i = 0; i < 2; i++) {
            #pragma unroll
            for (int j = 0; j < 8; j++) {
                const int row0 = bm0 + wm * 32 + i * 16 + g2;
                const int col  = bn0 + wn * 64 + j * 8 + t2 * 2;
                #pragma unroll
                for (int half = 0; half < 2; half++) {
                    const int row = row0 + half * 8;
                    float vx = acc[i][j][half * 2 + 0];
                    float vy = acc[i][j][half * 2 + 1];
                    if (BIAS) { vx += bias[col]; vy += bias[col + 1]; }
                    if (RES) {
                        const float2 rr = *reinterpret_cast<const float2*>(res + (size_t)row * N + col);
                        vx += rr.x; vy += rr.y;
                    }
                    if (RELU) { vx = fmaxf(vx, 0.f); vy = fmaxf(vy, 0.f); }
                    if (SPLIT) {
                        float hx = __bfloat162float(__float2bfloat16_rn(vx));
                        float hy = __bfloat162float(__float2bfloat16_rn(vy));
                        *reinterpret_cast<uint32_t*>(Chi + (size_t)row * N + col) = pack_bf16(vx, vy);
                        *reinterpret_cast<uint32_t*>(Clo + (size_t)row * N + col) = pack_bf16(vx - hx, vy - hy);
                    } else {
                        float2 v; v.x = vx; v.y = vy;
                        *reinterpret_cast<float2*>(C + (size_t)row * N + col) = v;
                    }
                }
            }
        }
        __syncthreads();
    }
}

// ---------------- tensor-core flash attention (bf16x3, causal), packed QKV ----------------
constexpr int AP = 72;
constexpr int AQ_HI = 0;
constexpr int AQ_LO = 128 * AP;
constexpr int AST0  = 2 * 128 * AP;
constexpr int AMAT  = 64 * AP;
constexpr int ASTAGE = 4 * AMAT;
constexpr int ATTN_SMEM = (AST0 + 2 * ASTAGE) * 2;   // 110,592 bytes

__global__ __launch_bounds__(128) void attn_tc_kernel(
    const __nv_bfloat16* __restrict__ QKVh, const __nv_bfloat16* __restrict__ QKVl,
    __nv_bfloat16* __restrict__ Ohi, __nv_bfloat16* __restrict__ Olo)
{
    extern __shared__ __nv_bfloat16 smb16[];
    const uint32_t smb = smem_u32(smb16);

    const int qt = gridDim.x - 1 - blockIdx.x;    // longest-first scheduling
    const int bh = blockIdx.y;
    const int b  = bh >> 4;
    const int h  = bh & 15;
    const int tid = threadIdx.x;
    const int lane = tid & 31, wid = tid >> 5;
    const int g2 = lane >> 2, t2 = lane & 3;

    const size_t rowbase = (size_t)(b * SEQ + qt * 128);
    const int hoff = h * 64;

    #pragma unroll
    for (int it = 0; it < 8; it++) {
        int idx = tid + it * 128;
        int row = idx >> 3, c8 = (idx & 7) * 8;
        const size_t gq = (rowbase + row) * QKV + hoff + c8;
        *reinterpret_cast<uint4*>(smb16 + AQ_HI + row * AP + c8) =
            *reinterpret_cast<const uint4*>(QKVh + gq);
        *reinterpret_cast<uint4*>(smb16 + AQ_LO + row * AP + c8) =
            *reinterpret_cast<const uint4*>(QKVl + gq);
    }

    auto issue_kv = [&](int jt) {
        const uint32_t st = smb + (AST0 + (jt & 1) * ASTAGE) * 2;
        const size_t kb = (size_t)(b * SEQ + jt * 64);
        #pragma unroll
        for (int it = 0; it < 4; it++) {
            int idx = tid + it * 128;
            int row = idx >> 3, c8 = (idx & 7) * 8;
            const size_t g = (kb + row) * QKV + hoff + c8;
            const uint32_t so = (uint32_t)((row * AP + c8) * 2);
            cp16(st + so,            QKVh + g + EMB);
            cp16(st + AMAT * 2 + so, QKVl + g + EMB);
            cp16(st + AMAT * 4 + so, QKVh + g + 2 * EMB);
            cp16(st + AMAT * 6 + so, QKVl + g + 2 * EMB);
        }
        cp_commit();
    };

    const int rA = lane & 15, cA = lane >> 4;
    uint32_t qoff[2];
    #pragma unroll
    for (int i = 0; i < 2; i++)
        qoff[i] = (uint32_t)(((wid * 32 + i * 16 + rA) * AP + cA * 8) * 2);
    const int rB = (lane & 7) | ((lane >> 4) << 3), cB = (lane >> 3) & 1;
    uint32_t koff[4];
    #pragma unroll
    for (int j = 0; j < 4; j++)
        koff[j] = (uint32_t)(((j * 16 + rB) * AP + cB * 8) * 2);
    const uint32_t voff_row = (uint32_t)(rA * AP + cA * 8) * 2;

    float oacc[2][8][4];
    float mstat[4], lstat[4];
    #pragma unroll
    for (int i = 0; i < 2; i++)
        #pragma unroll
        for (int j = 0; j < 8; j++)
            #pragma unroll
            for (int q = 0; q < 4; q++) oacc[i][j][q] = 0.f;
    #pragma unroll
    for (int t = 0; t < 4; t++) { mstat[t] = -1e30f; lstat[t] = 0.f; }

    const int NT = 2 * qt + 2;
    issue_kv(0);

    for (int jt = 0; jt < NT; jt++) {
        if (jt + 1 < NT) { issue_kv(jt + 1); cp_wait1(); }
        else cp_wait0();
        __syncthreads();

        const uint32_t st = smb + (AST0 + (jt & 1) * ASTAGE) * 2;

        float sacc[2][8][4];
        #pragma unroll
        for (int i = 0; i < 2; i++)
            #pragma unroll
            for (int j = 0; j < 8; j++)
                #pragma unroll
                for (int q = 0; q < 4; q++) sacc[i][j][q] = 0.f;

        #pragma unroll
        for (int ks = 0; ks < 4; ks++) {
            const uint32_t kadd = ks * 32;
            uint32_t qh[2][4], ql[2][4], kh[4][4], kl[4][4];
            #pragma unroll
            for (int i = 0; i < 2; i++) {
                ldm_x4(qh[i], smb + AQ_HI * 2 + qoff[i] + kadd);
                ldm_x4(ql[i], smb + AQ_LO * 2 + qoff[i] + kadd);
            }
            #pragma unroll
            for (int j = 0; j < 4; j++) {
                ldm_x4(kh[j], st + koff[j] + kadd);
                ldm_x4(kl[j], st + AMAT * 2 + koff[j] + kadd);
            }
            #pragma unroll
            for (int i = 0; i < 2; i++)
                #pragma unroll
                for (int j = 0; j < 8; j++) {
                    const int j4 = j >> 1, hh = (j & 1) * 2;
                    mma16816(sacc[i][j], qh[i], &kh[j4][hh]);
                    mma16816(sacc[i][j], qh[i], &kl[j4][hh]);
                    mma16816(sacc[i][j], ql[i], &kh[j4][hh]);
                }
        }

        const bool need_mask = (jt * 64 + 63) > (qt * 128);
        #pragma unroll
        for (int i = 0; i < 2; i++) {
            #pragma unroll
            for (int j = 0; j < 8; j++) {
                #pragma unroll
                for (int q = 0; q < 4; q++) {
                    float s = sacc[i][j][q] * 0.125f;
                    if (need_mask) {
                        const int row = qt * 128 + wid * 32 + i * 16 + g2 + (q >> 1) * 8;
                        const int col = jt * 64 + j * 8 + t2 * 2 + (q & 1);
                        if (col > row) s = -1e30f;
                    }
                    sacc[i][j][q] = s;
                }
            }
        }

        float alpha[4];
        #pragma unroll
        for (int i = 0; i < 2; i++) {
            #pragma unroll
            for (int half = 0; half < 2; half++) {
                const int t = i * 2 + half;
                float mx = -1e30f;
                #pragma unroll
                for (int j = 0; j < 8; j++)
                    mx = fmaxf(mx, fmaxf(sacc[i][j][half * 2], sacc[i][j][half * 2 + 1]));
                mx = fmaxf(mx, __shfl_xor_sync(0xffffffffu, mx, 1));
                mx = fmaxf(mx, __shfl_xor_sync(0xffffffffu, mx, 2));
                const float mnew = fmaxf(mstat[t], mx);
                alpha[t] = exp2f((mstat[t] - mnew) * 1.4426950408889634f);
                mstat[t] = mnew;
                float rs = 0.f;
                #pragma unroll
                for (int j = 0; j < 8; j++) {
                    float p0 = exp2f((sacc[i][j][half * 2]     - mnew) * 1.4426950408889634f);
                    float p1 = exp2f((sacc[i][j][half * 2 + 1] - mnew) * 1.4426950408889634f);
                    sacc[i][j][half * 2] = p0;
                    sacc[i][j][half * 2 + 1] = p1;
                    rs += p0 + p1;
                }
                rs += __shfl_xor_sync(0xffffffffu, rs, 1);
                rs += __shfl_xor_sync(0xffffffffu, rs, 2);
                lstat[t] = lstat[t] * alpha[t] + rs;
                #pragma unroll
                for (int j = 0; j < 8; j++) {
                    oacc[i][j][half * 2]     *= alpha[t];
                    oacc[i][j][half * 2 + 1] *= alpha[t];
                }
            }
        }

        #pragma unroll
        for (int kk = 0; kk < 4; kk++) {
            uint32_t ph[2][4], pl[2][4];
            #pragma unroll
            for (int i = 0; i < 2; i++) {
                const int j0 = 2 * kk, j1 = j0 + 1;
                const float c0 = sacc[i][j0][0], c1 = sacc[i][j0][1];
                const float c2 = sacc[i][j0][2], c3 = sacc[i][j0][3];
                const float d0 = sacc[i][j1][0], d1 = sacc[i][j1][1];
                const float d2 = sacc[i][j1][2], d3 = sacc[i][j1][3];
                ph[i][0] = pack_bf16(c0, c1);
                ph[i][1] = pack_bf16(c2, c3);
                ph[i][2] = pack_bf16(d0, d1);
                ph[i][3] = pack_bf16(d2, d3);
                const float h0 = __bfloat162float(__float2bfloat16_rn(c0));
                const float h1 = __bfloat162float(__float2bfloat16_rn(c1));
                const float h2 = __bfloat162float(__float2bfloat16_rn(c2));
                const float h3 = __bfloat162float(__float2bfloat16_rn(c3));
                const float e0 = __bfloat162float(__float2bfloat16_rn(d0));
                const float e1 = __bfloat162float(__float2bfloat16_rn(d1));
                const float e2 = __bfloat162float(__float2bfloat16_rn(d2));
                const float e3 = __bfloat162float(__float2bfloat16_rn(d3));
                pl[i][0] = pack_bf16(c0 - h0, c1 - h1);
                pl[i][1] = pack_bf16(c2 - h2, c3 - h3);
                pl[i][2] = pack_bf16(d0 - e0, d1 - e1);
                pl[i][3] = pack_bf16(d2 - e2, d3 - e3);
            }
            uint32_t vh[4][4], vl[4][4];
            const uint32_t vrow = (uint32_t)((kk * 16) * AP * 2);
            #pragma unroll
            for (int dgrp = 0; dgrp < 4; dgrp++) {
                const uint32_t va = st + AMAT * 4 + vrow + voff_row + (uint32_t)(dgrp * 16 * 2);
                ldm_x4t(vh[dgrp], va);
                ldm_x4t(vl[dgrp], va + AMAT * 2);
            }
            #pragma unroll
            for (int i = 0; i < 2; i++)
                #pragma unroll
                for (int jd = 0; jd < 8; jd++) {
                    const int vg = jd >> 1, sel = (jd & 1) * 2;
                    mma16816(oacc[i][jd], ph[i], &vh[vg][sel]);
                    mma16816(oacc[i][jd], ph[i], &vl[vg][sel]);
                    mma16816(oacc[i][jd], pl[i], &vh[vg][sel]);
                }
        }
        __syncthreads();
    }

    #pragma unroll
    for (int i = 0; i < 2; i++) {
        #pragma unroll
        for (int half = 0; half < 2; half++) {
            const int t = i * 2 + half;
            const float inv = 1.f / lstat[t];
            const size_t row = rowbase + wid * 32 + i * 16 + g2 + half * 8;
            #pragma unroll
            for (int jd = 0; jd < 8; jd++) {
                const int col = hoff + jd * 8 + t2 * 2;
                const float vx = oacc[i][jd][half * 2]     * inv;
                const float vy = oacc[i][jd][half * 2 + 1] * inv;
                const float hx = __bfloat162float(__float2bfloat16_rn(vx));
                const float hy = __bfloat162float(__float2bfloat16_rn(vy));
                *reinterpret_cast<uint32_t*>(Ohi + row * EMB + col) = pack_bf16(vx, vy);
                *reinterpret_cast<uint32_t*>(Olo + row * EMB + col) = pack_bf16(vx - hx, vy - hy);
            }
        }
    }
}

// ---------------- host orchestration ----------------
static inline int gclamp(int ntiles) { return ntiles < 148 ? ntiles : 148; }

extern "C" void kernel_launch(void* const* d_in, const int* in_sizes, int n_in,
                              void* d_out, int out_size)
{
    const int*   idx  = (const int*)  d_in[0];
    const float* tok  = (const float*)d_in[1];
    const float* pos  = (const float*)d_in[2];
    const float* Wq   = (const float*)d_in[3];
    const float* Wk   = (const float*)d_in[4];
    const float* Wv   = (const float*)d_in[5];
    const float* Wo   = (const float*)d_in[6];
    const float* bo   = (const float*)d_in[7];
    const float* W1   = (const float*)d_in[8];
    const float* b1   = (const float*)d_in[9];
    const float* W2   = (const float*)d_in[10];
    const float* b2   = (const float*)d_in[11];
    const float* ln1g = (const float*)d_in[12];
    const float* ln1b = (const float*)d_in[13];
    const float* ln2g = (const float*)d_in[14];
    const float* ln2b = (const float*)d_in[15];
    const float* lnfg = (const float*)d_in[16];
    const float* lnfb = (const float*)d_in[17];
    const float* lmb  = (const float*)d_in[18];
    float* out = (float*)d_out;

    float* x;
    __nv_bfloat16 *whi, *wlo, *tokhi, *toklo;
    __nv_bfloat16 *ahi, *alo, *qkvh, *qkvl, *ohi, *olo, *fhi, *flo;
    cudaGetSymbolAddress((void**)&x,  g_x);
    cudaGetSymbolAddress((void**)&whi, g_Whi);
    cudaGetSymbolAddress((void**)&wlo, g_Wlo);
    cudaGetSymbolAddress((void**)&tokhi, g_tokhi);
    cudaGetSymbolAddress((void**)&toklo, g_toklo);
    cudaGetSymbolAddress((void**)&ahi, g_ahi);
    cudaGetSymbolAddress((void**)&alo, g_alo);
    cudaGetSymbolAddress((void**)&qkvh, g_qkvh);
    cudaGetSymbolAddress((void**)&qkvl, g_qkvl);
    cudaGetSymbolAddress((void**)&ohi, g_ohi);
    cudaGetSymbolAddress((void**)&olo, g_olo);
    cudaGetSymbolAddress((void**)&fhi, g_fhi);
    cudaGetSymbolAddress((void**)&flo, g_flo);

    cudaFuncSetAttribute(attn_tc_kernel, cudaFuncAttributeMaxDynamicSharedMemorySize, ATTN_SMEM);
    cudaFuncSetAttribute(mma_gemm<false,false,false,true>, cudaFuncAttributeMaxDynamicSharedMemorySize, GEMM_SMEM);
    cudaFuncSetAttribute(mma_gemm<true,false,true,false>,  cudaFuncAttributeMaxDynamicSharedMemorySize, GEMM_SMEM);
    cudaFuncSetAttribute(mma_gemm<true,true,false,true>,   cudaFuncAttributeMaxDynamicSharedMemorySize, GEMM_SMEM);
    cudaFuncSetAttribute(mma_gemm<true,false,false,false>, cudaFuncAttributeMaxDynamicSharedMemorySize, GEMM_SMEM);

    // [0] merged weight + tok conversion (single launch)
    conv_all_kernel<<<CONV_BLKS, 256>>>(Wq, Wk, Wv, Wo, W1, W2, tok,
                                        whi, wlo, tokhi, toklo);
    // [1] embedding
    embed_kernel<<<(MROWS * EMB) / 256, 256>>>(x, idx, tok, pos);

    const int ntQKV = (MROWS / 128) * (QKV / 128);     // 384
    const int ntE   = (MROWS / 128) * (EMB / 128);     // 128
    const int ntF   = (MROWS / 128) * (DFF / 128);     // 512
    const int ntV   = (MROWS / 128) * (VOC / 128);     // 4000
    const dim3 gattn(SEQ / 128, BSZ * NH);

    for (int l = 0; l < LAY; l++) {
        const size_t wb = (size_t)l * WPL;
        ln_split_kernel<<<MROWS / 8, 256>>>(ahi, alo, x, ln1g + (size_t)l * EMB, ln1b + (size_t)l * EMB);
        mma_gemm<false,false,false,true><<<gclamp(ntQKV), 256, GEMM_SMEM>>>(
            ahi, alo, whi + wb + OFF_WQ, wlo + wb + OFF_WQ, nullptr, nullptr, nullptr,
            qkvh, qkvl, QKV, EMB, QKV / 128, ntQKV);
        attn_tc_kernel<<<gattn, 128, ATTN_SMEM>>>(qkvh, qkvl, ohi, olo);
        mma_gemm<true,false,true,false><<<gclamp(ntE), 256, GEMM_SMEM>>>(
            ohi, olo, whi + wb + OFF_WO, wlo + wb + OFF_WO, bo + (size_t)l * EMB, x, x,
            nullptr, nullptr, EMB, EMB, EMB / 128, ntE);
        ln_split_kernel<<<MROWS / 8, 256>>>(ahi, alo, x, ln2g + (size_t)l * EMB, ln2b + (size_t)l * EMB);
        mma_gemm<true,true,false,true><<<gclamp(ntF), 256, GEMM_SMEM>>>(
            ahi, alo, whi + wb + OFF_W1, wlo + wb + OFF_W1, b1 + (size_t)l * DFF, nullptr, nullptr,
            fhi, flo, DFF, EMB, DFF / 128, ntF);
        mma_gemm<true,false,true,false><<<gclamp(ntE), 256, GEMM_SMEM>>>(
            fhi, flo, whi + wb + OFF_W2, wlo + wb + OFF_W2, b2 + (size_t)l * EMB, x, x,
            nullptr, nullptr, EMB, DFF, EMB / 128, ntE);
    }

    ln_split_kernel<<<MROWS / 8, 256>>>(ahi, alo, x, lnfg, lnfb);
    mma_gemm<true,false,false,false><<<gclamp(ntV), 256, GEMM_SMEM>>>(
        ahi, alo, tokhi, toklo, lmb, nullptr, out,
        nullptr, nullptr, VOC, EMB, VOC / 128, ntV);
}

// round 9
// speedup vs baseline: 3.0863x; 1.0138x over previous
#include <cuda_runtime.h>
#include <cuda_bf16.h>
#include <cstdint>
#include <math.h>

// ---------------- problem constants ----------------
constexpr int LAY = 8;
constexpr int NH  = 16;
constexpr int EMB = 1024;
constexpr int VOC = 32000;
constexpr int SEQ = 1024;
constexpr int BSZ = 2;
constexpr int DFF = 4096;
constexpr int MROWS = BSZ * SEQ;   // 2048
constexpr int QKV = 3 * EMB;       // 3072

// ---------------- scratch (device globals; no cudaMalloc allowed) ----------------
__device__ float g_x [MROWS * EMB];

constexpr size_t WPL = 4ull * EMB * EMB + 2ull * EMB * DFF;
__device__ __align__(16) __nv_bfloat16 g_Whi[LAY * WPL];
__device__ __align__(16) __nv_bfloat16 g_Wlo[LAY * WPL];
__device__ __align__(16) __nv_bfloat16 g_tokhi[(size_t)VOC * EMB];
__device__ __align__(16) __nv_bfloat16 g_toklo[(size_t)VOC * EMB];

__device__ __align__(16) __nv_bfloat16 g_ahi[MROWS * EMB];
__device__ __align__(16) __nv_bfloat16 g_alo[MROWS * EMB];
__device__ __align__(16) __nv_bfloat16 g_qkvh[MROWS * QKV];
__device__ __align__(16) __nv_bfloat16 g_qkvl[MROWS * QKV];
__device__ __align__(16) __nv_bfloat16 g_ohi[MROWS * EMB];
__device__ __align__(16) __nv_bfloat16 g_olo[MROWS * EMB];
__device__ __align__(16) __nv_bfloat16 g_fhi[MROWS * DFF];
__device__ __align__(16) __nv_bfloat16 g_flo[MROWS * DFF];

// per-layer weight offsets inside WPL block (transposed to [N,K]); WQ/WK/WV contiguous => fused [3072,1024]
constexpr size_t OFF_WQ = 0;
constexpr size_t OFF_WO = 3ull << 20;
constexpr size_t OFF_W1 = 4ull << 20;
constexpr size_t OFF_W2 = 8ull << 20;

// ---------------- low-level helpers ----------------
__device__ __forceinline__ uint32_t smem_u32(const void* p) {
    uint32_t a;
    asm("{ .reg .u64 t; cvta.to.shared.u64 t, %1; cvt.u32.u64 %0, t; }" : "=r"(a) : "l"(p));
    return a;
}
__device__ __forceinline__ void cp16(uint32_t s, const void* g) {
    asm volatile("cp.async.cg.shared.global [%0], [%1], 16;" :: "r"(s), "l"(g) : "memory");
}
__device__ __forceinline__ void cp_commit() {
    asm volatile("cp.async.commit_group;" ::: "memory");
}
__device__ __forceinline__ void cp_wait1() {
    asm volatile("cp.async.wait_group 1;" ::: "memory");
}
__device__ __forceinline__ void cp_wait0() {
    asm volatile("cp.async.wait_group 0;" ::: "memory");
}
__device__ __forceinline__ void ldm_x4(uint32_t* r, uint32_t a) {
    asm volatile("ldmatrix.sync.aligned.m8n8.x4.shared.b16 {%0,%1,%2,%3}, [%4];"
                 : "=r"(r[0]), "=r"(r[1]), "=r"(r[2]), "=r"(r[3]) : "r"(a));
}
__device__ __forceinline__ void ldm_x4t(uint32_t* r, uint32_t a) {
    asm volatile("ldmatrix.sync.aligned.m8n8.x4.trans.shared.b16 {%0,%1,%2,%3}, [%4];"
                 : "=r"(r[0]), "=r"(r[1]), "=r"(r[2]), "=r"(r[3]) : "r"(a));
}
__device__ __forceinline__ void mma16816(float* d, const uint32_t* a, const uint32_t* b) {
    asm volatile(
        "mma.sync.aligned.m16n8k16.row.col.f32.bf16.bf16.f32 "
        "{%0,%1,%2,%3}, {%4,%5,%6,%7}, {%8,%9}, {%0,%1,%2,%3};"
        : "+f"(d[0]), "+f"(d[1]), "+f"(d[2]), "+f"(d[3])
        : "r"(a[0]), "r"(a[1]), "r"(a[2]), "r"(a[3]), "r"(b[0]), "r"(b[1]));
}
__device__ __forceinline__ uint32_t pack_bf16(float x, float y) {
    __nv_bfloat162 t = __floats2bfloat162_rn(x, y);
    return *reinterpret_cast<uint32_t*>(&t);
}

// ---------------- merged weight conversion (single launch) ----------------
constexpr int CONV_WBLKS = LAY * 6144;
constexpr int CONV_TOKBLKS = (VOC * EMB) / 2048;
constexpr int CONV_BLKS = CONV_WBLKS + CONV_TOKBLKS;

__global__ __launch_bounds__(256) void conv_all_kernel(
    const float* __restrict__ Wq, const float* __restrict__ Wk,
    const float* __restrict__ Wv, const float* __restrict__ Wo,
    const float* __restrict__ W1, const float* __restrict__ W2,
    const float* __restrict__ tok,
    __nv_bfloat16* __restrict__ whi, __nv_bfloat16* __restrict__ wlo,
    __nv_bfloat16* __restrict__ tokhi, __nv_bfloat16* __restrict__ toklo)
{
    const int blk = blockIdx.x;
    const int tid = threadIdx.x;
    if (blk < CONV_WBLKS) {
        const int l = blk / 6144;
        int r = blk % 6144;
        const float* src;
        size_t dst;
        int K, N;
        if (r < 2048) {
            const int m = r >> 9;
            r &= 511;
            src = (m == 0 ? Wq : m == 1 ? Wk : m == 2 ? Wv : Wo) + (size_t)l * EMB * EMB;
            dst = (size_t)l * WPL + (m < 3 ? ((size_t)m << 20) : OFF_WO);
            K = EMB; N = EMB;
        } else if (r < 4096) {
            r -= 2048;
            src = W1 + (size_t)l * EMB * DFF;
            dst = (size_t)l * WPL + OFF_W1;
            K = EMB; N = DFF;
        } else {
            r -= 4096;
            src = W2 + (size_t)l * DFF * EMB;
            dst = (size_t)l * WPL + OFF_W2;
            K = DFF; N = EMB;
        }
        const int ntk = K >> 5;
        const int n0 = (r / ntk) * 64;
        const int k0 = (r % ntk) * 32;
        const int lane = tid & 31, w = tid >> 5;
        const int n  = n0 + w * 8 + (lane >> 2);
        const int kg = k0 + (lane & 3) * 8;

        float v[8];
        #pragma unroll
        for (int i = 0; i < 8; i++)
            v[i] = src[(size_t)(kg + i) * N + n];
        uint32_t hp[4], lp[4];
        #pragma unroll
        for (int i = 0; i < 4; i++) {
            const float a = v[2 * i], b = v[2 * i + 1];
            const float ha = __bfloat162float(__float2bfloat16_rn(a));
            const float hb = __bfloat162float(__float2bfloat16_rn(b));
            hp[i] = pack_bf16(a, b);
            lp[i] = pack_bf16(a - ha, b - hb);
        }
        const size_t o = dst + (size_t)n * K + kg;
        *reinterpret_cast<uint4*>(whi + o) = *reinterpret_cast<uint4*>(hp);
        *reinterpret_cast<uint4*>(wlo + o) = *reinterpret_cast<uint4*>(lp);
    } else {
        const size_t base = (size_t)(blk - CONV_WBLKS) * 2048 + (size_t)tid * 8;
        const float4 a = *reinterpret_cast<const float4*>(tok + base);
        const float4 b = *reinterpret_cast<const float4*>(tok + base + 4);
        uint32_t hp[4], lp[4];
        const float h0 = __bfloat162float(__float2bfloat16_rn(a.x));
        const float h1 = __bfloat162float(__float2bfloat16_rn(a.y));
        const float h2 = __bfloat162float(__float2bfloat16_rn(a.z));
        const float h3 = __bfloat162float(__float2bfloat16_rn(a.w));
        const float h4 = __bfloat162float(__float2bfloat16_rn(b.x));
        const float h5 = __bfloat162float(__float2bfloat16_rn(b.y));
        const float h6 = __bfloat162float(__float2bfloat16_rn(b.z));
        const float h7 = __bfloat162float(__float2bfloat16_rn(b.w));
        hp[0] = pack_bf16(a.x, a.y);  hp[1] = pack_bf16(a.z, a.w);
        hp[2] = pack_bf16(b.x, b.y);  hp[3] = pack_bf16(b.z, b.w);
        lp[0] = pack_bf16(a.x - h0, a.y - h1);
        lp[1] = pack_bf16(a.z - h2, a.w - h3);
        lp[2] = pack_bf16(b.x - h4, b.y - h5);
        lp[3] = pack_bf16(b.z - h6, b.w - h7);
        *reinterpret_cast<uint4*>(tokhi + base) = *reinterpret_cast<uint4*>(hp);
        *reinterpret_cast<uint4*>(toklo + base) = *reinterpret_cast<uint4*>(lp);
    }
}

// ---------------- embedding ----------------
__global__ void embed_kernel(float* __restrict__ x, const int* __restrict__ idx,
                             const float* __restrict__ tok, const float* __restrict__ pos)
{
    int i = blockIdx.x * blockDim.x + threadIdx.x;
    int e  = i & (EMB - 1);
    int bt = i >> 10;
    int t  = bt & (SEQ - 1);
    x[i] = tok[(size_t)idx[bt] * EMB + e] + pos[(size_t)t * EMB + e];
}

// ---------------- layernorm (warp-per-row) with fused bf16 split output ----------------
__global__ __launch_bounds__(256) void ln_split_kernel(
    __nv_bfloat16* __restrict__ ohi, __nv_bfloat16* __restrict__ olo,
    const float* __restrict__ in,
    const float* __restrict__ g, const float* __restrict__ b)
{
    const int row  = blockIdx.x * 8 + (threadIdx.x >> 5);
    const int lane = threadIdx.x & 31;
    const float* xr = in + (size_t)row * EMB;

    float4 v[8];
    float s = 0.f;
    #pragma unroll
    for (int i = 0; i < 8; i++) {
        v[i] = *reinterpret_cast<const float4*>(xr + i * 128 + lane * 4);
        s += v[i].x + v[i].y + v[i].z + v[i].w;
    }
    #pragma unroll
    for (int o = 16; o; o >>= 1) s += __shfl_xor_sync(0xffffffffu, s, o);
    const float m = s * (1.f / EMB);

    float ss = 0.f;
    #pragma unroll
    for (int i = 0; i < 8; i++) {
        const float dx = v[i].x - m, dy = v[i].y - m, dz = v[i].z - m, dw = v[i].w - m;
        ss += dx * dx + dy * dy + dz * dz + dw * dw;
    }
    #pragma unroll
    for (int o = 16; o; o >>= 1) ss += __shfl_xor_sync(0xffffffffu, ss, o);
    const float r = rsqrtf(ss * (1.f / EMB) + 1e-5f);

    #pragma unroll
    for (int i = 0; i < 8; i++) {
        const int c0 = i * 128 + lane * 4;
        const float4 g4 = *reinterpret_cast<const float4*>(g + c0);
        const float4 b4 = *reinterpret_cast<const float4*>(b + c0);
        const float ox = (v[i].x - m) * r * g4.x + b4.x;
        const float oy = (v[i].y - m) * r * g4.y + b4.y;
        const float oz = (v[i].z - m) * r * g4.z + b4.z;
        const float ow = (v[i].w - m) * r * g4.w + b4.w;
        const float hx = __bfloat162float(__float2bfloat16_rn(ox));
        const float hy = __bfloat162float(__float2bfloat16_rn(oy));
        const float hz = __bfloat162float(__float2bfloat16_rn(oz));
        const float hw = __bfloat162float(__float2bfloat16_rn(ow));
        uint32_t hp[2], lp[2];
        hp[0] = pack_bf16(ox, oy);  hp[1] = pack_bf16(oz, ow);
        lp[0] = pack_bf16(ox - hx, oy - hy);
        lp[1] = pack_bf16(oz - hz, ow - hw);
        *reinterpret_cast<uint2*>(ohi + (size_t)row * EMB + c0) = *reinterpret_cast<uint2*>(hp);
        *reinterpret_cast<uint2*>(olo + (size_t)row * EMB + c0) = *reinterpret_cast<uint2*>(lp);
    }
}

// ---------------- bf16x3 GEMM (128x128 tile, 256 thr) — for N=1024 GEMMs ----------------
constexpr int PITCH = 72;
constexpr int MAT_BYTES = 128 * PITCH * 2;       // 18432
constexpr int STAGE_BYTES = 4 * MAT_BYTES;       // 73728
constexpr int GSTAGES = 3;
constexpr int GEMM_SMEM = GSTAGES * STAGE_BYTES; // 221184

template<bool BIAS, bool RELU, bool RES, bool SPLIT>
__global__ __launch_bounds__(256) void mma_gemm(
    const __nv_bfloat16* __restrict__ Ahi, const __nv_bfloat16* __restrict__ Alo,
    const __nv_bfloat16* __restrict__ Bhi, const __nv_bfloat16* __restrict__ Blo,
    const float* __restrict__ bias, const float* __restrict__ res,
    float* __restrict__ C,
    __nv_bfloat16* __restrict__ Chi, __nv_bfloat16* __restrict__ Clo,
    int N, int K, int ntn, int ntiles)
{
    extern __shared__ char sm[];
    const int tid  = threadIdx.x;
    const int lane = tid & 31, wid = tid >> 5;
    const int wm = wid >> 1, wn = wid & 1;
    const uint32_t smb = smem_u32(sm);
    const int NC = K >> 6;

    const int rA = lane & 15, cA = lane >> 4;
    uint32_t offA[2];
    #pragma unroll
    for (int i = 0; i < 2; i++)
        offA[i] = (uint32_t)(((wm * 32 + i * 16 + rA) * PITCH + cA * 8) * 2);
    const int rB = (lane & 7) | ((lane >> 4) << 3), cB = (lane >> 3) & 1;
    uint32_t offB[4];
    #pragma unroll
    for (int j = 0; j < 4; j++)
        offB[j] = (uint32_t)(((wn * 64 + j * 16 + rB) * PITCH + cB * 8) * 2);

    const int g2 = lane >> 2, t2 = lane & 3;

    for (int t = blockIdx.x; t < ntiles; t += gridDim.x) {
        const int bm0 = (t / ntn) * 128;
        const int bn0 = (t % ntn) * 128;

        float acc[2][8][4];
        #pragma unroll
        for (int i = 0; i < 2; i++)
            #pragma unroll
            for (int j = 0; j < 8; j++)
                #pragma unroll
                for (int q = 0; q < 4; q++) acc[i][j][q] = 0.f;

        auto issue = [&](int c) {
            const int k0 = c << 6;
            const uint32_t st = smb + (c % GSTAGES) * STAGE_BYTES;
            #pragma unroll
            for (int it = 0; it < 4; it++) {
                const int idx = tid + it * 256;
                const int row = idx >> 3, seg = idx & 7;
                const uint32_t so = (uint32_t)(row * PITCH * 2 + seg * 16);
                const size_t ga = (size_t)(bm0 + row) * K + k0 + seg * 8;
                const size_t gb = (size_t)(bn0 + row) * K + k0 + seg * 8;
                cp16(st + so,                 Ahi + ga);
                cp16(st + MAT_BYTES + so,     Alo + ga);
                cp16(st + 2 * MAT_BYTES + so, Bhi + gb);
                cp16(st + 3 * MAT_BYTES + so, Blo + gb);
            }
            cp_commit();
        };

        issue(0);
        if (NC > 1) issue(1);

        for (int c = 0; c < NC; c++) {
            if (c + 2 < NC) cp_wait1(); else cp_wait0();
            __syncthreads();
            if (c + 2 < NC) issue(c + 2);

            const uint32_t st = smb + (c % GSTAGES) * STAGE_BYTES;
            #pragma unroll
            for (int ks = 0; ks < 4; ks++) {
                const uint32_t kadd = ks * 32;
                uint32_t ah[2][4], al[2][4], bh[4][4], bl[4][4];
                #pragma unroll
                for (int i = 0; i < 2; i++) {
                    ldm_x4(ah[i], st + offA[i] + kadd);
                    ldm_x4(al[i], st + MAT_BYTES + offA[i] + kadd);
                }
                #pragma unroll
                for (int j = 0; j < 4; j++) {
                    ldm_x4(bh[j], st + 2 * MAT_BYTES + offB[j] + kadd);
                    ldm_x4(bl[j], st + 3 * MAT_BYTES + offB[j] + kadd);
                }
                #pragma unroll
                for (int i = 0; i < 2; i++)
                    #pragma unroll
                    for (int j = 0; j < 8; j++) {
                        const int j4 = j >> 1, hh = (j & 1) * 2;
                        mma16816(acc[i][j], ah[i], &bh[j4][hh]);
                        mma16816(acc[i][j], ah[i], &bl[j4][hh]);
                        mma16816(acc[i][j], al[i], &bh[j4][hh]);
                    }
            }
        }

        #pragma unroll
        for (int i = 0; i < 2; i++) {
            #pragma unroll
            for (int j = 0; j < 8; j++) {
                const int row0 = bm0 + wm * 32 + i * 16 + g2;
                const int col  = bn0 + wn * 64 + j * 8 + t2 * 2;
                #pragma unroll
                for (int half = 0; half < 2; half++) {
                    const int row = row0 + half * 8;
                    float vx = acc[i][j][half * 2 + 0];
                    float vy = acc[i][j][half * 2 + 1];
                    if (BIAS) { vx += bias[col]; vy += bias[col + 1]; }
                    if (RES) {
                        const float2 rr = *reinterpret_cast<const float2*>(res + (size_t)row * N + col);
                        vx += rr.x; vy += rr.y;
                    }
                    if (RELU) { vx = fmaxf(vx, 0.f); vy = fmaxf(vy, 0.f); }
                    if (SPLIT) {
                        float hx = __bfloat162float(__float2bfloat16_rn(vx));
                        float hy = __bfloat162float(__float2bfloat16_rn(vy));
                        *reinterpret_cast<uint32_t*>(Chi + (size_t)row * N + col) = pack_bf16(vx, vy);
                        *reinterpret_cast<uint32_t*>(Clo + (size_t)row * N + col) = pack_bf16(vx - hx, vy - hy);
                    } else {
                        float2 v; v.x = vx; v.y = vy;
                        *reinterpret_cast<float2*>(C + (size_t)row * N + col) = v;
                    }
                }
            }
        }
        __syncthreads();
    }
}

// ---------------- bf16x3 GEMM (256x128 tile, 512 thr, 16 warps) — big GEMMs ----------------
constexpr int P2 = 72;
constexpr int A_MAT2 = 256 * P2 * 2;                 // 36864
constexpr int B_MAT2 = 128 * P2 * 2;                 // 18432
constexpr int STAGE2 = 2 * A_MAT2 + 2 * B_MAT2;      // 110592
constexpr int GEMM2_SMEM = 2 * STAGE2;               // 221184
// stage offsets: Ahi=0, Alo=A_MAT2, Bhi=2*A_MAT2, Blo=2*A_MAT2+B_MAT2

template<bool BIAS, bool RELU, bool SPLIT>
__global__ __launch_bounds__(512) void mma_gemm2(
    const __nv_bfloat16* __restrict__ Ahi, const __nv_bfloat16* __restrict__ Alo,
    const __nv_bfloat16* __restrict__ Bhi, const __nv_bfloat16* __restrict__ Blo,
    const float* __restrict__ bias,
    float* __restrict__ C,
    __nv_bfloat16* __restrict__ Chi, __nv_bfloat16* __restrict__ Clo,
    int N, int K, int ntn, int ntiles)
{
    extern __shared__ char sm[];
    const int tid  = threadIdx.x;
    const int lane = tid & 31, wid = tid >> 5;   // 16 warps
    const int wm = wid >> 1, wn = wid & 1;       // 8 x 2
    const uint32_t smb = smem_u32(sm);
    const int NC = K >> 6;

    const int rA = lane & 15, cA = lane >> 4;
    uint32_t offA[2];
    #pragma unroll
    for (int i = 0; i < 2; i++)
        offA[i] = (uint32_t)(((wm * 32 + i * 16 + rA) * P2 + cA * 8) * 2);
    const int rB = (lane & 7) | ((lane >> 4) << 3), cB = (lane >> 3) & 1;
    uint32_t offB[4];
    #pragma unroll
    for (int j = 0; j < 4; j++)
        offB[j] = (uint32_t)(((wn * 64 + j * 16 + rB) * P2 + cB * 8) * 2);

    const int g2 = lane >> 2, t2 = lane & 3;

    for (int t = blockIdx.x; t < ntiles; t += gridDim.x) {
        const int bm0 = (t / ntn) * 256;
        const int bn0 = (t % ntn) * 128;

        float acc[2][8][4];
        #pragma unroll
        for (int i = 0; i < 2; i++)
            #pragma unroll
            for (int j = 0; j < 8; j++)
                #pragma unroll
                for (int q = 0; q < 4; q++) acc[i][j][q] = 0.f;

        auto issue = [&](int c) {
            const int k0 = c << 6;
            const uint32_t st = smb + (c & 1) * STAGE2;
            #pragma unroll
            for (int it = 0; it < 4; it++) {          // A: 2048 segs / 512 thr
                const int idx = tid + it * 512;
                const int row = idx >> 3, seg = idx & 7;
                const uint32_t so = (uint32_t)(row * P2 * 2 + seg * 16);
                const size_t ga = (size_t)(bm0 + row) * K + k0 + seg * 8;
                cp16(st + so,          Ahi + ga);
                cp16(st + A_MAT2 + so, Alo + ga);
            }
            #pragma unroll
            for (int it = 0; it < 2; it++) {          // B: 1024 segs / 512 thr
                const int idx = tid + it * 512;
                const int row = idx >> 3, seg = idx & 7;
                const uint32_t so = (uint32_t)(row * P2 * 2 + seg * 16);
                const size_t gb = (size_t)(bn0 + row) * K + k0 + seg * 8;
                cp16(st + 2 * A_MAT2 + so,          Bhi + gb);
                cp16(st + 2 * A_MAT2 + B_MAT2 + so, Blo + gb);
            }
            cp_commit();
        };

        issue(0);

        for (int c = 0; c < NC; c++) {
            if (c + 1 < NC) { issue(c + 1); cp_wait1(); }
            else cp_wait0();
            __syncthreads();

            const uint32_t st = smb + (c & 1) * STAGE2;
            #pragma unroll
            for (int ks = 0; ks < 4; ks++) {
                const uint32_t kadd = ks * 32;
                uint32_t ah[2][4], al[2][4];
                #pragma unroll
                for (int i = 0; i < 2; i++) {
                    ldm_x4(ah[i], st + offA[i] + kadd);
                    ldm_x4(al[i], st + A_MAT2 + offA[i] + kadd);
                }
                #pragma unroll
                for (int j4 = 0; j4 < 4; j4++) {
                    uint32_t bh[4], bl[4];
                    ldm_x4(bh, st + 2 * A_MAT2 + offB[j4] + kadd);
                    ldm_x4(bl, st + 2 * A_MAT2 + B_MAT2 + offB[j4] + kadd);
                    #pragma unroll
                    for (int i = 0; i < 2; i++)
                        #pragma unroll
                        for (int jj = 0; jj < 2; jj++) {
                            const int j = j4 * 2 + jj, hh = jj * 2;
                            mma16816(acc[i][j], ah[i], &bh[hh]);
                            mma16816(acc[i][j], ah[i], &bl[hh]);
                            mma16816(acc[i][j], al[i], &bh[hh]);
                        }
                }
            }
            __syncthreads();   // stage c fully consumed before issue(c+2) overwrites it
        }

        #pragma unroll
        for (int i = 0; i < 2; i++) {
            #pragma unroll
            for (int j = 0; j < 8; j++) {
                const int row0 = bm0 + wm * 32 + i * 16 + g2;
                const int col  = bn0 + wn * 64 + j * 8 + t2 * 2;
                #pragma unroll
                for (int half = 0; half < 2; half++) {
                    const int row = row0 + half * 8;
                    float vx = acc[i][j][half * 2 + 0];
                    float vy = acc[i][j][half * 2 + 1];
                    if (BIAS) { vx += bias[col]; vy += bias[col + 1]; }
                    if (RELU) { vx = fmaxf(vx, 0.f); vy = fmaxf(vy, 0.f); }
                    if (SPLIT) {
                        float hx = __bfloat162float(__float2bfloat16_rn(vx));
                        float hy = __bfloat162float(__float2bfloat16_rn(vy));
                        *reinterpret_cast<uint32_t*>(Chi + (size_t)row * N + col) = pack_bf16(vx, vy);
                        *reinterpret_cast<uint32_t*>(Clo + (size_t)row * N + col) = pack_bf16(vx - hx, vy - hy);
                    } else {
                        float2 v; v.x = vx; v.y = vy;
                        *reinterpret_cast<float2*>(C + (size_t)row * N + col) = v;
                    }
                }
            }
        }
    }
}

// ---------------- tensor-core flash attention (bf16x3, causal), packed QKV ----------------
constexpr int AP = 72;
constexpr int AQ_HI = 0;
constexpr int AQ_LO = 128 * AP;
constexpr int AST0  = 2 * 128 * AP;
constexpr int AMAT  = 64 * AP;
constexpr int ASTAGE = 4 * AMAT;
constexpr int ATTN_SMEM = (AST0 + 2 * ASTAGE) * 2;   // 110,592 bytes

__global__ __launch_bounds__(128) void attn_tc_kernel(
    const __nv_bfloat16* __restrict__ QKVh, const __nv_bfloat16* __restrict__ QKVl,
    __nv_bfloat16* __restrict__ Ohi, __nv_bfloat16* __restrict__ Olo)
{
    extern __shared__ __nv_bfloat16 smb16[];
    const uint32_t smb = smem_u32(smb16);

    const int qt = gridDim.x - 1 - blockIdx.x;
    const int bh = blockIdx.y;
    const int b  = bh >> 4;
    const int h  = bh & 15;
    const int tid = threadIdx.x;
    const int lane = tid & 31, wid = tid >> 5;
    const int g2 = lane >> 2, t2 = lane & 3;

    const size_t rowbase = (size_t)(b * SEQ + qt * 128);
    const int hoff = h * 64;

    #pragma unroll
    for (int it = 0; it < 8; it++) {
        int idx = tid + it * 128;
        int row = idx >> 3, c8 = (idx & 7) * 8;
        const size_t gq = (rowbase + row) * QKV + hoff + c8;
        *reinterpret_cast<uint4*>(smb16 + AQ_HI + row * AP + c8) =
            *reinterpret_cast<const uint4*>(QKVh + gq);
        *reinterpret_cast<uint4*>(smb16 + AQ_LO + row * AP + c8) =
            *reinterpret_cast<const uint4*>(QKVl + gq);
    }

    auto issue_kv = [&](int jt) {
        const uint32_t st = smb + (AST0 + (jt & 1) * ASTAGE) * 2;
        const size_t kb = (size_t)(b * SEQ + jt * 64);
        #pragma unroll
        for (int it = 0; it < 4; it++) {
            int idx = tid + it * 128;
            int row = idx >> 3, c8 = (idx & 7) * 8;
            const size_t g = (kb + row) * QKV + hoff + c8;
            const uint32_t so = (uint32_t)((row * AP + c8) * 2);
            cp16(st + so,            QKVh + g + EMB);
            cp16(st + AMAT * 2 + so, QKVl + g + EMB);
            cp16(st + AMAT * 4 + so, QKVh + g + 2 * EMB);
            cp16(st + AMAT * 6 + so, QKVl + g + 2 * EMB);
        }
        cp_commit();
    };

    const int rA = lane & 15, cA = lane >> 4;
    uint32_t qoff[2];
    #pragma unroll
    for (int i = 0; i < 2; i++)
        qoff[i] = (uint32_t)(((wid * 32 + i * 16 + rA) * AP + cA * 8) * 2);
    const int rB = (lane & 7) | ((lane >> 4) << 3), cB = (lane >> 3) & 1;
    uint32_t koff[4];
    #pragma unroll
    for (int j = 0; j < 4; j++)
        koff[j] = (uint32_t)(((j * 16 + rB) * AP + cB * 8) * 2);
    const uint32_t voff_row = (uint32_t)(rA * AP + cA * 8) * 2;

    float oacc[2][8][4];
    float mstat[4], lstat[4];
    #pragma unroll
    for (int i = 0; i < 2; i++)
        #pragma unroll
        for (int j = 0; j < 8; j++)
            #pragma unroll
            for (int q = 0; q < 4; q++) oacc[i][j][q] = 0.f;
    #pragma unroll
    for (int t = 0; t < 4; t++) { mstat[t] = -1e30f; lstat[t] = 0.f; }

    const int NT = 2 * qt + 2;
    issue_kv(0);

    for (int jt = 0; jt < NT; jt++) {
        if (jt + 1 < NT) { issue_kv(jt + 1); cp_wait1(); }
        else cp_wait0();
        __syncthreads();

        const uint32_t st = smb + (AST0 + (jt & 1) * ASTAGE) * 2;

        float sacc[2][8][4];
        #pragma unroll
        for (int i = 0; i < 2; i++)
            #pragma unroll
            for (int j = 0; j < 8; j++)
                #pragma unroll
                for (int q = 0; q < 4; q++) sacc[i][j][q] = 0.f;

        #pragma unroll
        for (int ks = 0; ks < 4; ks++) {
            const uint32_t kadd = ks * 32;
            uint32_t qh[2][4], ql[2][4], kh[4][4], kl[4][4];
            #pragma unroll
            for (int i = 0; i < 2; i++) {
                ldm_x4(qh[i], smb + AQ_HI * 2 + qoff[i] + kadd);
                ldm_x4(ql[i], smb + AQ_LO * 2 + qoff[i] + kadd);
            }
            #pragma unroll
            for (int j = 0; j < 4; j++) {
                ldm_x4(kh[j], st + koff[j] + kadd);
                ldm_x4(kl[j], st + AMAT * 2 + koff[j] + kadd);
            }
            #pragma unroll
            for (int i = 0; i < 2; i++)
                #pragma unroll
                for (int j = 0; j < 8; j++) {
                    const int j4 = j >> 1, hh = (j & 1) * 2;
                    mma16816(sacc[i][j], qh[i], &kh[j4][hh]);
                    mma16816(sacc[i][j], qh[i], &kl[j4][hh]);
                    mma16816(sacc[i][j], ql[i], &kh[j4][hh]);
                }
        }

        const bool need_mask = (jt * 64 + 63) > (qt * 128);
        #pragma unroll
        for (int i = 0; i < 2; i++) {
            #pragma unroll
            for (int j = 0; j < 8; j++) {
                #pragma unroll
                for (int q = 0; q < 4; q++) {
                    float s = sacc[i][j][q] * 0.125f;
                    if (need_mask) {
                        const int row = qt * 128 + wid * 32 + i * 16 + g2 + (q >> 1) * 8;
                        const int col = jt * 64 + j * 8 + t2 * 2 + (q & 1);
                        if (col > row) s = -1e30f;
                    }
                    sacc[i][j][q] = s;
                }
            }
        }

        float alpha[4];
        #pragma unroll
        for (int i = 0; i < 2; i++) {
            #pragma unroll
            for (int half = 0; half < 2; half++) {
                const int t = i * 2 + half;
                float mx = -1e30f;
                #pragma unroll
                for (int j = 0; j < 8; j++)
                    mx = fmaxf(mx, fmaxf(sacc[i][j][half * 2], sacc[i][j][half * 2 + 1]));
                mx = fmaxf(mx, __shfl_xor_sync(0xffffffffu, mx, 1));
                mx = fmaxf(mx, __shfl_xor_sync(0xffffffffu, mx, 2));
                const float mnew = fmaxf(mstat[t], mx);
                alpha[t] = exp2f((mstat[t] - mnew) * 1.4426950408889634f);
                mstat[t] = mnew;
                float rs = 0.f;
                #pragma unroll
                for (int j = 0; j < 8; j++) {
                    float p0 = exp2f((sacc[i][j][half * 2]     - mnew) * 1.4426950408889634f);
                    float p1 = exp2f((sacc[i][j][half * 2 + 1] - mnew) * 1.4426950408889634f);
                    sacc[i][j][half * 2] = p0;
                    sacc[i][j][half * 2 + 1] = p1;
                    rs += p0 + p1;
                }
                rs += __shfl_xor_sync(0xffffffffu, rs, 1);
                rs += __shfl_xor_sync(0xffffffffu, rs, 2);
                lstat[t] = lstat[t] * alpha[t] + rs;
                #pragma unroll
                for (int j = 0; j < 8; j++) {
                    oacc[i][j][half * 2]     *= alpha[t];
                    oacc[i][j][half * 2 + 1] *= alpha[t];
                }
            }
        }

        #pragma unroll
        for (int kk = 0; kk < 4; kk++) {
            uint32_t ph[2][4], pl[2][4];
            #pragma unroll
            for (int i = 0; i < 2; i++) {
                const int j0 = 2 * kk, j1 = j0 + 1;
                const float c0 = sacc[i][j0][0], c1 = sacc[i][j0][1];
                const float c2 = sacc[i][j0][2], c3 = sacc[i][j0][3];
                const float d0 = sacc[i][j1][0], d1 = sacc[i][j1][1];
                const float d2 = sacc[i][j1][2], d3 = sacc[i][j1][3];
                ph[i][0] = pack_bf16(c0, c1);
                ph[i][1] = pack_bf16(c2, c3);
                ph[i][2] = pack_bf16(d0, d1);
                ph[i][3] = pack_bf16(d2, d3);
                const float h0 = __bfloat162float(__float2bfloat16_rn(c0));
                const float h1 = __bfloat162float(__float2bfloat16_rn(c1));
                const float h2 = __bfloat162float(__float2bfloat16_rn(c2));
                const float h3 = __bfloat162float(__float2bfloat16_rn(c3));
                const float e0 = __bfloat162float(__float2bfloat16_rn(d0));
                const float e1 = __bfloat162float(__float2bfloat16_rn(d1));
                const float e2 = __bfloat162float(__float2bfloat16_rn(d2));
                const float e3 = __bfloat162float(__float2bfloat16_rn(d3));
                pl[i][0] = pack_bf16(c0 - h0, c1 - h1);
                pl[i][1] = pack_bf16(c2 - h2, c3 - h3);
                pl[i][2] = pack_bf16(d0 - e0, d1 - e1);
                pl[i][3] = pack_bf16(d2 - e2, d3 - e3);
            }
            uint32_t vh[4][4], vl[4][4];
            const uint32_t vrow = (uint32_t)((kk * 16) * AP * 2);
            #pragma unroll
            for (int dgrp = 0; dgrp < 4; dgrp++) {
                const uint32_t va = st + AMAT * 4 + vrow + voff_row + (uint32_t)(dgrp * 16 * 2);
                ldm_x4t(vh[dgrp], va);
                ldm_x4t(vl[dgrp], va + AMAT * 2);
            }
            #pragma unroll
            for (int i = 0; i < 2; i++)
                #pragma unroll
                for (int jd = 0; jd < 8; jd++) {
                    const int vg = jd >> 1, sel = (jd & 1) * 2;
                    mma16816(oacc[i][jd], ph[i], &vh[vg][sel]);
                    mma16816(oacc[i][jd], ph[i], &vl[vg][sel]);
                    mma16816(oacc[i][jd], pl[i], &vh[vg][sel]);
                }
        }
        __syncthreads();
    }

    #pragma unroll
    for (int i = 0; i < 2; i++) {
        #pragma unroll
        for (int half = 0; half < 2; half++) {
            const int t = i * 2 + half;
            const float inv = 1.f / lstat[t];
            const size_t row = rowbase + wid * 32 + i * 16 + g2 + half * 8;
            #pragma unroll
            for (int jd = 0; jd < 8; jd++) {
                const int col = hoff + jd * 8 + t2 * 2;
                const float vx = oacc[i][jd][half * 2]     * inv;
                const float vy = oacc[i][jd][half * 2 + 1] * inv;
                const float hx = __bfloat162float(__float2bfloat16_rn(vx));
                const float hy = __bfloat162float(__float2bfloat16_rn(vy));
                *reinterpret_cast<uint32_t*>(Ohi + row * EMB + col) = pack_bf16(vx, vy);
                *reinterpret_cast<uint32_t*>(Olo + row * EMB + col) = pack_bf16(vx - hx, vy - hy);
            }
        }
    }
}

// ---------------- host orchestration ----------------
static inline int gclamp(int ntiles) { return ntiles < 148 ? ntiles : 148; }

extern "C" void kernel_launch(void* const* d_in, const int* in_sizes, int n_in,
                              void* d_out, int out_size)
{
    const int*   idx  = (const int*)  d_in[0];
    const float* tok  = (const float*)d_in[1];
    const float* pos  = (const float*)d_in[2];
    const float* Wq   = (const float*)d_in[3];
    const float* Wk   = (const float*)d_in[4];
    const float* Wv   = (const float*)d_in[5];
    const float* Wo   = (const float*)d_in[6];
    const float* bo   = (const float*)d_in[7];
    const float* W1   = (const float*)d_in[8];
    const float* b1   = (const float*)d_in[9];
    const float* W2   = (const float*)d_in[10];
    const float* b2   = (const float*)d_in[11];
    const float* ln1g = (const float*)d_in[12];
    const float* ln1b = (const float*)d_in[13];
    const float* ln2g = (const float*)d_in[14];
    const float* ln2b = (const float*)d_in[15];
    const float* lnfg = (const float*)d_in[16];
    const float* lnfb = (const float*)d_in[17];
    const float* lmb  = (const float*)d_in[18];
    float* out = (float*)d_out;

    float* x;
    __nv_bfloat16 *whi, *wlo, *tokhi, *toklo;
    __nv_bfloat16 *ahi, *alo, *qkvh, *qkvl, *ohi, *olo, *fhi, *flo;
    cudaGetSymbolAddress((void**)&x,  g_x);
    cudaGetSymbolAddress((void**)&whi, g_Whi);
    cudaGetSymbolAddress((void**)&wlo, g_Wlo);
    cudaGetSymbolAddress((void**)&tokhi, g_tokhi);
    cudaGetSymbolAddress((void**)&toklo, g_toklo);
    cudaGetSymbolAddress((void**)&ahi, g_ahi);
    cudaGetSymbolAddress((void**)&alo, g_alo);
    cudaGetSymbolAddress((void**)&qkvh, g_qkvh);
    cudaGetSymbolAddress((void**)&qkvl, g_qkvl);
    cudaGetSymbolAddress((void**)&ohi, g_ohi);
    cudaGetSymbolAddress((void**)&olo, g_olo);
    cudaGetSymbolAddress((void**)&fhi, g_fhi);
    cudaGetSymbolAddress((void**)&flo, g_flo);

    cudaFuncSetAttribute(attn_tc_kernel, cudaFuncAttributeMaxDynamicSharedMemorySize, ATTN_SMEM);
    cudaFuncSetAttribute(mma_gemm<true,false,true,false>,  cudaFuncAttributeMaxDynamicSharedMemorySize, GEMM_SMEM);
    cudaFuncSetAttribute(mma_gemm2<false,false,true>, cudaFuncAttributeMaxDynamicSharedMemorySize, GEMM2_SMEM);
    cudaFuncSetAttribute(mma_gemm2<true,true,true>,   cudaFuncAttributeMaxDynamicSharedMemorySize, GEMM2_SMEM);
    cudaFuncSetAttribute(mma_gemm2<true,false,false>, cudaFuncAttributeMaxDynamicSharedMemorySize, GEMM2_SMEM);

    // [0] merged weight + tok conversion
    conv_all_kernel<<<CONV_BLKS, 256>>>(Wq, Wk, Wv, Wo, W1, W2, tok,
                                        whi, wlo, tokhi, toklo);
    // [1] embedding
    embed_kernel<<<(MROWS * EMB) / 256, 256>>>(x, idx, tok, pos);

    const int ntQKV2 = (MROWS / 256) * (QKV / 128);    // 192
    const int ntE    = (MROWS / 128) * (EMB / 128);    // 128
    const int ntF2   = (MROWS / 256) * (DFF / 128);    // 256
    const int ntV2   = (MROWS / 256) * (VOC / 128);    // 2000
    const dim3 gattn(SEQ / 128, BSZ * NH);

    for (int l = 0; l < LAY; l++) {
        const size_t wb = (size_t)l * WPL;
        ln_split_kernel<<<MROWS / 8, 256>>>(ahi, alo, x, ln1g + (size_t)l * EMB, ln1b + (size_t)l * EMB);
        mma_gemm2<false,false,true><<<gclamp(ntQKV2), 512, GEMM2_SMEM>>>(
            ahi, alo, whi + wb + OFF_WQ, wlo + wb + OFF_WQ, nullptr, nullptr,
            qkvh, qkvl, QKV, EMB, QKV / 128, ntQKV2);
        attn_tc_kernel<<<gattn, 128, ATTN_SMEM>>>(qkvh, qkvl, ohi, olo);
        mma_gemm<true,false,true,false><<<gclamp(ntE), 256, GEMM_SMEM>>>(
            ohi, olo, whi + wb + OFF_WO, wlo + wb + OFF_WO, bo + (size_t)l * EMB, x, x,
            nullptr, nullptr, EMB, EMB, EMB / 128, ntE);
        ln_split_kernel<<<MROWS / 8, 256>>>(ahi, alo, x, ln2g + (size_t)l * EMB, ln2b + (size_t)l * EMB);
        mma_gemm2<true,true,true><<<gclamp(ntF2), 512, GEMM2_SMEM>>>(
            ahi, alo, whi + wb + OFF_W1, wlo + wb + OFF_W1, b1 + (size_t)l * DFF,
            nullptr, fhi, flo, DFF, EMB, DFF / 128, ntF2);
        mma_gemm<true,false,true,false><<<gclamp(ntE), 256, GEMM_SMEM>>>(
            fhi, flo, whi + wb + OFF_W2, wlo + wb + OFF_W2, b2 + (size_t)l * EMB, x, x,
            nullptr, nullptr, EMB, DFF, EMB / 128, ntE);
    }

    ln_split_kernel<<<MROWS / 8, 256>>>(ahi, alo, x, lnfg, lnfb);
    mma_gemm2<true,false,false><<<gclamp(ntV2), 512, GEMM2_SMEM>>>(
        ahi, alo, tokhi, toklo, lmb, out,
        nullptr, nullptr, VOC, EMB, VOC / 128, ntV2);
}

// round 11
// speedup vs baseline: 3.1613x; 1.0243x over previous
#include <cuda_runtime.h>
#include <cuda_bf16.h>
#include <cstdint>
#include <math.h>

// ---------------- problem constants ----------------
constexpr int LAY = 8;
constexpr int NH  = 16;
constexpr int EMB = 1024;
constexpr int VOC = 32000;
constexpr int SEQ = 1024;
constexpr int BSZ = 2;
constexpr int DFF = 4096;
constexpr int MROWS = BSZ * SEQ;   // 2048
constexpr int QKV = 3 * EMB;       // 3072

// ---------------- scratch (device globals; no cudaMalloc allowed) ----------------
__device__ float g_x [MROWS * EMB];

constexpr size_t WPL = 4ull * EMB * EMB + 2ull * EMB * DFF;
__device__ __align__(16) __nv_bfloat16 g_Whi[LAY * WPL];
__device__ __align__(16) __nv_bfloat16 g_Wlo[LAY * WPL];
__device__ __align__(16) __nv_bfloat16 g_tokhi[(size_t)VOC * EMB];
__device__ __align__(16) __nv_bfloat16 g_toklo[(size_t)VOC * EMB];

__device__ __align__(16) __nv_bfloat16 g_ahi[MROWS * EMB];
__device__ __align__(16) __nv_bfloat16 g_alo[MROWS * EMB];
__device__ __align__(16) __nv_bfloat16 g_qkvh[MROWS * QKV];
__device__ __align__(16) __nv_bfloat16 g_qkvl[MROWS * QKV];
__device__ __align__(16) __nv_bfloat16 g_ohi[MROWS * EMB];
__device__ __align__(16) __nv_bfloat16 g_olo[MROWS * EMB];
__device__ __align__(16) __nv_bfloat16 g_fhi[MROWS * DFF];
__device__ __align__(16) __nv_bfloat16 g_flo[MROWS * DFF];

// per-layer weight offsets inside WPL block (transposed to [N,K]); WQ/WK/WV contiguous
constexpr size_t OFF_WQ = 0;
constexpr size_t OFF_WO = 3ull << 20;
constexpr size_t OFF_W1 = 4ull << 20;
constexpr size_t OFF_W2 = 8ull << 20;

// ---------------- low-level helpers ----------------
__device__ __forceinline__ uint32_t smem_u32(const void* p) {
    uint32_t a;
    asm("{ .reg .u64 t; cvta.to.shared.u64 t, %1; cvt.u32.u64 %0, t; }" : "=r"(a) : "l"(p));
    return a;
}
__device__ __forceinline__ void cp16(uint32_t s, const void* g) {
    asm volatile("cp.async.cg.shared.global [%0], [%1], 16;" :: "r"(s), "l"(g) : "memory");
}
__device__ __forceinline__ void cp_commit() {
    asm volatile("cp.async.commit_group;" ::: "memory");
}
__device__ __forceinline__ void cp_wait1() {
    asm volatile("cp.async.wait_group 1;" ::: "memory");
}
__device__ __forceinline__ void cp_wait0() {
    asm volatile("cp.async.wait_group 0;" ::: "memory");
}
__device__ __forceinline__ void ldm_x4(uint32_t* r, uint32_t a) {
    asm volatile("ldmatrix.sync.aligned.m8n8.x4.shared.b16 {%0,%1,%2,%3}, [%4];"
                 : "=r"(r[0]), "=r"(r[1]), "=r"(r[2]), "=r"(r[3]) : "r"(a));
}
__device__ __forceinline__ void ldm_x4t(uint32_t* r, uint32_t a) {
    asm volatile("ldmatrix.sync.aligned.m8n8.x4.trans.shared.b16 {%0,%1,%2,%3}, [%4];"
                 : "=r"(r[0]), "=r"(r[1]), "=r"(r[2]), "=r"(r[3]) : "r"(a));
}
__device__ __forceinline__ void mma16816(float* d, const uint32_t* a, const uint32_t* b) {
    asm volatile(
        "mma.sync.aligned.m16n8k16.row.col.f32.bf16.bf16.f32 "
        "{%0,%1,%2,%3}, {%4,%5,%6,%7}, {%8,%9}, {%0,%1,%2,%3};"
        : "+f"(d[0]), "+f"(d[1]), "+f"(d[2]), "+f"(d[3])
        : "r"(a[0]), "r"(a[1]), "r"(a[2]), "r"(a[3]), "r"(b[0]), "r"(b[1]));
}
__device__ __forceinline__ uint32_t pack_bf16(float x, float y) {
    __nv_bfloat162 t = __floats2bfloat162_rn(x, y);
    return *reinterpret_cast<uint32_t*>(&t);
}

// ---------------- merged weight conversion (single launch) ----------------
constexpr int CONV_WBLKS = LAY * 6144;
constexpr int CONV_TOKBLKS = (VOC * EMB) / 2048;
constexpr int CONV_BLKS = CONV_WBLKS + CONV_TOKBLKS;

__global__ __launch_bounds__(256) void conv_all_kernel(
    const float* __restrict__ Wq, const float* __restrict__ Wk,
    const float* __restrict__ Wv, const float* __restrict__ Wo,
    const float* __restrict__ W1, const float* __restrict__ W2,
    const float* __restrict__ tok,
    __nv_bfloat16* __restrict__ whi, __nv_bfloat16* __restrict__ wlo,
    __nv_bfloat16* __restrict__ tokhi, __nv_bfloat16* __restrict__ toklo)
{
    const int blk = blockIdx.x;
    const int tid = threadIdx.x;
    if (blk < CONV_WBLKS) {
        const int l = blk / 6144;
        int r = blk % 6144;
        const float* src;
        size_t dst;
        int K, N;
        if (r < 2048) {
            const int m = r >> 9;
            r &= 511;
            src = (m == 0 ? Wq : m == 1 ? Wk : m == 2 ? Wv : Wo) + (size_t)l * EMB * EMB;
            dst = (size_t)l * WPL + (m < 3 ? ((size_t)m << 20) : OFF_WO);
            K = EMB; N = EMB;
        } else if (r < 4096) {
            r -= 2048;
            src = W1 + (size_t)l * EMB * DFF;
            dst = (size_t)l * WPL + OFF_W1;
            K = EMB; N = DFF;
        } else {
            r -= 4096;
            src = W2 + (size_t)l * DFF * EMB;
            dst = (size_t)l * WPL + OFF_W2;
            K = DFF; N = EMB;
        }
        const int ntk = K >> 5;
        const int n0 = (r / ntk) * 64;
        const int k0 = (r % ntk) * 32;
        const int lane = tid & 31, w = tid >> 5;
        const int n  = n0 + w * 8 + (lane >> 2);
        const int kg = k0 + (lane & 3) * 8;

        float v[8];
        #pragma unroll
        for (int i = 0; i < 8; i++)
            v[i] = src[(size_t)(kg + i) * N + n];
        uint32_t hp[4], lp[4];
        #pragma unroll
        for (int i = 0; i < 4; i++) {
            const float a = v[2 * i], b = v[2 * i + 1];
            const float ha = __bfloat162float(__float2bfloat16_rn(a));
            const float hb = __bfloat162float(__float2bfloat16_rn(b));
            hp[i] = pack_bf16(a, b);
            lp[i] = pack_bf16(a - ha, b - hb);
        }
        const size_t o = dst + (size_t)n * K + kg;
        *reinterpret_cast<uint4*>(whi + o) = *reinterpret_cast<uint4*>(hp);
        *reinterpret_cast<uint4*>(wlo + o) = *reinterpret_cast<uint4*>(lp);
    } else {
        const size_t base = (size_t)(blk - CONV_WBLKS) * 2048 + (size_t)tid * 8;
        const float4 a = *reinterpret_cast<const float4*>(tok + base);
        const float4 b = *reinterpret_cast<const float4*>(tok + base + 4);
        uint32_t hp[4], lp[4];
        const float h0 = __bfloat162float(__float2bfloat16_rn(a.x));
        const float h1 = __bfloat162float(__float2bfloat16_rn(a.y));
        const float h2 = __bfloat162float(__float2bfloat16_rn(a.z));
        const float h3 = __bfloat162float(__float2bfloat16_rn(a.w));
        const float h4 = __bfloat162float(__float2bfloat16_rn(b.x));
        const float h5 = __bfloat162float(__float2bfloat16_rn(b.y));
        const float h6 = __bfloat162float(__float2bfloat16_rn(b.z));
        const float h7 = __bfloat162float(__float2bfloat16_rn(b.w));
        hp[0] = pack_bf16(a.x, a.y);  hp[1] = pack_bf16(a.z, a.w);
        hp[2] = pack_bf16(b.x, b.y);  hp[3] = pack_bf16(b.z, b.w);
        lp[0] = pack_bf16(a.x - h0, a.y - h1);
        lp[1] = pack_bf16(a.z - h2, a.w - h3);
        lp[2] = pack_bf16(b.x - h4, b.y - h5);
        lp[3] = pack_bf16(b.z - h6, b.w - h7);
        *reinterpret_cast<uint4*>(tokhi + base) = *reinterpret_cast<uint4*>(hp);
        *reinterpret_cast<uint4*>(toklo + base) = *reinterpret_cast<uint4*>(lp);
    }
}

// ---------------- embedding ----------------
__global__ void embed_kernel(float* __restrict__ x, const int* __restrict__ idx,
                             const float* __restrict__ tok, const float* __restrict__ pos)
{
    int i = blockIdx.x * blockDim.x + threadIdx.x;
    int e  = i & (EMB - 1);
    int bt = i >> 10;
    int t  = bt & (SEQ - 1);
    x[i] = tok[(size_t)idx[bt] * EMB + e] + pos[(size_t)t * EMB + e];
}

// ---------------- layernorm (warp-per-row) with fused bf16 split output ----------------
__global__ __launch_bounds__(256) void ln_split_kernel(
    __nv_bfloat16* __restrict__ ohi, __nv_bfloat16* __restrict__ olo,
    const float* __restrict__ in,
    const float* __restrict__ g, const float* __restrict__ b)
{
    const int row  = blockIdx.x * 8 + (threadIdx.x >> 5);
    const int lane = threadIdx.x & 31;
    const float* xr = in + (size_t)row * EMB;

    float4 v[8];
    float s = 0.f;
    #pragma unroll
    for (int i = 0; i < 8; i++) {
        v[i] = *reinterpret_cast<const float4*>(xr + i * 128 + lane * 4);
        s += v[i].x + v[i].y + v[i].z + v[i].w;
    }
    #pragma unroll
    for (int o = 16; o; o >>= 1) s += __shfl_xor_sync(0xffffffffu, s, o);
    const float m = s * (1.f / EMB);

    float ss = 0.f;
    #pragma unroll
    for (int i = 0; i < 8; i++) {
        const float dx = v[i].x - m, dy = v[i].y - m, dz = v[i].z - m, dw = v[i].w - m;
        ss += dx * dx + dy * dy + dz * dz + dw * dw;
    }
    #pragma unroll
    for (int o = 16; o; o >>= 1) ss += __shfl_xor_sync(0xffffffffu, ss, o);
    const float r = rsqrtf(ss * (1.f / EMB) + 1e-5f);

    #pragma unroll
    for (int i = 0; i < 8; i++) {
        const int c0 = i * 128 + lane * 4;
        const float4 g4 = *reinterpret_cast<const float4*>(g + c0);
        const float4 b4 = *reinterpret_cast<const float4*>(b + c0);
        const float ox = (v[i].x - m) * r * g4.x + b4.x;
        const float oy = (v[i].y - m) * r * g4.y + b4.y;
        const float oz = (v[i].z - m) * r * g4.z + b4.z;
        const float ow = (v[i].w - m) * r * g4.w + b4.w;
        const float hx = __bfloat162float(__float2bfloat16_rn(ox));
        const float hy = __bfloat162float(__float2bfloat16_rn(oy));
        const float hz = __bfloat162float(__float2bfloat16_rn(oz));
        const float hw = __bfloat162float(__float2bfloat16_rn(ow));
        uint32_t hp[2], lp[2];
        hp[0] = pack_bf16(ox, oy);  hp[1] = pack_bf16(oz, ow);
        lp[0] = pack_bf16(ox - hx, oy - hy);
        lp[1] = pack_bf16(oz - hz, ow - hw);
        *reinterpret_cast<uint2*>(ohi + (size_t)row * EMB + c0) = *reinterpret_cast<uint2*>(hp);
        *reinterpret_cast<uint2*>(olo + (size_t)row * EMB + c0) = *reinterpret_cast<uint2*>(lp);
    }
}

// ---------------- bf16x3 GEMM: 128x128 tile, BK=32, XOR-swizzled 64B rows ----------------
// 3 stages x 32KB = 96KB smem -> 2 CTAs/SM. 256 threads, __launch_bounds__(256,2).
// swizzle: 16B-chunk c of row r stored at r*64 + ((c ^ ((r>>1)&3)) * 16). k-step = offset^32.
constexpr int MAT3 = 128 * 64;          // 8192 bytes per matrix per stage
constexpr int STG3 = 4 * MAT3;          // 32768
constexpr int GEMM_SMEM = 3 * STG3;     // 98304

template<bool BIAS, bool RELU, bool RES, bool SPLIT>
__global__ __launch_bounds__(256, 2) void mma_gemm(
    const __nv_bfloat16* __restrict__ Ahi, const __nv_bfloat16* __restrict__ Alo,
    const __nv_bfloat16* __restrict__ Bhi, const __nv_bfloat16* __restrict__ Blo,
    const float* __restrict__ bias, const float* __restrict__ res,
    float* __restrict__ C,
    __nv_bfloat16* __restrict__ Chi, __nv_bfloat16* __restrict__ Clo,
    int N, int K, int ntn, int ntiles)
{
    extern __shared__ char sm[];
    const int tid  = threadIdx.x;
    const int lane = tid & 31, wid = tid >> 5;
    const int wm = wid >> 1, wn = wid & 1;       // 4 x 2 warp grid, warp tile 32x64
    const uint32_t smb = smem_u32(sm);
    const int NC = K >> 5;

    // ldmatrix offsets for ks=0 (XOR 32 gives ks=1)
    const int rA = lane & 15, cA = lane >> 4;
    uint32_t offA[2];
    #pragma unroll
    for (int i = 0; i < 2; i++) {
        const int row = wm * 32 + i * 16 + rA;
        offA[i] = (uint32_t)(row * 64 + ((cA ^ ((row >> 1) & 3)) * 16));
    }
    const int rB = (lane & 7) | ((lane >> 4) << 3), cB = (lane >> 3) & 1;
    uint32_t offB[4];
    #pragma unroll
    for (int j = 0; j < 4; j++) {
        const int row = wn * 64 + j * 16 + rB;
        offB[j] = (uint32_t)(row * 64 + ((cB ^ ((row >> 1) & 3)) * 16));
    }

    // loader per-thread positions (2 chunks per matrix)
    const int lrow0 = tid >> 2,           lc0 = tid & 3;
    const int lrow1 = (tid + 256) >> 2,   lc1 = (tid + 256) & 3;
    const uint32_t lso0 = (uint32_t)(lrow0 * 64 + ((lc0 ^ ((lrow0 >> 1) & 3)) * 16));
    const uint32_t lso1 = (uint32_t)(lrow1 * 64 + ((lc1 ^ ((lrow1 >> 1) & 3)) * 16));

    const int g2 = lane >> 2, t2 = lane & 3;

    for (int t = blockIdx.x; t < ntiles; t += gridDim.x) {
        const int bm0 = (t / ntn) * 128;
        const int bn0 = (t % ntn) * 128;

        float acc[2][8][4];
        #pragma unroll
        for (int i = 0; i < 2; i++)
            #pragma unroll
            for (int j = 0; j < 8; j++)
                #pragma unroll
                for (int q = 0; q < 4; q++) acc[i][j][q] = 0.f;

        auto issue = [&](int c) {
            const int k0 = c << 5;
            const uint32_t st = smb + (c % 3) * STG3;
            {
                const size_t ga = (size_t)(bm0 + lrow0) * K + k0 + lc0 * 8;
                const size_t gb = (size_t)(bn0 + lrow0) * K + k0 + lc0 * 8;
                cp16(st + lso0,            Ahi + ga);
                cp16(st + MAT3 + lso0,     Alo + ga);
                cp16(st + 2 * MAT3 + lso0, Bhi + gb);
                cp16(st + 3 * MAT3 + lso0, Blo + gb);
            }
            {
                const size_t ga = (size_t)(bm0 + lrow1) * K + k0 + lc1 * 8;
                const size_t gb = (size_t)(bn0 + lrow1) * K + k0 + lc1 * 8;
                cp16(st + lso1,            Ahi + ga);
                cp16(st + MAT3 + lso1,     Alo + ga);
                cp16(st + 2 * MAT3 + lso1, Bhi + gb);
                cp16(st + 3 * MAT3 + lso1, Blo + gb);
            }
            cp_commit();
        };

        issue(0);
        issue(1);

        for (int c = 0; c < NC; c++) {
            if (c + 2 < NC) cp_wait1(); else cp_wait0();
            __syncthreads();
            if (c + 2 < NC) issue(c + 2);

            const uint32_t st = smb + (c % 3) * STG3;
            #pragma unroll
            for (int ks = 0; ks < 2; ks++) {
                const uint32_t kx = ks * 32;
                uint32_t ah[2][4], al[2][4];
                #pragma unroll
                for (int i = 0; i < 2; i++) {
                    ldm_x4(ah[i], st + (offA[i] ^ kx));
                    ldm_x4(al[i], st + MAT3 + (offA[i] ^ kx));
                }
                #pragma unroll
                for (int j4 = 0; j4 < 4; j4++) {
                    uint32_t bh[4], bl[4];
                    ldm_x4(bh, st + 2 * MAT3 + (offB[j4] ^ kx));
                    ldm_x4(bl, st + 3 * MAT3 + (offB[j4] ^ kx));
                    #pragma unroll
                    for (int i = 0; i < 2; i++)
                        #pragma unroll
                        for (int jj = 0; jj < 2; jj++) {
                            const int j = j4 * 2 + jj, hh = jj * 2;
                            mma16816(acc[i][j], ah[i], &bh[hh]);
                            mma16816(acc[i][j], ah[i], &bl[hh]);
                            mma16816(acc[i][j], al[i], &bh[hh]);
                        }
                }
            }
        }

        #pragma unroll
        for (int i = 0; i < 2; i++) {
            #pragma unroll
            for (int j = 0; j < 8; j++) {
                const int row0 = bm0 + wm * 32 + i * 16 + g2;
                const int col  = bn0 + wn * 64 + j * 8 + t2 * 2;
                #pragma unroll
                for (int half = 0; half < 2; half++) {
                    const int row = row0 + half * 8;
                    float vx = acc[i][j][half * 2 + 0];
                    float vy = acc[i][j][half * 2 + 1];
                    if (BIAS) { vx += bias[col]; vy += bias[col + 1]; }
                    if (RES) {
                        const float2 rr = *reinterpret_cast<const float2*>(res + (size_t)row * N + col);
                        vx += rr.x; vy += rr.y;
                    }
                    if (RELU) { vx = fmaxf(vx, 0.f); vy = fmaxf(vy, 0.f); }
                    if (SPLIT) {
                        float hx = __bfloat162float(__float2bfloat16_rn(vx));
                        float hy = __bfloat162float(__float2bfloat16_rn(vy));
                        *reinterpret_cast<uint32_t*>(Chi + (size_t)row * N + col) = pack_bf16(vx, vy);
                        *reinterpret_cast<uint32_t*>(Clo + (size_t)row * N + col) = pack_bf16(vx - hx, vy - hy);
                    } else {
                        float2 v; v.x = vx; v.y = vy;
                        *reinterpret_cast<float2*>(C + (size_t)row * N + col) = v;
                    }
                }
            }
        }
        __syncthreads();   // protect smem before next tile's prologue
    }
}

// ---------------- tensor-core flash attention (bf16x3, causal), packed QKV ----------------
constexpr int AP = 72;
constexpr int AQ_HI = 0;
constexpr int AQ_LO = 128 * AP;
constexpr int AST0  = 2 * 128 * AP;
constexpr int AMAT  = 64 * AP;
constexpr int ASTAGE = 4 * AMAT;
constexpr int ATTN_SMEM = (AST0 + 2 * ASTAGE) * 2;   // 110,592 bytes

__global__ __launch_bounds__(128) void attn_tc_kernel(
    const __nv_bfloat16* __restrict__ QKVh, const __nv_bfloat16* __restrict__ QKVl,
    __nv_bfloat16* __restrict__ Ohi, __nv_bfloat16* __restrict__ Olo)
{
    extern __shared__ __nv_bfloat16 smb16[];
    const uint32_t smb = smem_u32(smb16);

    const int qt = gridDim.x - 1 - blockIdx.x;
    const int bh = blockIdx.y;
    const int b  = bh >> 4;
    const int h  = bh & 15;
    const int tid = threadIdx.x;
    const int lane = tid & 31, wid = tid >> 5;
    const int g2 = lane >> 2, t2 = lane & 3;

    const size_t rowbase = (size_t)(b * SEQ + qt * 128);
    const int hoff = h * 64;

    #pragma unroll
    for (int it = 0; it < 8; it++) {
        int idx = tid + it * 128;
        int row = idx >> 3, c8 = (idx & 7) * 8;
        const size_t gq = (rowbase + row) * QKV + hoff + c8;
        *reinterpret_cast<uint4*>(smb16 + AQ_HI + row * AP + c8) =
            *reinterpret_cast<const uint4*>(QKVh + gq);
        *reinterpret_cast<uint4*>(smb16 + AQ_LO + row * AP + c8) =
            *reinterpret_cast<const uint4*>(QKVl + gq);
    }

    auto issue_kv = [&](int jt) {
        const uint32_t st = smb + (AST0 + (jt & 1) * ASTAGE) * 2;
        const size_t kb = (size_t)(b * SEQ + jt * 64);
        #pragma unroll
        for (int it = 0; it < 4; it++) {
            int idx = tid + it * 128;
            int row = idx >> 3, c8 = (idx & 7) * 8;
            const size_t g = (kb + row) * QKV + hoff + c8;
            const uint32_t so = (uint32_t)((row * AP + c8) * 2);
            cp16(st + so,            QKVh + g + EMB);
            cp16(st + AMAT * 2 + so, QKVl + g + EMB);
            cp16(st + AMAT * 4 + so, QKVh + g + 2 * EMB);
            cp16(st + AMAT * 6 + so, QKVl + g + 2 * EMB);
        }
        cp_commit();
    };

    const int rA = lane & 15, cA = lane >> 4;
    uint32_t qoff[2];
    #pragma unroll
    for (int i = 0; i < 2; i++)
        qoff[i] = (uint32_t)(((wid * 32 + i * 16 + rA) * AP + cA * 8) * 2);
    const int rB = (lane & 7) | ((lane >> 4) << 3), cB = (lane >> 3) & 1;
    uint32_t koff[4];
    #pragma unroll
    for (int j = 0; j < 4; j++)
        koff[j] = (uint32_t)(((j * 16 + rB) * AP + cB * 8) * 2);
    const uint32_t voff_row = (uint32_t)(rA * AP + cA * 8) * 2;

    float oacc[2][8][4];
    float mstat[4], lstat[4];
    #pragma unroll
    for (int i = 0; i < 2; i++)
        #pragma unroll
        for (int j = 0; j < 8; j++)
            #pragma unroll
            for (int q = 0; q < 4; q++) oacc[i][j][q] = 0.f;
    #pragma unroll
    for (int t = 0; t < 4; t++) { mstat[t] = -1e30f; lstat[t] = 0.f; }

    const int NT = 2 * qt + 2;
    issue_kv(0);

    for (int jt = 0; jt < NT; jt++) {
        if (jt + 1 < NT) { issue_kv(jt + 1); cp_wait1(); }
        else cp_wait0();
        __syncthreads();

        const uint32_t st = smb + (AST0 + (jt & 1) * ASTAGE) * 2;

        float sacc[2][8][4];
        #pragma unroll
        for (int i = 0; i < 2; i++)
            #pragma unroll
            for (int j = 0; j < 8; j++)
                #pragma unroll
                for (int q = 0; q < 4; q++) sacc[i][j][q] = 0.f;

        #pragma unroll
        for (int ks = 0; ks < 4; ks++) {
            const uint32_t kadd = ks * 32;
            uint32_t qh[2][4], ql[2][4], kh[4][4], kl[4][4];
            #pragma unroll
            for (int i = 0; i < 2; i++) {
                ldm_x4(qh[i], smb + AQ_HI * 2 + qoff[i] + kadd);
                ldm_x4(ql[i], smb + AQ_LO * 2 + qoff[i] + kadd);
            }
            #pragma unroll
            for (int j = 0; j < 4; j++) {
                ldm_x4(kh[j], st + koff[j] + kadd);
                ldm_x4(kl[j], st + AMAT * 2 + koff[j] + kadd);
            }
            #pragma unroll
            for (int i = 0; i < 2; i++)
                #pragma unroll
                for (int j = 0; j < 8; j++) {
                    const int j4 = j >> 1, hh = (j & 1) * 2;
                    mma16816(sacc[i][j], qh[i], &kh[j4][hh]);
                    mma16816(sacc[i][j], qh[i], &kl[j4][hh]);
                    mma16816(sacc[i][j], ql[i], &kh[j4][hh]);
                }
        }

        const bool need_mask = (jt * 64 + 63) > (qt * 128);
        #pragma unroll
        for (int i = 0; i < 2; i++) {
            #pragma unroll
            for (int j = 0; j < 8; j++) {
                #pragma unroll
                for (int q = 0; q < 4; q++) {
                    float s = sacc[i][j][q] * 0.125f;
                    if (need_mask) {
                        const int row = qt * 128 + wid * 32 + i * 16 + g2 + (q >> 1) * 8;
                        const int col = jt * 64 + j * 8 + t2 * 2 + (q & 1);
                        if (col > row) s = -1e30f;
                    }
                    sacc[i][j][q] = s;
                }
            }
        }

        float alpha[4];
        #pragma unroll
        for (int i = 0; i < 2; i++) {
            #pragma unroll
            for (int half = 0; half < 2; half++) {
                const int t = i * 2 + half;
                float mx = -1e30f;
                #pragma unroll
                for (int j = 0; j < 8; j++)
                    mx = fmaxf(mx, fmaxf(sacc[i][j][half * 2], sacc[i][j][half * 2 + 1]));
                mx = fmaxf(mx, __shfl_xor_sync(0xffffffffu, mx, 1));
                mx = fmaxf(mx, __shfl_xor_sync(0xffffffffu, mx, 2));
                const float mnew = fmaxf(mstat[t], mx);
                alpha[t] = exp2f((mstat[t] - mnew) * 1.4426950408889634f);
                mstat[t] = mnew;
                float rs = 0.f;
                #pragma unroll
                for (int j = 0; j < 8; j++) {
                    float p0 = exp2f((sacc[i][j][half * 2]     - mnew) * 1.4426950408889634f);
                    float p1 = exp2f((sacc[i][j][half * 2 + 1] - mnew) * 1.4426950408889634f);
                    sacc[i][j][half * 2] = p0;
                    sacc[i][j][half * 2 + 1] = p1;
                    rs += p0 + p1;
                }
                rs += __shfl_xor_sync(0xffffffffu, rs, 1);
                rs += __shfl_xor_sync(0xffffffffu, rs, 2);
                lstat[t] = lstat[t] * alpha[t] + rs;
                #pragma unroll
                for (int j = 0; j < 8; j++) {
                    oacc[i][j][half * 2]     *= alpha[t];
                    oacc[i][j][half * 2 + 1] *= alpha[t];
                }
            }
        }

        #pragma unroll
        for (int kk = 0; kk < 4; kk++) {
            uint32_t ph[2][4], pl[2][4];
            #pragma unroll
            for (int i = 0; i < 2; i++) {
                const int j0 = 2 * kk, j1 = j0 + 1;
                const float c0 = sacc[i][j0][0], c1 = sacc[i][j0][1];
                const float c2 = sacc[i][j0][2], c3 = sacc[i][j0][3];
                const float d0 = sacc[i][j1][0], d1 = sacc[i][j1][1];
                const float d2 = sacc[i][j1][2], d3 = sacc[i][j1][3];
                ph[i][0] = pack_bf16(c0, c1);
                ph[i][1] = pack_bf16(c2, c3);
                ph[i][2] = pack_bf16(d0, d1);
                ph[i][3] = pack_bf16(d2, d3);
                const float h0 = __bfloat162float(__float2bfloat16_rn(c0));
                const float h1 = __bfloat162float(__float2bfloat16_rn(c1));
                const float h2 = __bfloat162float(__float2bfloat16_rn(c2));
                const float h3 = __bfloat162float(__float2bfloat16_rn(c3));
                const float e0 = __bfloat162float(__float2bfloat16_rn(d0));
                const float e1 = __bfloat162float(__float2bfloat16_rn(d1));
                const float e2 = __bfloat162float(__float2bfloat16_rn(d2));
                const float e3 = __bfloat162float(__float2bfloat16_rn(d3));
                pl[i][0] = pack_bf16(c0 - h0, c1 - h1);
                pl[i][1] = pack_bf16(c2 - h2, c3 - h3);
                pl[i][2] = pack_bf16(d0 - e0, d1 - e1);
                pl[i][3] = pack_bf16(d2 - e2, d3 - e3);
            }
            uint32_t vh[4][4], vl[4][4];
            const uint32_t vrow = (uint32_t)((kk * 16) * AP * 2);
            #pragma unroll
            for (int dgrp = 0; dgrp < 4; dgrp++) {
                const uint32_t va = st + AMAT * 4 + vrow + voff_row + (uint32_t)(dgrp * 16 * 2);
                ldm_x4t(vh[dgrp], va);
                ldm_x4t(vl[dgrp], va + AMAT * 2);
            }
            #pragma unroll
            for (int i = 0; i < 2; i++)
                #pragma unroll
                for (int jd = 0; jd < 8; jd++) {
                    const int vg = jd >> 1, sel = (jd & 1) * 2;
                    mma16816(oacc[i][jd], ph[i], &vh[vg][sel]);
                    mma16816(oacc[i][jd], ph[i], &vl[vg][sel]);
                    mma16816(oacc[i][jd], pl[i], &vh[vg][sel]);
                }
        }
        __syncthreads();
    }

    #pragma unroll
    for (int i = 0; i < 2; i++) {
        #pragma unroll
        for (int half = 0; half < 2; half++) {
            const int t = i * 2 + half;
            const float inv = 1.f / lstat[t];
            const size_t row = rowbase + wid * 32 + i * 16 + g2 + half * 8;
            #pragma unroll
            for (int jd = 0; jd < 8; jd++) {
                const int col = hoff + jd * 8 + t2 * 2;
                const float vx = oacc[i][jd][half * 2]     * inv;
                const float vy = oacc[i][jd][half * 2 + 1] * inv;
                const float hx = __bfloat162float(__float2bfloat16_rn(vx));
                const float hy = __bfloat162float(__float2bfloat16_rn(vy));
                *reinterpret_cast<uint32_t*>(Ohi + row * EMB + col) = pack_bf16(vx, vy);
                *reinterpret_cast<uint32_t*>(Olo + row * EMB + col) = pack_bf16(vx - hx, vy - hy);
            }
        }
    }
}

// ---------------- host orchestration ----------------
static inline int gclamp2(int ntiles) { return ntiles < 296 ? ntiles : 296; }

extern "C" void kernel_launch(void* const* d_in, const int* in_sizes, int n_in,
                              void* d_out, int out_size)
{
    const int*   idx  = (const int*)  d_in[0];
    const float* tok  = (const float*)d_in[1];
    const float* pos  = (const float*)d_in[2];
    const float* Wq   = (const float*)d_in[3];
    const float* Wk   = (const float*)d_in[4];
    const float* Wv   = (const float*)d_in[5];
    const float* Wo   = (const float*)d_in[6];
    const float* bo   = (const float*)d_in[7];
    const float* W1   = (const float*)d_in[8];
    const float* b1   = (const float*)d_in[9];
    const float* W2   = (const float*)d_in[10];
    const float* b2   = (const float*)d_in[11];
    const float* ln1g = (const float*)d_in[12];
    const float* ln1b = (const float*)d_in[13];
    const float* ln2g = (const float*)d_in[14];
    const float* ln2b = (const float*)d_in[15];
    const float* lnfg = (const float*)d_in[16];
    const float* lnfb = (const float*)d_in[17];
    const float* lmb  = (const float*)d_in[18];
    float* out = (float*)d_out;

    float* x;
    __nv_bfloat16 *whi, *wlo, *tokhi, *toklo;
    __nv_bfloat16 *ahi, *alo, *qkvh, *qkvl, *ohi, *olo, *fhi, *flo;
    cudaGetSymbolAddress((void**)&x,  g_x);
    cudaGetSymbolAddress((void**)&whi, g_Whi);
    cudaGetSymbolAddress((void**)&wlo, g_Wlo);
    cudaGetSymbolAddress((void**)&tokhi, g_tokhi);
    cudaGetSymbolAddress((void**)&toklo, g_toklo);
    cudaGetSymbolAddress((void**)&ahi, g_ahi);
    cudaGetSymbolAddress((void**)&alo, g_alo);
    cudaGetSymbolAddress((void**)&qkvh, g_qkvh);
    cudaGetSymbolAddress((void**)&qkvl, g_qkvl);
    cudaGetSymbolAddress((void**)&ohi, g_ohi);
    cudaGetSymbolAddress((void**)&olo, g_olo);
    cudaGetSymbolAddress((void**)&fhi, g_fhi);
    cudaGetSymbolAddress((void**)&flo, g_flo);

    cudaFuncSetAttribute(attn_tc_kernel, cudaFuncAttributeMaxDynamicSharedMemorySize, ATTN_SMEM);
    cudaFuncSetAttribute(mma_gemm<false,false,false,true>, cudaFuncAttributeMaxDynamicSharedMemorySize, GEMM_SMEM);
    cudaFuncSetAttribute(mma_gemm<true,false,true,false>,  cudaFuncAttributeMaxDynamicSharedMemorySize, GEMM_SMEM);
    cudaFuncSetAttribute(mma_gemm<true,true,false,true>,   cudaFuncAttributeMaxDynamicSharedMemorySize, GEMM_SMEM);
    cudaFuncSetAttribute(mma_gemm<true,false,false,false>, cudaFuncAttributeMaxDynamicSharedMemorySize, GEMM_SMEM);

    // [0] merged weight + tok conversion
    conv_all_kernel<<<CONV_BLKS, 256>>>(Wq, Wk, Wv, Wo, W1, W2, tok,
                                        whi, wlo, tokhi, toklo);
    // [1] embedding
    embed_kernel<<<(MROWS * EMB) / 256, 256>>>(x, idx, tok, pos);

    const int ntQKV = (MROWS / 128) * (QKV / 128);     // 384
    const int ntE   = (MROWS / 128) * (EMB / 128);     // 128
    const int ntF   = (MROWS / 128) * (DFF / 128);     // 512
    const int ntV   = (MROWS / 128) * (VOC / 128);     // 4000
    const dim3 gattn(SEQ / 128, BSZ * NH);

    for (int l = 0; l < LAY; l++) {
        const size_t wb = (size_t)l * WPL;
        ln_split_kernel<<<MROWS / 8, 256>>>(ahi, alo, x, ln1g + (size_t)l * EMB, ln1b + (size_t)l * EMB);
        mma_gemm<false,false,false,true><<<gclamp2(ntQKV), 256, GEMM_SMEM>>>(
            ahi, alo, whi + wb + OFF_WQ, wlo + wb + OFF_WQ, nullptr, nullptr, nullptr,
            qkvh, qkvl, QKV, EMB, QKV / 128, ntQKV);
        attn_tc_kernel<<<gattn, 128, ATTN_SMEM>>>(qkvh, qkvl, ohi, olo);
        mma_gemm<true,false,true,false><<<gclamp2(ntE), 256, GEMM_SMEM>>>(
            ohi, olo, whi + wb + OFF_WO, wlo + wb + OFF_WO, bo + (size_t)l * EMB, x, x,
            nullptr, nullptr, EMB, EMB, EMB / 128, ntE);
        ln_split_kernel<<<MROWS / 8, 256>>>(ahi, alo, x, ln2g + (size_t)l * EMB, ln2b + (size_t)l * EMB);
        mma_gemm<true,true,false,true><<<gclamp2(ntF), 256, GEMM_SMEM>>>(
            ahi, alo, whi + wb + OFF_W1, wlo + wb + OFF_W1, b1 + (size_t)l * DFF, nullptr, nullptr,
            fhi, flo, DFF, EMB, DFF / 128, ntF);
        mma_gemm<true,false,true,false><<<gclamp2(ntE), 256, GEMM_SMEM>>>(
            fhi, flo, whi + wb + OFF_W2, wlo + wb + OFF_W2, b2 + (size_t)l * EMB, x, x,
            nullptr, nullptr, EMB, DFF, EMB / 128, ntE);
    }

    ln_split_kernel<<<MROWS / 8, 256>>>(ahi, alo, x, lnfg, lnfb);
    mma_gemm<true,false,false,false><<<gclamp2(ntV), 256, GEMM_SMEM>>>(
        ahi, alo, tokhi, toklo, lmb, nullptr, out,
        nullptr, nullptr, VOC, EMB, VOC / 128, ntV);
}